// round 1
// baseline (speedup 1.0000x reference)
#include <cuda_runtime.h>
#include <cuda_bf16.h>
#include <math.h>

// Problem constants
#define S_   32
#define FRM  8
#define CLS_ 32
#define D_   512
#define HWA2 64      // 8*8
#define HWV2 196     // 14*14
#define DOUT 128
#define BA   (S_*CLS_)   // 1024 audio images
#define BV   (S_*FRM)    // 256 video frames

// ---------------- device scratch (globals: no allocation allowed) ----------------
__device__ float d_fa[BA * D_];          // 2 MB   fa[b][o]
__device__ float d_ta[BA * DOUT];        // ta[b][o]
__device__ float d_g[BV * CLS_ * D_];    // 16 MB  g[b][c][i]
__device__ float d_camsum[BV * CLS_];
__device__ float d_tv[BV * CLS_ * DOUT]; // 4 MB   tv[(s*8+f)*32+c][o]
__device__ float d_Wvs[DOUT * D_];       // Wv @ Ws
__device__ float d_wbs[DOUT];            // Wv @ bs

// =====================================================================
// K1: fa[b,o] = max_hw( sum_i feat_a[b,i,hw] * Wt[o,i] ) + bt[o]
// grid (1024, 4) : b, o-tile of 128.  Block tile: 128 o x 64 hw, BK=32.
// 256 threads: tx(16) over hw (x4), ty(16) over o (x8)
// =====================================================================
__global__ __launch_bounds__(256) void k_fa(const float* __restrict__ feat_a,
                                            const float* __restrict__ Wt,
                                            const float* __restrict__ bt) {
    __shared__ float sW[32][132];        // [kk][o]   (pad keeps 16B align: 132*4=528)
    __shared__ float sF[32][64];         // [kk][hw]
    __shared__ float sRed[128][16];

    const int b  = blockIdx.x;
    const int ot = blockIdx.y;           // 0..3
    const int t  = threadIdx.x;
    const int tx = t & 15;
    const int ty = t >> 4;
    const float* fbase = feat_a + (size_t)b * D_ * HWA2;

    float acc[8][4];
#pragma unroll
    for (int i = 0; i < 8; i++)
#pragma unroll
        for (int j = 0; j < 4; j++) acc[i][j] = 0.f;

    const int kk_l = t & 31;
    const int or_l = t >> 5;             // 0..7

    for (int k0 = 0; k0 < D_; k0 += 32) {
        // load Wt tile (transposed into [kk][o])
#pragma unroll
        for (int r = 0; r < 16; r++) {
            int o = r * 8 + or_l;
            sW[kk_l][o] = Wt[(size_t)(ot * 128 + o) * D_ + k0 + kk_l];
        }
        // load feat tile [kk][hw]
#pragma unroll
        for (int r = 0; r < 8; r++) {
            int idx = r * 256 + t;
            int kk = idx >> 6, hw = idx & 63;
            sF[kk][hw] = fbase[(size_t)(k0 + kk) * HWA2 + hw];
        }
        __syncthreads();
#pragma unroll
        for (int kk = 0; kk < 32; kk++) {
            float4 a0 = *(const float4*)&sW[kk][ty * 8 + 0];
            float4 a1 = *(const float4*)&sW[kk][ty * 8 + 4];
            float4 bb = *(const float4*)&sF[kk][tx * 4];
            float av[8] = {a0.x, a0.y, a0.z, a0.w, a1.x, a1.y, a1.z, a1.w};
            float bv4[4] = {bb.x, bb.y, bb.z, bb.w};
#pragma unroll
            for (int i = 0; i < 8; i++)
#pragma unroll
                for (int j = 0; j < 4; j++)
                    acc[i][j] = fmaf(av[i], bv4[j], acc[i][j]);
        }
        __syncthreads();
    }
    // per-thread max over the 4 hw columns
#pragma unroll
    for (int i = 0; i < 8; i++) {
        float m = fmaxf(fmaxf(acc[i][0], acc[i][1]), fmaxf(acc[i][2], acc[i][3]));
        sRed[ty * 8 + i][tx] = m;
    }
    __syncthreads();
    if (t < 128) {
        float m = sRed[t][0];
#pragma unroll
        for (int j = 1; j < 16; j++) m = fmaxf(m, sRed[t][j]);
        int o = ot * 128 + t;
        d_fa[(size_t)b * D_ + o] = m + bt[o];
    }
}

// =====================================================================
// K2: g[b,c,i] = sum_hw feat_v[b,i,hw] * cam[b,c,hw]
// grid (256, 4): b, i-tile of 128. 256 threads: tx(32) over i (x4 strided),
// ty(8) over c (x4 strided). K = 196 in chunks of 32 (guarded).
// =====================================================================
__global__ __launch_bounds__(256) void k_g(const float* __restrict__ feat_v,
                                           const float* __restrict__ cam) {
    __shared__ float sC[32][33];   // [c][kk]
    __shared__ float sF[128][33];  // [i][kk]

    const int b  = blockIdx.x;
    const int it = blockIdx.y;     // 0..3
    const int t  = threadIdx.x;
    const int tx = t & 31;
    const int ty = t >> 5;         // 0..7

    float acc[4][4];
#pragma unroll
    for (int ci = 0; ci < 4; ci++)
#pragma unroll
        for (int ij = 0; ij < 4; ij++) acc[ci][ij] = 0.f;

    for (int hw0 = 0; hw0 < HWV2; hw0 += 32) {
        // cam chunk: 32c x 32kk
#pragma unroll
        for (int r = 0; r < 4; r++) {
            int idx = r * 256 + t;
            int c = idx >> 5, kk = idx & 31;
            int hw = hw0 + kk;
            sC[c][kk] = (hw < HWV2) ? cam[((size_t)b * CLS_ + c) * HWV2 + hw] : 0.f;
        }
        // feat chunk: 128i x 32kk
#pragma unroll
        for (int r = 0; r < 16; r++) {
            int idx = r * 256 + t;
            int i = idx >> 5, kk = idx & 31;
            int hw = hw0 + kk;
            sF[i][kk] = (hw < HWV2)
                ? feat_v[((size_t)b * D_ + it * 128 + i) * HWV2 + hw] : 0.f;
        }
        __syncthreads();
#pragma unroll
        for (int kk = 0; kk < 32; kk++) {
            float a[4], fv[4];
#pragma unroll
            for (int ci = 0; ci < 4; ci++) a[ci] = sC[ty + 8 * ci][kk];
#pragma unroll
            for (int ij = 0; ij < 4; ij++) fv[ij] = sF[tx + 32 * ij][kk];
#pragma unroll
            for (int ci = 0; ci < 4; ci++)
#pragma unroll
                for (int ij = 0; ij < 4; ij++)
                    acc[ci][ij] = fmaf(a[ci], fv[ij], acc[ci][ij]);
        }
        __syncthreads();
    }
#pragma unroll
    for (int ci = 0; ci < 4; ci++) {
        int c = ty + 8 * ci;
#pragma unroll
        for (int ij = 0; ij < 4; ij++) {
            int i = it * 128 + tx + 32 * ij;
            d_g[((size_t)b * CLS_ + c) * D_ + i] = acc[ci][ij];
        }
    }
}

// camsum[b,c] = sum_hw cam[b,c,hw]
__global__ void k_camsum(const float* __restrict__ cam) {
    int b = blockIdx.x;
    int w = threadIdx.x >> 5, lane = threadIdx.x & 31;
    for (int c = w; c < CLS_; c += 8) {
        const float* p = cam + ((size_t)b * CLS_ + c) * HWV2;
        float s = 0.f;
        for (int k = lane; k < HWV2; k += 32) s += p[k];
#pragma unroll
        for (int off = 16; off; off >>= 1) s += __shfl_xor_sync(0xffffffffu, s, off);
        if (!lane) d_camsum[b * CLS_ + c] = s;
    }
}

// Wvs[o,i] = sum_d Wv[o,d]*Ws[d,i]; wbs[o] = sum_d Wv[o,d]*bs[d]
__global__ void k_wvs(const float* __restrict__ Wv, const float* __restrict__ Ws,
                      const float* __restrict__ bs) {
    __shared__ float wv[D_];
    int o = blockIdx.x, t = threadIdx.x;
    wv[t] = Wv[o * D_ + t];
    wv[t + 256] = Wv[o * D_ + t + 256];
    __syncthreads();
    float s0 = 0.f, s1 = 0.f;
    for (int d = 0; d < D_; d++) {
        float w = wv[d];
        s0 = fmaf(w, Ws[(size_t)d * D_ + t], s0);
        s1 = fmaf(w, Ws[(size_t)d * D_ + t + 256], s1);
    }
    d_Wvs[o * D_ + t] = s0;
    d_Wvs[o * D_ + t + 256] = s1;
    if (t == 0) {
        float s = 0.f;
        for (int d = 0; d < D_; d++) s += wv[d] * bs[d];
        d_wbs[o] = s;
    }
}

// =====================================================================
// Generic C[m,o] = sum_i A[m,i]*B[o,i] (+epilogue), N=128 fixed, K=512.
// mode 0: A=d_fa,B=Bext(Wa),C=d_ta,  C += bias
// mode 1: A=d_g, B=d_Wvs,  C=d_tv,  C = (acc + wbs[o]*cs)/(cs+1e-10) + bias
// grid (M/128), 256 threads, 128x128 tile, 8x8 per thread.
// =====================================================================
__global__ __launch_bounds__(256) void k_gemm(int mode, const float* __restrict__ Bext,
                                              const float* __restrict__ bias) {
    __shared__ float sA[128][33];
    __shared__ float sB[128][33];

    const float* A = (mode == 0) ? d_fa : d_g;
    const float* B = (mode == 0) ? Bext : d_Wvs;
    float* C       = (mode == 0) ? d_ta : d_tv;

    const int m0 = blockIdx.x * 128;
    const int t  = threadIdx.x;
    const int tx = t & 15, ty = t >> 4;

    float acc[8][8];
#pragma unroll
    for (int i = 0; i < 8; i++)
#pragma unroll
        for (int j = 0; j < 8; j++) acc[i][j] = 0.f;

    for (int k0 = 0; k0 < D_; k0 += 32) {
#pragma unroll
        for (int r = 0; r < 16; r++) {
            int idx = r * 256 + t;
            int mm = idx >> 5, kk = idx & 31;
            sA[mm][kk] = A[(size_t)(m0 + mm) * D_ + k0 + kk];
            sB[mm][kk] = B[(size_t)mm * D_ + k0 + kk];
        }
        __syncthreads();
#pragma unroll
        for (int kk = 0; kk < 32; kk++) {
            float a[8], b[8];
#pragma unroll
            for (int mi = 0; mi < 8; mi++) a[mi] = sA[ty + 16 * mi][kk];
#pragma unroll
            for (int oj = 0; oj < 8; oj++) b[oj] = sB[tx + 16 * oj][kk];
#pragma unroll
            for (int mi = 0; mi < 8; mi++)
#pragma unroll
                for (int oj = 0; oj < 8; oj++)
                    acc[mi][oj] = fmaf(a[mi], b[oj], acc[mi][oj]);
        }
        __syncthreads();
    }
#pragma unroll
    for (int mi = 0; mi < 8; mi++) {
        int m = m0 + ty + 16 * mi;
        float cs = (mode == 1) ? d_camsum[m] : 0.f;
        float inv = (mode == 1) ? (1.f / (cs + 1e-10f)) : 0.f;
#pragma unroll
        for (int oj = 0; oj < 8; oj++) {
            int o = tx + 16 * oj;
            float v = acc[mi][oj];
            if (mode == 0) {
                C[(size_t)m * DOUT + o] = v + bias[o];
            } else {
                C[(size_t)m * DOUT + o] = (v + d_wbs[o] * cs) * inv + bias[o];
            }
        }
    }
}

// =====================================================================
// K_loss: grid (32 s, 32 c), 256 threads = 8 warps (warp = f)
// =====================================================================
__global__ void k_loss(const float* __restrict__ pred_a, const float* __restrict__ pred_v,
                       const int* __restrict__ rand_frames, const int* __restrict__ rand_classes,
                       float* __restrict__ out) {
    const int s = blockIdx.x, c = blockIdx.y;
    const int f = threadIdx.x >> 5, lane = threadIdx.x & 31;

    const float pa = pred_a[s * CLS_ + c];
    const bool aa = pa > 0.3f;
    const int num = (int)(pa * (float)FRM);

    const float* tap = d_ta + (size_t)(s * CLS_ + c) * DOUT;
    const float* tvp = d_tv + (size_t)((s * FRM + f) * CLS_ + c) * DOUT;
    const int rf = rand_frames[(s * CLS_ + c) * FRM + f];
    const int rc = rand_classes[(s * CLS_ + c) * FRM + f];
    const float* tvd = d_tv + (size_t)(((s ^ 1) * FRM + rf) * CLS_ + rc) * DOUT;

    float sco = 0.f, sdi = 0.f;
#pragma unroll
    for (int j = 0; j < 4; j++) {
        int o = lane + 32 * j;
        float t0 = tap[o];
        float d0 = t0 - tvp[o]; sco = fmaf(d0, d0, sco);
        float d1 = t0 - tvd[o]; sdi = fmaf(d1, d1, sdi);
    }
#pragma unroll
    for (int off = 16; off; off >>= 1) {
        sco += __shfl_xor_sync(0xffffffffu, sco, off);
        sdi += __shfl_xor_sync(0xffffffffu, sdi, off);
    }
    if (!lane) {
        float pv = 1.f / (1.f + expf(-pred_v[(s * FRM + f) * CLS_ + c]));
        bool av = pv > 0.3f;
        float mco = (aa && av) ? 1.f : 0.f;
        float mdi = (aa && (f < num)) ? 1.f : 0.f;
        out[((0 * S_ + s) * CLS_ + c) * FRM + f] = sco * (1.f / 128.f) * mco;
        out[((1 * S_ + s) * CLS_ + c) * FRM + f] = sdi * (1.f / 128.f) * mdi;
    }
}

// =====================================================================
extern "C" void kernel_launch(void* const* d_in, const int* in_sizes, int n_in,
                              void* d_out, int out_size) {
    const float* feat_a = (const float*)d_in[0];
    const float* pred_a = (const float*)d_in[1];
    const float* feat_v = (const float*)d_in[2];
    const float* pred_v = (const float*)d_in[3];
    const float* cam    = (const float*)d_in[4];
    const int* rand_frames  = (const int*)d_in[5];
    const int* rand_classes = (const int*)d_in[6];
    const float* Wt = (const float*)d_in[7];
    const float* bt = (const float*)d_in[8];
    const float* Ws = (const float*)d_in[9];
    const float* bs = (const float*)d_in[10];
    const float* Wa = (const float*)d_in[11];
    const float* ba = (const float*)d_in[12];
    const float* Wv = (const float*)d_in[13];
    const float* bv = (const float*)d_in[14];
    float* out = (float*)d_out;

    // independent producers
    k_fa<<<dim3(BA, 4), 256>>>(feat_a, Wt, bt);
    k_g<<<dim3(BV, 4), 256>>>(feat_v, cam);
    k_camsum<<<BV, 256>>>(cam);
    k_wvs<<<DOUT, 256>>>(Wv, Ws, bs);
    // projections
    k_gemm<<<BA / 128, 256>>>(0, Wa, ba);               // ta: M=1024
    k_gemm<<<(BV * CLS_) / 128, 256>>>(1, nullptr, bv); // tv: M=8192
    // losses
    k_loss<<<dim3(S_, CLS_), 256>>>(pred_a, pred_v, rand_frames, rand_classes, out);
}

// round 3
// speedup vs baseline: 1.3968x; 1.3968x over previous
#include <cuda_runtime.h>
#include <cuda_bf16.h>
#include <math.h>
#include <cstdint>

// Problem constants
#define S_   32
#define FRM  8
#define CLS_ 32
#define D_   512
#define HWA2 64      // 8*8
#define HWV2 196     // 14*14
#define DOUT 128
#define BA   (S_*CLS_)   // 1024
#define BV   (S_*FRM)    // 256

// ---------------- device scratch ----------------
__device__ float d_fa[BA * D_];
__device__ float d_ta[BA * DOUT];
__device__ float d_g[BV * CLS_ * D_];
__device__ float d_camsum[BV * CLS_];
__device__ float d_tv[BV * CLS_ * DOUT];
__device__ float d_Wvs[DOUT * D_];
__device__ float d_wbs[DOUT];
// permuted bf16 hi/lo copies
__device__ __nv_bfloat16 d_wt_hi[D_ * D_];
__device__ __nv_bfloat16 d_wt_lo[D_ * D_];
__device__ __nv_bfloat16 d_ft_hi[(size_t)BA * HWA2 * D_];   // [b][hw][kperm]
__device__ __nv_bfloat16 d_ft_lo[(size_t)BA * HWA2 * D_];

// =============== small asm helpers ===============
__device__ __forceinline__ uint32_t smem_to_u32(const void* p) {
    uint32_t a;
    asm("{ .reg .u64 t; cvta.to.shared.u64 t, %1; cvt.u32.u64 %0, t; }" : "=r"(a) : "l"(p));
    return a;
}
#define CP_ASYNC16(sm, g) \
    asm volatile("cp.async.cg.shared.global [%0], [%1], 16;" :: "r"((uint32_t)(sm)), "l"(g) : "memory")
#define CP_ASYNC_COMMIT() asm volatile("cp.async.commit_group;" ::: "memory")
#define CP_ASYNC_WAIT0()  asm volatile("cp.async.wait_group 0;" ::: "memory")
#define CP_ASYNC_WAIT1()  asm volatile("cp.async.wait_group 1;" ::: "memory")

#define LDS64(r0, r1, addr) \
    asm volatile("ld.shared.v2.b32 {%0,%1}, [%2];" : "=r"(r0), "=r"(r1) : "r"((uint32_t)(addr)))

#define MMA_BF16(d, a, b) \
    asm volatile("mma.sync.aligned.m16n8k16.row.col.f32.bf16.bf16.f32 " \
        "{%0,%1,%2,%3}, {%4,%5,%6,%7}, {%8,%9}, {%0,%1,%2,%3};" \
        : "+f"((d)[0]), "+f"((d)[1]), "+f"((d)[2]), "+f"((d)[3]) \
        : "r"((a)[0]), "r"((a)[1]), "r"((a)[2]), "r"((a)[3]), "r"((b)[0]), "r"((b)[1]))

__device__ __forceinline__ uint32_t pack_bf16x2(float a, float b) {
    __nv_bfloat162 p = __floats2bfloat162_rn(a, b);   // .x = a (low), .y = b (high)
    return *(uint32_t*)&p;
}

// k-permutation within a 16-element group:
// stored half order: [k0,k1,k8,k9,k2,k3,k10,k11,k4,k5,k12,k13,k6,k7,k14,k15]
// word w (pair) of a group: w even -> k = w ; w odd -> k = w + 7.

// =====================================================================
// Prep 1: Wt fp32 -> permuted bf16 hi/lo.  thread per (o, group)
// =====================================================================
__global__ __launch_bounds__(256) void k_cvt_wt(const float* __restrict__ Wt) {
    int idx = blockIdx.x * 256 + threadIdx.x;   // 0 .. 512*32-1
    int o = idx >> 5, g = idx & 31;
    const float* src = Wt + (size_t)o * D_ + g * 16;
    float v[16];
#pragma unroll
    for (int q = 0; q < 4; q++) {
        float4 f = *(const float4*)(src + q * 4);
        v[q * 4 + 0] = f.x; v[q * 4 + 1] = f.y; v[q * 4 + 2] = f.z; v[q * 4 + 3] = f.w;
    }
    uint32_t hw_[8], lw_[8];
#pragma unroll
    for (int w = 0; w < 8; w++) {
        int k = (w & 1) ? (w + 7) : w;
        float v0 = v[k], v1 = v[k + 1];
        __nv_bfloat16 h0 = __float2bfloat16(v0), h1 = __float2bfloat16(v1);
        hw_[w] = pack_bf16x2(__bfloat162float(h0), __bfloat162float(h1));
        lw_[w] = pack_bf16x2(v0 - __bfloat162float(h0), v1 - __bfloat162float(h1));
    }
    uint32_t* dh = (uint32_t*)d_wt_hi + (size_t)o * 256 + g * 8;
    uint32_t* dl = (uint32_t*)d_wt_lo + (size_t)o * 256 + g * 8;
    *(uint4*)(dh + 0) = make_uint4(hw_[0], hw_[1], hw_[2], hw_[3]);
    *(uint4*)(dh + 4) = make_uint4(hw_[4], hw_[5], hw_[6], hw_[7]);
    *(uint4*)(dl + 0) = make_uint4(lw_[0], lw_[1], lw_[2], lw_[3]);
    *(uint4*)(dl + 4) = make_uint4(lw_[4], lw_[5], lw_[6], lw_[7]);
}

// =====================================================================
// Prep 2: feat_a [b][k][hw] fp32 -> d_ft_hi/lo [b][hw][kperm] bf16
// grid = 1024 (b), 256 threads, dyn smem = 512*68*4 = 139264
// =====================================================================
#define FT_PAD 68
__global__ __launch_bounds__(256) void k_prep_feat(const float* __restrict__ feat_a) {
    extern __shared__ float sm[];    // [512][68]
    const int b = blockIdx.x;
    const int t = threadIdx.x;
    const float* src = feat_a + (size_t)b * D_ * HWA2;
#pragma unroll
    for (int r = 0; r < 32; r++) {
        int fi = r * 256 + t;            // float4 index, 8192 total
        int row = fi >> 4, c4 = fi & 15;
        float4 f = *(const float4*)(src + fi * 4);
        float* dst = sm + row * FT_PAD + c4 * 4;
        *(float4*)dst = f;
    }
    __syncthreads();
    const int hw = t >> 2, kseg = t & 3;     // 128 k each
    uint32_t* dh = (uint32_t*)d_ft_hi + ((size_t)b * HWA2 + hw) * 256;
    uint32_t* dl = (uint32_t*)d_ft_lo + ((size_t)b * HWA2 + hw) * 256;
#pragma unroll
    for (int g = 0; g < 8; g++) {
        int kbase = kseg * 128 + g * 16;
        uint32_t hw_[8], lw_[8];
#pragma unroll
        for (int w = 0; w < 8; w++) {
            int k = (w & 1) ? (w + 7) : w;
            float v0 = sm[(kbase + k) * FT_PAD + hw];
            float v1 = sm[(kbase + k + 1) * FT_PAD + hw];
            __nv_bfloat16 h0 = __float2bfloat16(v0), h1 = __float2bfloat16(v1);
            hw_[w] = pack_bf16x2(__bfloat162float(h0), __bfloat162float(h1));
            lw_[w] = pack_bf16x2(v0 - __bfloat162float(h0), v1 - __bfloat162float(h1));
        }
        int wbase = (kbase >> 1);
        *(uint4*)(dh + wbase + 0) = make_uint4(hw_[0], hw_[1], hw_[2], hw_[3]);
        *(uint4*)(dh + wbase + 4) = make_uint4(hw_[4], hw_[5], hw_[6], hw_[7]);
        *(uint4*)(dl + wbase + 0) = make_uint4(lw_[0], lw_[1], lw_[2], lw_[3]);
        *(uint4*)(dl + wbase + 4) = make_uint4(lw_[4], lw_[5], lw_[6], lw_[7]);
    }
}

// =====================================================================
// k_fa_mma: fa[b,o] = max_hw( feat[b,:,hw] . Wt[o,:] ) + bt[o]
// one CTA per b (grid 1024), 256 threads = 8 warps.
// feat[b] resident in SMEM (hi/lo), Wt streamed (128o x 64k chunks, dbl buf).
// warp tile 32o x 32hw; warps = (ot2, oy, hx). bf16 3-pass hi/lo split.
// =====================================================================
#define RED_OFF   0
#define FEAT_OFF  1024
#define FEAT_ROWB 1072                  // 512 halves + 24 pad = 67*16 B
#define FEAT_HSZ  (64 * FEAT_ROWB)     // 68608
#define WT_OFF    (FEAT_OFF + 2 * FEAT_HSZ)   // 138240
#define WT_ROWB   144                  // 64 halves + 8 pad = 9*16 B
#define WT_HSZ    (128 * WT_ROWB)      // 18432
#define WT_BUFSZ  (2 * WT_HSZ)         // 36864
#define FA_SMEM   (WT_OFF + 2 * WT_BUFSZ)     // 211968

__device__ __forceinline__ void fa_load_wt(uint32_t sb, int buf, int otp, int kc, int t) {
#pragma unroll
    for (int r = 0; r < 8; r++) {
        int idx = r * 256 + t;
        int h = idx >> 10, rem = idx & 1023;
        int row = rem >> 3, c = rem & 7;
        const __nv_bfloat16* src = (h ? d_wt_lo : d_wt_hi)
            + ((size_t)(otp * 128 + row) * D_ + kc * 64 + c * 8);
        uint32_t dst = sb + WT_OFF + buf * WT_BUFSZ + h * WT_HSZ + row * WT_ROWB + c * 16;
        CP_ASYNC16(dst, src);
    }
}

__global__ void __launch_bounds__(256, 1) k_fa_mma(const float* __restrict__ bt) {
    extern __shared__ char smem[];
    float* red = (float*)smem;
    uint32_t sb = smem_to_u32(smem);
    const int b = blockIdx.x;
    const int t = threadIdx.x;
    const int w = t >> 5, lane = t & 31;
    const int ot2 = w >> 2, oy = (w >> 1) & 1, hx = w & 1;
    const int j = lane & 3, r4 = lane >> 2;

    // initial loads: full feat[b] (hi+lo) + Wt chunk 0  -> group 0
#pragma unroll
    for (int r = 0; r < 32; r++) {
        int idx = r * 256 + t;
        int h = idx >> 12, rem = idx & 4095;
        int row = rem >> 6, c = rem & 63;
        const __nv_bfloat16* src = (h ? d_ft_lo : d_ft_hi)
            + ((size_t)(b * HWA2 + row) * D_ + c * 8);
        uint32_t dst = sb + FEAT_OFF + h * FEAT_HSZ + row * FEAT_ROWB + c * 16;
        CP_ASYNC16(dst, src);
    }
    fa_load_wt(sb, 0, 0, 0, t);
    CP_ASYNC_COMMIT();

    float acc[2][4][4];
#pragma unroll
    for (int mf = 0; mf < 2; mf++)
#pragma unroll
        for (int nf = 0; nf < 4; nf++)
#pragma unroll
            for (int q = 0; q < 4; q++) acc[mf][nf][q] = 0.f;

    const int oA = ot2 * 64 + oy * 32 + r4;      // A base row within 128-row chunk
    const int hwB = hx * 32 + r4;                // B base row

    for (int it = 0; it < 32; it++) {
        const int otp = it >> 3, kc = it & 7, buf = it & 1;
        if (it + 1 < 32) {
            fa_load_wt(sb, buf ^ 1, (it + 1) >> 3, (it + 1) & 7, t);
            CP_ASYNC_COMMIT();
            CP_ASYNC_WAIT1();
        } else {
            CP_ASYNC_WAIT0();
        }
        __syncthreads();

        const uint32_t wtb = sb + WT_OFF + buf * WT_BUFSZ;
#pragma unroll
        for (int kst = 0; kst < 4; kst++) {
            const int ks = kc * 4 + kst;
            uint32_t ah[2][4], al[2][4];
#pragma unroll
            for (int mf = 0; mf < 2; mf++) {
                uint32_t base = wtb + (oA + mf * 16) * WT_ROWB + kst * 32 + j * 8;
                LDS64(ah[mf][0], ah[mf][2], base);
                LDS64(ah[mf][1], ah[mf][3], base + 8 * WT_ROWB);
                LDS64(al[mf][0], al[mf][2], base + WT_HSZ);
                LDS64(al[mf][1], al[mf][3], base + WT_HSZ + 8 * WT_ROWB);
            }
            uint32_t bh[4][2], bl[4][2];
#pragma unroll
            for (int nf = 0; nf < 4; nf++) {
                uint32_t bb = sb + FEAT_OFF + (hwB + nf * 8) * FEAT_ROWB + ks * 32 + j * 8;
                LDS64(bh[nf][0], bh[nf][1], bb);
                LDS64(bl[nf][0], bl[nf][1], bb + FEAT_HSZ);
            }
#pragma unroll
            for (int mf = 0; mf < 2; mf++)
#pragma unroll
                for (int nf = 0; nf < 4; nf++) {
                    MMA_BF16(acc[mf][nf], ah[mf], bh[nf]);
                    MMA_BF16(acc[mf][nf], ah[mf], bl[nf]);
                    MMA_BF16(acc[mf][nf], al[mf], bh[nf]);
                }
        }

        if (kc == 7) {
            // max over hw + cross-warp (hx) reduce + store
#pragma unroll
            for (int mf = 0; mf < 2; mf++) {
                float m0 = acc[mf][0][0], m1 = acc[mf][0][2];
#pragma unroll
                for (int nf = 0; nf < 4; nf++) {
                    m0 = fmaxf(m0, fmaxf(acc[mf][nf][0], acc[mf][nf][1]));
                    m1 = fmaxf(m1, fmaxf(acc[mf][nf][2], acc[mf][nf][3]));
                }
                m0 = fmaxf(m0, __shfl_xor_sync(0xffffffffu, m0, 1));
                m0 = fmaxf(m0, __shfl_xor_sync(0xffffffffu, m0, 2));
                m1 = fmaxf(m1, __shfl_xor_sync(0xffffffffu, m1, 1));
                m1 = fmaxf(m1, __shfl_xor_sync(0xffffffffu, m1, 2));
                if (j == 0) {
                    red[ot2 * 128 + hx * 64 + oy * 32 + mf * 16 + r4] = m0;
                    red[ot2 * 128 + hx * 64 + oy * 32 + mf * 16 + r4 + 8] = m1;
                }
            }
            __syncthreads();
            if (t < 128) {
                int o2 = t >> 6, ol = t & 63;
                float v = fmaxf(red[o2 * 128 + ol], red[o2 * 128 + 64 + ol]);
                int og = otp * 128 + o2 * 64 + ol;
                d_fa[(size_t)b * D_ + og] = v + bt[og];
            }
#pragma unroll
            for (int mf = 0; mf < 2; mf++)
#pragma unroll
                for (int nf = 0; nf < 4; nf++)
#pragma unroll
                    for (int q = 0; q < 4; q++) acc[mf][nf][q] = 0.f;
        }
        __syncthreads();
    }
}

// =====================================================================
// K2: g[b,c,i] = sum_hw feat_v[b,i,hw] * cam[b,c,hw]
// =====================================================================
__global__ __launch_bounds__(256) void k_g(const float* __restrict__ feat_v,
                                           const float* __restrict__ cam) {
    __shared__ float sC[32][33];
    __shared__ float sF[128][33];

    const int b  = blockIdx.x;
    const int it = blockIdx.y;
    const int t  = threadIdx.x;
    const int tx = t & 31;
    const int ty = t >> 5;

    float acc[4][4];
#pragma unroll
    for (int ci = 0; ci < 4; ci++)
#pragma unroll
        for (int ij = 0; ij < 4; ij++) acc[ci][ij] = 0.f;

    for (int hw0 = 0; hw0 < HWV2; hw0 += 32) {
#pragma unroll
        for (int r = 0; r < 4; r++) {
            int idx = r * 256 + t;
            int c = idx >> 5, kk = idx & 31;
            int hw = hw0 + kk;
            sC[c][kk] = (hw < HWV2) ? cam[((size_t)b * CLS_ + c) * HWV2 + hw] : 0.f;
        }
#pragma unroll
        for (int r = 0; r < 16; r++) {
            int idx = r * 256 + t;
            int i = idx >> 5, kk = idx & 31;
            int hw = hw0 + kk;
            sF[i][kk] = (hw < HWV2)
                ? feat_v[((size_t)b * D_ + it * 128 + i) * HWV2 + hw] : 0.f;
        }
        __syncthreads();
#pragma unroll
        for (int kk = 0; kk < 32; kk++) {
            float a[4], fv[4];
#pragma unroll
            for (int ci = 0; ci < 4; ci++) a[ci] = sC[ty + 8 * ci][kk];
#pragma unroll
            for (int ij = 0; ij < 4; ij++) fv[ij] = sF[tx + 32 * ij][kk];
#pragma unroll
            for (int ci = 0; ci < 4; ci++)
#pragma unroll
                for (int ij = 0; ij < 4; ij++)
                    acc[ci][ij] = fmaf(a[ci], fv[ij], acc[ci][ij]);
        }
        __syncthreads();
    }
#pragma unroll
    for (int ci = 0; ci < 4; ci++) {
        int c = ty + 8 * ci;
#pragma unroll
        for (int ij = 0; ij < 4; ij++) {
            int i = it * 128 + tx + 32 * ij;
            d_g[((size_t)b * CLS_ + c) * D_ + i] = acc[ci][ij];
        }
    }
}

__global__ void k_camsum(const float* __restrict__ cam) {
    int b = blockIdx.x;
    int w = threadIdx.x >> 5, lane = threadIdx.x & 31;
    for (int c = w; c < CLS_; c += 8) {
        const float* p = cam + ((size_t)b * CLS_ + c) * HWV2;
        float s = 0.f;
        for (int k = lane; k < HWV2; k += 32) s += p[k];
#pragma unroll
        for (int off = 16; off; off >>= 1) s += __shfl_xor_sync(0xffffffffu, s, off);
        if (!lane) d_camsum[b * CLS_ + c] = s;
    }
}

// =====================================================================
// Wvs[o,i] = sum_d Wv[o,d]*Ws[d,i]  — tiled 32o x 64i, grid (4, 8)
// =====================================================================
__global__ __launch_bounds__(256) void k_wvs(const float* __restrict__ Wv,
                                             const float* __restrict__ Ws) {
    __shared__ float sV[32][65];
    __shared__ float sS[64][65];
    const int oT = blockIdx.x, iT = blockIdx.y;
    const int t = threadIdx.x;
    const int tx = t & 31, ty = t >> 5;

    float acc[4][2];
#pragma unroll
    for (int a = 0; a < 4; a++) { acc[a][0] = 0.f; acc[a][1] = 0.f; }

    for (int k0 = 0; k0 < D_; k0 += 64) {
#pragma unroll
        for (int r = 0; r < 8; r++) {
            int idx = r * 256 + t;
            int o = idx >> 6, kk = idx & 63;
            sV[o][kk] = Wv[(size_t)(oT * 32 + o) * D_ + k0 + kk];
        }
#pragma unroll
        for (int r = 0; r < 16; r++) {
            int idx = r * 256 + t;
            int kk = idx >> 6, i = idx & 63;
            sS[kk][i] = Ws[(size_t)(k0 + kk) * D_ + iT * 64 + i];
        }
        __syncthreads();
#pragma unroll
        for (int kk = 0; kk < 64; kk++) {
            float bb0 = sS[kk][tx], bb1 = sS[kk][tx + 32];
#pragma unroll
            for (int a = 0; a < 4; a++) {
                float av = sV[ty * 4 + a][kk];
                acc[a][0] = fmaf(av, bb0, acc[a][0]);
                acc[a][1] = fmaf(av, bb1, acc[a][1]);
            }
        }
        __syncthreads();
    }
#pragma unroll
    for (int a = 0; a < 4; a++) {
        int o = oT * 32 + ty * 4 + a;
        d_Wvs[(size_t)o * D_ + iT * 64 + tx] = acc[a][0];
        d_Wvs[(size_t)o * D_ + iT * 64 + tx + 32] = acc[a][1];
    }
}

__global__ void k_wbs(const float* __restrict__ Wv, const float* __restrict__ bs) {
    int o = blockIdx.x, lane = threadIdx.x;
    float s = 0.f;
    for (int d = lane; d < D_; d += 32) s = fmaf(Wv[(size_t)o * D_ + d], bs[d], s);
#pragma unroll
    for (int off = 16; off; off >>= 1) s += __shfl_xor_sync(0xffffffffu, s, off);
    if (!lane) d_wbs[o] = s;
}

// =====================================================================
// Generic C[m,o] = sum_i A[m,i]*B[o,i], N=128, K=512
// =====================================================================
__global__ __launch_bounds__(256) void k_gemm(int mode, const float* __restrict__ Bext,
                                              const float* __restrict__ bias) {
    __shared__ float sA[128][33];
    __shared__ float sB[128][33];

    const float* A = (mode == 0) ? d_fa : d_g;
    const float* B = (mode == 0) ? Bext : d_Wvs;
    float* C       = (mode == 0) ? d_ta : d_tv;

    const int m0 = blockIdx.x * 128;
    const int t  = threadIdx.x;
    const int tx = t & 15, ty = t >> 4;

    float acc[8][8];
#pragma unroll
    for (int i = 0; i < 8; i++)
#pragma unroll
        for (int jq = 0; jq < 8; jq++) acc[i][jq] = 0.f;

    for (int k0 = 0; k0 < D_; k0 += 32) {
#pragma unroll
        for (int r = 0; r < 16; r++) {
            int idx = r * 256 + t;
            int mm = idx >> 5, kk = idx & 31;
            sA[mm][kk] = A[(size_t)(m0 + mm) * D_ + k0 + kk];
            sB[mm][kk] = B[(size_t)mm * D_ + k0 + kk];
        }
        __syncthreads();
#pragma unroll
        for (int kk = 0; kk < 32; kk++) {
            float a[8], b[8];
#pragma unroll
            for (int mi = 0; mi < 8; mi++) a[mi] = sA[ty + 16 * mi][kk];
#pragma unroll
            for (int oj = 0; oj < 8; oj++) b[oj] = sB[tx + 16 * oj][kk];
#pragma unroll
            for (int mi = 0; mi < 8; mi++)
#pragma unroll
                for (int oj = 0; oj < 8; oj++)
                    acc[mi][oj] = fmaf(a[mi], b[oj], acc[mi][oj]);
        }
        __syncthreads();
    }
#pragma unroll
    for (int mi = 0; mi < 8; mi++) {
        int m = m0 + ty + 16 * mi;
        float cs = (mode == 1) ? d_camsum[m] : 0.f;
        float inv = (mode == 1) ? (1.f / (cs + 1e-10f)) : 0.f;
#pragma unroll
        for (int oj = 0; oj < 8; oj++) {
            int o = tx + 16 * oj;
            float v = acc[mi][oj];
            if (mode == 0) {
                C[(size_t)m * DOUT + o] = v + bias[o];
            } else {
                C[(size_t)m * DOUT + o] = (v + d_wbs[o] * cs) * inv + bias[o];
            }
        }
    }
}

// =====================================================================
// losses
// =====================================================================
__global__ void k_loss(const float* __restrict__ pred_a, const float* __restrict__ pred_v,
                       const int* __restrict__ rand_frames, const int* __restrict__ rand_classes,
                       float* __restrict__ out) {
    const int s = blockIdx.x, c = blockIdx.y;
    const int f = threadIdx.x >> 5, lane = threadIdx.x & 31;

    const float pa = pred_a[s * CLS_ + c];
    const bool aa = pa > 0.3f;
    const int num = (int)(pa * (float)FRM);

    const float* tap = d_ta + (size_t)(s * CLS_ + c) * DOUT;
    const float* tvp = d_tv + (size_t)((s * FRM + f) * CLS_ + c) * DOUT;
    const int rf = rand_frames[(s * CLS_ + c) * FRM + f];
    const int rc = rand_classes[(s * CLS_ + c) * FRM + f];
    const float* tvd = d_tv + (size_t)(((s ^ 1) * FRM + rf) * CLS_ + rc) * DOUT;

    float sco = 0.f, sdi = 0.f;
#pragma unroll
    for (int jq = 0; jq < 4; jq++) {
        int o = lane + 32 * jq;
        float t0 = tap[o];
        float d0 = t0 - tvp[o]; sco = fmaf(d0, d0, sco);
        float d1 = t0 - tvd[o]; sdi = fmaf(d1, d1, sdi);
    }
#pragma unroll
    for (int off = 16; off; off >>= 1) {
        sco += __shfl_xor_sync(0xffffffffu, sco, off);
        sdi += __shfl_xor_sync(0xffffffffu, sdi, off);
    }
    if (!lane) {
        float pv = 1.f / (1.f + expf(-pred_v[(s * FRM + f) * CLS_ + c]));
        bool av = pv > 0.3f;
        float mco = (aa && av) ? 1.f : 0.f;
        float mdi = (aa && (f < num)) ? 1.f : 0.f;
        out[((0 * S_ + s) * CLS_ + c) * FRM + f] = sco * (1.f / 128.f) * mco;
        out[((1 * S_ + s) * CLS_ + c) * FRM + f] = sdi * (1.f / 128.f) * mdi;
    }
}

// =====================================================================
extern "C" void kernel_launch(void* const* d_in, const int* in_sizes, int n_in,
                              void* d_out, int out_size) {
    const float* feat_a = (const float*)d_in[0];
    const float* pred_a = (const float*)d_in[1];
    const float* feat_v = (const float*)d_in[2];
    const float* pred_v = (const float*)d_in[3];
    const float* cam    = (const float*)d_in[4];
    const int* rand_frames  = (const int*)d_in[5];
    const int* rand_classes = (const int*)d_in[6];
    const float* Wt = (const float*)d_in[7];
    const float* bt = (const float*)d_in[8];
    const float* Ws = (const float*)d_in[9];
    const float* bs = (const float*)d_in[10];
    const float* Wa = (const float*)d_in[11];
    const float* ba = (const float*)d_in[12];
    const float* Wv = (const float*)d_in[13];
    const float* bv = (const float*)d_in[14];
    float* out = (float*)d_out;

    static bool attr_set = false;
    if (!attr_set) {
        cudaFuncSetAttribute(k_fa_mma, cudaFuncAttributeMaxDynamicSharedMemorySize, FA_SMEM);
        cudaFuncSetAttribute(k_prep_feat, cudaFuncAttributeMaxDynamicSharedMemorySize,
                             D_ * FT_PAD * 4);
        attr_set = true;
    }

    // prep (bf16 hi/lo, permuted layouts)
    k_cvt_wt<<<64, 256>>>(Wt);
    k_prep_feat<<<BA, 256, D_ * FT_PAD * 4>>>(feat_a);
    // main tensor-core GEMM + max
    k_fa_mma<<<BA, 256, FA_SMEM>>>(bt);
    // video path
    k_g<<<dim3(BV, 4), 256>>>(feat_v, cam);
    k_camsum<<<BV, 256>>>(cam);
    k_wvs<<<dim3(4, 8), 256>>>(Wv, Ws);
    k_wbs<<<DOUT, 32>>>(Wv, bs);
    // projections
    k_gemm<<<BA / 128, 256>>>(0, Wa, ba);
    k_gemm<<<(BV * CLS_) / 128, 256>>>(1, nullptr, bv);
    // losses
    k_loss<<<dim3(S_, CLS_), 256>>>(pred_a, pred_v, rand_frames, rand_classes, out);
}

// round 4
// speedup vs baseline: 1.8726x; 1.3406x over previous
#include <cuda_runtime.h>
#include <cuda_fp16.h>
#include <math.h>
#include <cstdint>

// Problem constants
#define S_   32
#define FRM  8
#define CLS_ 32
#define D_   512
#define HWA2 64      // 8*8
#define HWV2 196     // 14*14
#define DOUT 128
#define BA   (S_*CLS_)   // 1024
#define BV   (S_*FRM)    // 256

#define LO_SCALE 2048.0f
#define LO_INV   (1.0f / 2048.0f)

// ---------------- device scratch ----------------
__device__ float d_fa[BA * D_];
__device__ float d_ta[BA * DOUT];
__device__ float d_g[BV * CLS_ * D_];
__device__ float d_camsum[BV * CLS_];
__device__ float d_tv[BV * CLS_ * DOUT];
__device__ float d_Wvs[DOUT * D_];
__device__ float d_wbs[DOUT];
// permuted fp16 copies
__device__ __half d_wt_h[D_ * D_];                         // [o][kperm] fp16
__device__ __half d_ft_hi[(size_t)BA * HWA2 * D_];         // [b][hw][kperm]
__device__ __half d_ft_lo[(size_t)BA * HWA2 * D_];         // (f - hi) * 2048

// =============== small asm helpers ===============
__device__ __forceinline__ uint32_t smem_to_u32(const void* p) {
    uint32_t a;
    asm("{ .reg .u64 t; cvta.to.shared.u64 t, %1; cvt.u32.u64 %0, t; }" : "=r"(a) : "l"(p));
    return a;
}
#define CP_ASYNC16(sm, g) \
    asm volatile("cp.async.cg.shared.global [%0], [%1], 16;" :: "r"((uint32_t)(sm)), "l"(g) : "memory")
#define CP_ASYNC_COMMIT() asm volatile("cp.async.commit_group;" ::: "memory")
#define CP_ASYNC_WAIT0()  asm volatile("cp.async.wait_group 0;" ::: "memory")
#define CP_ASYNC_WAIT1()  asm volatile("cp.async.wait_group 1;" ::: "memory")

#define LDS64(r0, r1, addr) \
    asm volatile("ld.shared.v2.b32 {%0,%1}, [%2];" : "=r"(r0), "=r"(r1) : "r"((uint32_t)(addr)))

#define MMA_F16(d, a, b) \
    asm volatile("mma.sync.aligned.m16n8k16.row.col.f32.f16.f16.f32 " \
        "{%0,%1,%2,%3}, {%4,%5,%6,%7}, {%8,%9}, {%0,%1,%2,%3};" \
        : "+f"((d)[0]), "+f"((d)[1]), "+f"((d)[2]), "+f"((d)[3]) \
        : "r"((a)[0]), "r"((a)[1]), "r"((a)[2]), "r"((a)[3]), "r"((b)[0]), "r"((b)[1]))

__device__ __forceinline__ uint32_t pack_h2(__half a, __half b) {
    __half2 p = __halves2half2(a, b);
    return *(uint32_t*)&p;
}

// k-permutation within a 16-element group (matches mma frag layout):
// word w (pair): w even -> k = w ; w odd -> k = w + 7.

// =====================================================================
// Prep 1: Wt fp32 -> permuted fp16.  thread per (o, group)
// =====================================================================
__global__ __launch_bounds__(256) void k_cvt_wt(const float* __restrict__ Wt) {
    int idx = blockIdx.x * 256 + threadIdx.x;   // 0 .. 512*32-1
    int o = idx >> 5, g = idx & 31;
    const float* src = Wt + (size_t)o * D_ + g * 16;
    float v[16];
#pragma unroll
    for (int q = 0; q < 4; q++) {
        float4 f = *(const float4*)(src + q * 4);
        v[q * 4 + 0] = f.x; v[q * 4 + 1] = f.y; v[q * 4 + 2] = f.z; v[q * 4 + 3] = f.w;
    }
    uint32_t hw_[8];
#pragma unroll
    for (int w = 0; w < 8; w++) {
        int k = (w & 1) ? (w + 7) : w;
        hw_[w] = pack_h2(__float2half_rn(v[k]), __float2half_rn(v[k + 1]));
    }
    uint32_t* dh = (uint32_t*)d_wt_h + (size_t)o * 256 + g * 8;
    *(uint4*)(dh + 0) = make_uint4(hw_[0], hw_[1], hw_[2], hw_[3]);
    *(uint4*)(dh + 4) = make_uint4(hw_[4], hw_[5], hw_[6], hw_[7]);
}

// =====================================================================
// Prep 2: feat_a [b][k][hw] fp32 -> d_ft_hi / d_ft_lo [b][hw][kperm] fp16
// grid = 1024 (b), 256 threads, dyn smem = 512*68*4
// =====================================================================
#define FT_PAD 68
__global__ __launch_bounds__(256) void k_prep_feat(const float* __restrict__ feat_a) {
    extern __shared__ float sm[];    // [512][68]
    const int b = blockIdx.x;
    const int t = threadIdx.x;
    const float* src = feat_a + (size_t)b * D_ * HWA2;
#pragma unroll
    for (int r = 0; r < 32; r++) {
        int fi = r * 256 + t;            // float4 index
        int row = fi >> 4, c4 = fi & 15;
        float4 f = *(const float4*)(src + fi * 4);
        *(float4*)(sm + row * FT_PAD + c4 * 4) = f;
    }
    __syncthreads();
    const int hw = t >> 2, kseg = t & 3;
    uint32_t* dh = (uint32_t*)d_ft_hi + ((size_t)b * HWA2 + hw) * 256;
    uint32_t* dl = (uint32_t*)d_ft_lo + ((size_t)b * HWA2 + hw) * 256;
#pragma unroll
    for (int g = 0; g < 8; g++) {
        int kbase = kseg * 128 + g * 16;
        uint32_t hw_[8], lw_[8];
#pragma unroll
        for (int w = 0; w < 8; w++) {
            int k = (w & 1) ? (w + 7) : w;
            float v0 = sm[(kbase + k) * FT_PAD + hw];
            float v1 = sm[(kbase + k + 1) * FT_PAD + hw];
            __half h0 = __float2half_rn(v0), h1 = __float2half_rn(v1);
            hw_[w] = pack_h2(h0, h1);
            lw_[w] = pack_h2(__float2half_rn((v0 - __half2float(h0)) * LO_SCALE),
                             __float2half_rn((v1 - __half2float(h1)) * LO_SCALE));
        }
        int wbase = (kbase >> 1);
        *(uint4*)(dh + wbase + 0) = make_uint4(hw_[0], hw_[1], hw_[2], hw_[3]);
        *(uint4*)(dh + wbase + 4) = make_uint4(hw_[4], hw_[5], hw_[6], hw_[7]);
        *(uint4*)(dl + wbase + 0) = make_uint4(lw_[0], lw_[1], lw_[2], lw_[3]);
        *(uint4*)(dl + wbase + 4) = make_uint4(lw_[4], lw_[5], lw_[6], lw_[7]);
    }
}

// =====================================================================
// k_fa_mma: fa[b,o] = max_hw( feat[b,:,hw] . Wt[o,:] ) + bt[o]
// fp16 asymmetric 2-pass: acc_h = Wt_h . f_hi,  acc_l = Wt_h . f_lo(x2048)
// final = acc_h + acc_l/2048.
// one CTA per b (grid 1024), 256 threads = 8 warps.
// feat[b] resident (hi/lo), Wt streamed in 128o x 128k chunks, dbl buffered.
// Conflict-free strides: row bytes ≡ 32 (mod 128).
// =====================================================================
#define FEAT_OFF  1024
#define FEAT_ROWB 1056                  // 1024 B data + 32 pad
#define FEAT_HSZ  (64 * FEAT_ROWB)      // 67584
#define WT_OFF    (FEAT_OFF + 2 * FEAT_HSZ)   // 136192
#define WT_ROWB   288                   // 256 B data + 32 pad
#define WT_BUFSZ  (128 * WT_ROWB)       // 36864
#define FA_SMEM   (WT_OFF + 2 * WT_BUFSZ)     // 209920

__device__ __forceinline__ void fa_load_wt(uint32_t sb, int buf, int otp, int kc, int t) {
#pragma unroll
    for (int r = 0; r < 8; r++) {
        int idx = r * 256 + t;          // 2048 x 16B
        int row = idx >> 4, c = idx & 15;
        const __half* src = d_wt_h + ((size_t)(otp * 128 + row) * D_ + kc * 128 + c * 8);
        uint32_t dst = sb + WT_OFF + buf * WT_BUFSZ + row * WT_ROWB + c * 16;
        CP_ASYNC16(dst, src);
    }
}

__global__ void __launch_bounds__(256, 1) k_fa_mma(const float* __restrict__ bt) {
    extern __shared__ char smem[];
    float* red = (float*)smem;          // 256 floats used
    uint32_t sb = smem_to_u32(smem);
    const int b = blockIdx.x;
    const int t = threadIdx.x;
    const int w = t >> 5, lane = t & 31;
    const int ot2 = w >> 2, oy = (w >> 1) & 1, hx = w & 1;
    const int j = lane & 3, r4 = lane >> 2;

    // initial loads: full feat[b] (hi+lo fp16) + Wt chunk 0
#pragma unroll
    for (int r = 0; r < 32; r++) {
        int idx = r * 256 + t;          // 8192 x 16B
        int h = idx >> 12, rem = idx & 4095;
        int row = rem >> 6, c = rem & 63;
        const __half* src = (h ? d_ft_lo : d_ft_hi)
            + ((size_t)(b * HWA2 + row) * D_ + c * 8);
        uint32_t dst = sb + FEAT_OFF + h * FEAT_HSZ + row * FEAT_ROWB + c * 16;
        CP_ASYNC16(dst, src);
    }
    fa_load_wt(sb, 0, 0, 0, t);
    CP_ASYNC_COMMIT();

    float acch[2][4][4], accl[2][4][4];
#pragma unroll
    for (int mf = 0; mf < 2; mf++)
#pragma unroll
        for (int nf = 0; nf < 4; nf++)
#pragma unroll
            for (int q = 0; q < 4; q++) { acch[mf][nf][q] = 0.f; accl[mf][nf][q] = 0.f; }

    const int oA = ot2 * 64 + oy * 32 + r4;
    const int hwB = hx * 32 + r4;

    for (int it = 0; it < 16; it++) {
        const int otp = it >> 2, kc = it & 3, buf = it & 1;
        if (it + 1 < 16) {
            fa_load_wt(sb, buf ^ 1, (it + 1) >> 2, (it + 1) & 3, t);
            CP_ASYNC_COMMIT();
            CP_ASYNC_WAIT1();
        } else {
            CP_ASYNC_WAIT0();
        }
        __syncthreads();

        const uint32_t wtb = sb + WT_OFF + buf * WT_BUFSZ;
#pragma unroll
        for (int kst = 0; kst < 8; kst++) {
            const int ks = kc * 8 + kst;
            uint32_t a[2][4];
#pragma unroll
            for (int mf = 0; mf < 2; mf++) {
                uint32_t base = wtb + (oA + mf * 16) * WT_ROWB + kst * 32 + j * 8;
                LDS64(a[mf][0], a[mf][2], base);
                LDS64(a[mf][1], a[mf][3], base + 8 * WT_ROWB);
            }
            uint32_t bh[4][2], bl[4][2];
#pragma unroll
            for (int nf = 0; nf < 4; nf++) {
                uint32_t bb = sb + FEAT_OFF + (hwB + nf * 8) * FEAT_ROWB + ks * 32 + j * 8;
                LDS64(bh[nf][0], bh[nf][1], bb);
                LDS64(bl[nf][0], bl[nf][1], bb + FEAT_HSZ);
            }
#pragma unroll
            for (int mf = 0; mf < 2; mf++)
#pragma unroll
                for (int nf = 0; nf < 4; nf++) {
                    MMA_F16(acch[mf][nf], a[mf], bh[nf]);
                    MMA_F16(accl[mf][nf], a[mf], bl[nf]);
                }
        }

        if (kc == 3) {
            // combine + max over hw + cross-warp reduce + store
#pragma unroll
            for (int mf = 0; mf < 2; mf++) {
                float m0 = -3.4e38f, m1 = -3.4e38f;
#pragma unroll
                for (int nf = 0; nf < 4; nf++) {
                    float v0 = acch[mf][nf][0] + accl[mf][nf][0] * LO_INV;
                    float v1 = acch[mf][nf][1] + accl[mf][nf][1] * LO_INV;
                    float v2 = acch[mf][nf][2] + accl[mf][nf][2] * LO_INV;
                    float v3 = acch[mf][nf][3] + accl[mf][nf][3] * LO_INV;
                    m0 = fmaxf(m0, fmaxf(v0, v1));
                    m1 = fmaxf(m1, fmaxf(v2, v3));
                }
                m0 = fmaxf(m0, __shfl_xor_sync(0xffffffffu, m0, 1));
                m0 = fmaxf(m0, __shfl_xor_sync(0xffffffffu, m0, 2));
                m1 = fmaxf(m1, __shfl_xor_sync(0xffffffffu, m1, 1));
                m1 = fmaxf(m1, __shfl_xor_sync(0xffffffffu, m1, 2));
                if (j == 0) {
                    red[ot2 * 128 + hx * 64 + oy * 32 + mf * 16 + r4] = m0;
                    red[ot2 * 128 + hx * 64 + oy * 32 + mf * 16 + r4 + 8] = m1;
                }
            }
            __syncthreads();
            if (t < 128) {
                int o2 = t >> 6, ol = t & 63;
                float v = fmaxf(red[o2 * 128 + ol], red[o2 * 128 + 64 + ol]);
                int og = otp * 128 + o2 * 64 + ol;
                d_fa[(size_t)b * D_ + og] = v + bt[og];
            }
#pragma unroll
            for (int mf = 0; mf < 2; mf++)
#pragma unroll
                for (int nf = 0; nf < 4; nf++)
#pragma unroll
                    for (int q = 0; q < 4; q++) { acch[mf][nf][q] = 0.f; accl[mf][nf][q] = 0.f; }
        }
        __syncthreads();
    }
}

// =====================================================================
// K2: g[b,c,i] = sum_hw feat_v[b,i,hw] * cam[b,c,hw]   (float2 over hw)
// =====================================================================
__global__ __launch_bounds__(256) void k_g(const float* __restrict__ feat_v,
                                           const float* __restrict__ cam) {
    __shared__ float sC[32][34];
    __shared__ float sF[128][34];

    const int b  = blockIdx.x;
    const int it = blockIdx.y;
    const int t  = threadIdx.x;
    const int tx = t & 31;
    const int ty = t >> 5;

    float acc[4][4];
#pragma unroll
    for (int ci = 0; ci < 4; ci++)
#pragma unroll
        for (int ij = 0; ij < 4; ij++) acc[ci][ij] = 0.f;

    for (int hw0 = 0; hw0 < HWV2; hw0 += 32) {
#pragma unroll
        for (int r = 0; r < 4; r++) {
            int idx = r * 256 + t;
            int c = idx >> 5, kk = idx & 31;
            int hw = hw0 + kk;
            sC[c][kk] = (hw < HWV2) ? cam[((size_t)b * CLS_ + c) * HWV2 + hw] : 0.f;
        }
#pragma unroll
        for (int r = 0; r < 16; r++) {
            int idx = r * 256 + t;
            int i = idx >> 5, kk = idx & 31;
            int hw = hw0 + kk;
            sF[i][kk] = (hw < HWV2)
                ? feat_v[((size_t)b * D_ + it * 128 + i) * HWV2 + hw] : 0.f;
        }
        __syncthreads();
#pragma unroll
        for (int kk2 = 0; kk2 < 16; kk2++) {
            float2 a2[4], f2[4];
#pragma unroll
            for (int ci = 0; ci < 4; ci++) a2[ci] = *(const float2*)&sC[ty + 8 * ci][kk2 * 2];
#pragma unroll
            for (int ij = 0; ij < 4; ij++) f2[ij] = *(const float2*)&sF[tx + 32 * ij][kk2 * 2];
#pragma unroll
            for (int ci = 0; ci < 4; ci++)
#pragma unroll
                for (int ij = 0; ij < 4; ij++) {
                    acc[ci][ij] = fmaf(a2[ci].x, f2[ij].x, acc[ci][ij]);
                    acc[ci][ij] = fmaf(a2[ci].y, f2[ij].y, acc[ci][ij]);
                }
        }
        __syncthreads();
    }
#pragma unroll
    for (int ci = 0; ci < 4; ci++) {
        int c = ty + 8 * ci;
#pragma unroll
        for (int ij = 0; ij < 4; ij++) {
            int i = it * 128 + tx + 32 * ij;
            d_g[((size_t)b * CLS_ + c) * D_ + i] = acc[ci][ij];
        }
    }
}

__global__ void k_camsum(const float* __restrict__ cam) {
    int b = blockIdx.x;
    int w = threadIdx.x >> 5, lane = threadIdx.x & 31;
    for (int c = w; c < CLS_; c += 8) {
        const float* p = cam + ((size_t)b * CLS_ + c) * HWV2;
        float s = 0.f;
        for (int k = lane; k < HWV2; k += 32) s += p[k];
#pragma unroll
        for (int off = 16; off; off >>= 1) s += __shfl_xor_sync(0xffffffffu, s, off);
        if (!lane) d_camsum[b * CLS_ + c] = s;
    }
}

// =====================================================================
// Wvs[o,i] = sum_d Wv[o,d]*Ws[d,i]  — tiled 32o x 64i, grid (4, 8)
// =====================================================================
__global__ __launch_bounds__(256) void k_wvs(const float* __restrict__ Wv,
                                             const float* __restrict__ Ws) {
    __shared__ float sV[32][65];
    __shared__ float sS[64][65];
    const int oT = blockIdx.x, iT = blockIdx.y;
    const int t = threadIdx.x;
    const int tx = t & 31, ty = t >> 5;

    float acc[4][2];
#pragma unroll
    for (int a = 0; a < 4; a++) { acc[a][0] = 0.f; acc[a][1] = 0.f; }

    for (int k0 = 0; k0 < D_; k0 += 64) {
#pragma unroll
        for (int r = 0; r < 8; r++) {
            int idx = r * 256 + t;
            int o = idx >> 6, kk = idx & 63;
            sV[o][kk] = Wv[(size_t)(oT * 32 + o) * D_ + k0 + kk];
        }
#pragma unroll
        for (int r = 0; r < 16; r++) {
            int idx = r * 256 + t;
            int kk = idx >> 6, i = idx & 63;
            sS[kk][i] = Ws[(size_t)(k0 + kk) * D_ + iT * 64 + i];
        }
        __syncthreads();
#pragma unroll
        for (int kk = 0; kk < 64; kk++) {
            float bb0 = sS[kk][tx], bb1 = sS[kk][tx + 32];
#pragma unroll
            for (int a = 0; a < 4; a++) {
                float av = sV[ty * 4 + a][kk];
                acc[a][0] = fmaf(av, bb0, acc[a][0]);
                acc[a][1] = fmaf(av, bb1, acc[a][1]);
            }
        }
        __syncthreads();
    }
#pragma unroll
    for (int a = 0; a < 4; a++) {
        int o = oT * 32 + ty * 4 + a;
        d_Wvs[(size_t)o * D_ + iT * 64 + tx] = acc[a][0];
        d_Wvs[(size_t)o * D_ + iT * 64 + tx + 32] = acc[a][1];
    }
}

__global__ void k_wbs(const float* __restrict__ Wv, const float* __restrict__ bs) {
    int o = blockIdx.x, lane = threadIdx.x;
    float s = 0.f;
    for (int d = lane; d < D_; d += 32) s = fmaf(Wv[(size_t)o * D_ + d], bs[d], s);
#pragma unroll
    for (int off = 16; off; off >>= 1) s += __shfl_xor_sync(0xffffffffu, s, off);
    if (!lane) d_wbs[o] = s;
}

// =====================================================================
// Generic C[m,o] = sum_i A[m,i]*B[o,i], N=128, K=512
// =====================================================================
__global__ __launch_bounds__(256) void k_gemm(int mode, const float* __restrict__ Bext,
                                              const float* __restrict__ bias) {
    __shared__ float sA[128][33];
    __shared__ float sB[128][33];

    const float* A = (mode == 0) ? d_fa : d_g;
    const float* B = (mode == 0) ? Bext : d_Wvs;
    float* C       = (mode == 0) ? d_ta : d_tv;

    const int m0 = blockIdx.x * 128;
    const int t  = threadIdx.x;
    const int tx = t & 15, ty = t >> 4;

    float acc[8][8];
#pragma unroll
    for (int i = 0; i < 8; i++)
#pragma unroll
        for (int jq = 0; jq < 8; jq++) acc[i][jq] = 0.f;

    for (int k0 = 0; k0 < D_; k0 += 32) {
#pragma unroll
        for (int r = 0; r < 16; r++) {
            int idx = r * 256 + t;
            int mm = idx >> 5, kk = idx & 31;
            sA[mm][kk] = A[(size_t)(m0 + mm) * D_ + k0 + kk];
            sB[mm][kk] = B[(size_t)mm * D_ + k0 + kk];
        }
        __syncthreads();
#pragma unroll
        for (int kk = 0; kk < 32; kk++) {
            float a[8], b[8];
#pragma unroll
            for (int mi = 0; mi < 8; mi++) a[mi] = sA[ty + 16 * mi][kk];
#pragma unroll
            for (int oj = 0; oj < 8; oj++) b[oj] = sB[tx + 16 * oj][kk];
#pragma unroll
            for (int mi = 0; mi < 8; mi++)
#pragma unroll
                for (int oj = 0; oj < 8; oj++)
                    acc[mi][oj] = fmaf(a[mi], b[oj], acc[mi][oj]);
        }
        __syncthreads();
    }
#pragma unroll
    for (int mi = 0; mi < 8; mi++) {
        int m = m0 + ty + 16 * mi;
        float cs = (mode == 1) ? d_camsum[m] : 0.f;
        float inv = (mode == 1) ? (1.f / (cs + 1e-10f)) : 0.f;
#pragma unroll
        for (int oj = 0; oj < 8; oj++) {
            int o = tx + 16 * oj;
            float v = acc[mi][oj];
            if (mode == 0) {
                C[(size_t)m * DOUT + o] = v + bias[o];
            } else {
                C[(size_t)m * DOUT + o] = (v + d_wbs[o] * cs) * inv + bias[o];
            }
        }
    }
}

// =====================================================================
// losses
// =====================================================================
__global__ void k_loss(const float* __restrict__ pred_a, const float* __restrict__ pred_v,
                       const int* __restrict__ rand_frames, const int* __restrict__ rand_classes,
                       float* __restrict__ out) {
    const int s = blockIdx.x, c = blockIdx.y;
    const int f = threadIdx.x >> 5, lane = threadIdx.x & 31;

    const float pa = pred_a[s * CLS_ + c];
    const bool aa = pa > 0.3f;
    const int num = (int)(pa * (float)FRM);

    const float* tap = d_ta + (size_t)(s * CLS_ + c) * DOUT;
    const float* tvp = d_tv + (size_t)((s * FRM + f) * CLS_ + c) * DOUT;
    const int rf = rand_frames[(s * CLS_ + c) * FRM + f];
    const int rc = rand_classes[(s * CLS_ + c) * FRM + f];
    const float* tvd = d_tv + (size_t)(((s ^ 1) * FRM + rf) * CLS_ + rc) * DOUT;

    float sco = 0.f, sdi = 0.f;
#pragma unroll
    for (int jq = 0; jq < 4; jq++) {
        int o = lane + 32 * jq;
        float t0 = tap[o];
        float d0 = t0 - tvp[o]; sco = fmaf(d0, d0, sco);
        float d1 = t0 - tvd[o]; sdi = fmaf(d1, d1, sdi);
    }
#pragma unroll
    for (int off = 16; off; off >>= 1) {
        sco += __shfl_xor_sync(0xffffffffu, sco, off);
        sdi += __shfl_xor_sync(0xffffffffu, sdi, off);
    }
    if (!lane) {
        float pv = 1.f / (1.f + expf(-pred_v[(s * FRM + f) * CLS_ + c]));
        bool av = pv > 0.3f;
        float mco = (aa && av) ? 1.f : 0.f;
        float mdi = (aa && (f < num)) ? 1.f : 0.f;
        out[((0 * S_ + s) * CLS_ + c) * FRM + f] = sco * (1.f / 128.f) * mco;
        out[((1 * S_ + s) * CLS_ + c) * FRM + f] = sdi * (1.f / 128.f) * mdi;
    }
}

// =====================================================================
extern "C" void kernel_launch(void* const* d_in, const int* in_sizes, int n_in,
                              void* d_out, int out_size) {
    const float* feat_a = (const float*)d_in[0];
    const float* pred_a = (const float*)d_in[1];
    const float* feat_v = (const float*)d_in[2];
    const float* pred_v = (const float*)d_in[3];
    const float* cam    = (const float*)d_in[4];
    const int* rand_frames  = (const int*)d_in[5];
    const int* rand_classes = (const int*)d_in[6];
    const float* Wt = (const float*)d_in[7];
    const float* bt = (const float*)d_in[8];
    const float* Ws = (const float*)d_in[9];
    const float* bs = (const float*)d_in[10];
    const float* Wa = (const float*)d_in[11];
    const float* ba = (const float*)d_in[12];
    const float* Wv = (const float*)d_in[13];
    const float* bv = (const float*)d_in[14];
    float* out = (float*)d_out;

    static bool attr_set = false;
    if (!attr_set) {
        cudaFuncSetAttribute(k_fa_mma, cudaFuncAttributeMaxDynamicSharedMemorySize, FA_SMEM);
        cudaFuncSetAttribute(k_prep_feat, cudaFuncAttributeMaxDynamicSharedMemorySize,
                             D_ * FT_PAD * 4);
        attr_set = true;
    }

    // prep (fp16 permuted layouts)
    k_cvt_wt<<<64, 256>>>(Wt);
    k_prep_feat<<<BA, 256, D_ * FT_PAD * 4>>>(feat_a);
    // main tensor-core GEMM + max
    k_fa_mma<<<BA, 256, FA_SMEM>>>(bt);
    // video path
    k_g<<<dim3(BV, 4), 256>>>(feat_v, cam);
    k_camsum<<<BV, 256>>>(cam);
    k_wvs<<<dim3(4, 8), 256>>>(Wv, Ws);
    k_wbs<<<DOUT, 32>>>(Wv, bs);
    // projections
    k_gemm<<<BA / 128, 256>>>(0, Wa, ba);
    k_gemm<<<(BV * CLS_) / 128, 256>>>(1, nullptr, bv);
    // losses
    k_loss<<<dim3(S_, CLS_), 256>>>(pred_a, pred_v, rand_frames, rand_classes, out);
}

// round 5
// speedup vs baseline: 2.3043x; 1.2306x over previous
#include <cuda_runtime.h>
#include <cuda_fp16.h>
#include <math.h>
#include <cstdint>

// Problem constants
#define S_   32
#define FRM  8
#define CLS_ 32
#define D_   512
#define HWA2 64      // 8*8
#define HWV2 196     // 14*14
#define HWP  208     // padded to 13*16
#define DOUT 128
#define BA   (S_*CLS_)   // 1024
#define BV   (S_*FRM)    // 256

// ---------------- device scratch ----------------
__device__ float d_fa[BA * D_];
__device__ float d_ta[BA * DOUT];
__device__ float d_g[BV * CLS_ * D_];
__device__ float d_camsum[BV * CLS_];
__device__ float d_tv[BV * CLS_ * DOUT];
__device__ float d_Wvs[DOUT * D_];
__device__ float d_wbs[DOUT];
// permuted fp16 copies
__device__ __half d_wt_h[D_ * D_];                      // [o][kperm]
__device__ __half d_ft_h[(size_t)BA * HWA2 * D_];       // [b][hw][kperm]
__device__ __half d_fv_h[(size_t)BV * D_ * HWP];        // [b][i][hwperm]
__device__ __half d_cam_h[(size_t)BV * CLS_ * HWP];     // [b][c][hwperm]

// =============== small asm helpers ===============
__device__ __forceinline__ uint32_t smem_to_u32(const void* p) {
    uint32_t a;
    asm("{ .reg .u64 t; cvta.to.shared.u64 t, %1; cvt.u32.u64 %0, t; }" : "=r"(a) : "l"(p));
    return a;
}
#define CP_ASYNC16(sm, g) \
    asm volatile("cp.async.cg.shared.global [%0], [%1], 16;" :: "r"((uint32_t)(sm)), "l"(g) : "memory")
#define CP_ASYNC_COMMIT() asm volatile("cp.async.commit_group;" ::: "memory")
#define CP_ASYNC_WAIT0()  asm volatile("cp.async.wait_group 0;" ::: "memory")
#define CP_ASYNC_WAIT1()  asm volatile("cp.async.wait_group 1;" ::: "memory")

#define LDS64(r0, r1, addr) \
    asm volatile("ld.shared.v2.b32 {%0,%1}, [%2];" : "=r"(r0), "=r"(r1) : "r"((uint32_t)(addr)))

#define MMA_F16(d, a, b) \
    asm volatile("mma.sync.aligned.m16n8k16.row.col.f32.f16.f16.f32 " \
        "{%0,%1,%2,%3}, {%4,%5,%6,%7}, {%8,%9}, {%0,%1,%2,%3};" \
        : "+f"((d)[0]), "+f"((d)[1]), "+f"((d)[2]), "+f"((d)[3]) \
        : "r"((a)[0]), "r"((a)[1]), "r"((a)[2]), "r"((a)[3]), "r"((b)[0]), "r"((b)[1]))

__device__ __forceinline__ uint32_t pack_h2(__half a, __half b) {
    __half2 p = __halves2half2(a, b);
    return *(uint32_t*)&p;
}

// k-permutation within a 16-group (matches m16n8k16 frag layout):
// stored word w (fp16 pair): w even -> k = w ; w odd -> k = w + 7.

// =====================================================================
// Prep 1: Wt fp32 -> permuted fp16.
// =====================================================================
__global__ __launch_bounds__(256) void k_cvt_wt(const float* __restrict__ Wt) {
    int idx = blockIdx.x * 256 + threadIdx.x;
    int o = idx >> 5, g = idx & 31;
    const float* src = Wt + (size_t)o * D_ + g * 16;
    float v[16];
#pragma unroll
    for (int q = 0; q < 4; q++) {
        float4 f = *(const float4*)(src + q * 4);
        v[q * 4 + 0] = f.x; v[q * 4 + 1] = f.y; v[q * 4 + 2] = f.z; v[q * 4 + 3] = f.w;
    }
    uint32_t hw_[8];
#pragma unroll
    for (int w = 0; w < 8; w++) {
        int k = (w & 1) ? (w + 7) : w;
        hw_[w] = pack_h2(__float2half_rn(v[k]), __float2half_rn(v[k + 1]));
    }
    uint32_t* dh = (uint32_t*)d_wt_h + (size_t)o * 256 + g * 8;
    *(uint4*)(dh + 0) = make_uint4(hw_[0], hw_[1], hw_[2], hw_[3]);
    *(uint4*)(dh + 4) = make_uint4(hw_[4], hw_[5], hw_[6], hw_[7]);
}

// =====================================================================
// Prep 2: feat_a [b][k][hw] fp32 -> d_ft_h [b][hw][kperm] fp16
// =====================================================================
#define FT_PAD 68
__global__ __launch_bounds__(256) void k_prep_feat(const float* __restrict__ feat_a) {
    extern __shared__ float sm[];    // [512][68]
    const int b = blockIdx.x;
    const int t = threadIdx.x;
    const float* src = feat_a + (size_t)b * D_ * HWA2;
#pragma unroll
    for (int r = 0; r < 32; r++) {
        int fi = r * 256 + t;
        int row = fi >> 4, c4 = fi & 15;
        float4 f = *(const float4*)(src + fi * 4);
        *(float4*)(sm + row * FT_PAD + c4 * 4) = f;
    }
    __syncthreads();
    const int hw = t >> 2, kseg = t & 3;
    uint32_t* dh = (uint32_t*)d_ft_h + ((size_t)b * HWA2 + hw) * 256;
#pragma unroll
    for (int g = 0; g < 8; g++) {
        int kbase = kseg * 128 + g * 16;
        uint32_t hw_[8];
#pragma unroll
        for (int w = 0; w < 8; w++) {
            int k = (w & 1) ? (w + 7) : w;
            hw_[w] = pack_h2(__float2half_rn(sm[(kbase + k) * FT_PAD + hw]),
                             __float2half_rn(sm[(kbase + k + 1) * FT_PAD + hw]));
        }
        int wbase = (kbase >> 1);
        *(uint4*)(dh + wbase + 0) = make_uint4(hw_[0], hw_[1], hw_[2], hw_[3]);
        *(uint4*)(dh + wbase + 4) = make_uint4(hw_[4], hw_[5], hw_[6], hw_[7]);
    }
}

// =====================================================================
// Prep 3: feat_v [b][i][hw] fp32 -> d_fv_h [b][i][hwperm] (pad 208)
// 16 rows per block, thread = (row, group)
// =====================================================================
__global__ __launch_bounds__(256) void k_prep_fv(const float* __restrict__ feat_v) {
    const int t = threadIdx.x;
    const int g = t & 15, rloc = t >> 4;
    const long row = (long)blockIdx.x * 16 + rloc;   // 0 .. 131071
    if (g >= 13) return;
    const float* src = feat_v + row * HWV2 + g * 16;
    float v[16];
#pragma unroll
    for (int q = 0; q < 16; q++) {
        int hw = g * 16 + q;
        v[q] = (hw < HWV2) ? src[q] : 0.f;
    }
    uint32_t wv[8];
#pragma unroll
    for (int w = 0; w < 8; w++) {
        int k = (w & 1) ? (w + 7) : w;
        wv[w] = pack_h2(__float2half_rn(v[k]), __float2half_rn(v[k + 1]));
    }
    uint32_t* dst = (uint32_t*)d_fv_h + row * (HWP / 2) + g * 8;
    *(uint4*)(dst + 0) = make_uint4(wv[0], wv[1], wv[2], wv[3]);
    *(uint4*)(dst + 4) = make_uint4(wv[4], wv[5], wv[6], wv[7]);
}

// Prep 4: cam -> d_cam_h (same permutation), 8192 rows
__global__ __launch_bounds__(256) void k_prep_cam(const float* __restrict__ cam) {
    const int t = threadIdx.x;
    const int g = t & 15, rloc = t >> 4;
    const long row = (long)blockIdx.x * 16 + rloc;   // 0 .. 8191
    if (g >= 13) return;
    const float* src = cam + row * HWV2 + g * 16;
    float v[16];
#pragma unroll
    for (int q = 0; q < 16; q++) {
        int hw = g * 16 + q;
        v[q] = (hw < HWV2) ? src[q] : 0.f;
    }
    uint32_t wv[8];
#pragma unroll
    for (int w = 0; w < 8; w++) {
        int k = (w & 1) ? (w + 7) : w;
        wv[w] = pack_h2(__float2half_rn(v[k]), __float2half_rn(v[k + 1]));
    }
    uint32_t* dst = (uint32_t*)d_cam_h + row * (HWP / 2) + g * 8;
    *(uint4*)(dst + 0) = make_uint4(wv[0], wv[1], wv[2], wv[3]);
    *(uint4*)(dst + 4) = make_uint4(wv[4], wv[5], wv[6], wv[7]);
}

// =====================================================================
// k_fa_mma: fa[b,o] = max_hw( feat[b,:,hw] . Wt[o,:] ) + bt[o]
// single-pass fp16. one CTA per b, 256 threads = 8 warps.
// feat[b] resident, Wt streamed 128o x 128k chunks, dbl buffered.
// =====================================================================
#define FEAT_OFF  1024
#define FEAT_ROWB 1056                  // 1024 B data + 32 pad (≡32 mod 128)
#define FEAT_SZ   (64 * FEAT_ROWB)      // 67584
#define WT_OFF    (FEAT_OFF + FEAT_SZ)  // 68608
#define WT_ROWB   288                   // 256 B data + 32 pad
#define WT_BUFSZ  (128 * WT_ROWB)       // 36864
#define FA_SMEM   (WT_OFF + 2 * WT_BUFSZ)     // 142336

__device__ __forceinline__ void fa_load_wt(uint32_t sb, int buf, int otp, int kc, int t) {
#pragma unroll
    for (int r = 0; r < 8; r++) {
        int idx = r * 256 + t;          // 2048 x 16B
        int row = idx >> 4, c = idx & 15;
        const __half* src = d_wt_h + ((size_t)(otp * 128 + row) * D_ + kc * 128 + c * 8);
        uint32_t dst = sb + WT_OFF + buf * WT_BUFSZ + row * WT_ROWB + c * 16;
        CP_ASYNC16(dst, src);
    }
}

__global__ void __launch_bounds__(256, 1) k_fa_mma(const float* __restrict__ bt) {
    extern __shared__ char smem[];
    float* red = (float*)smem;
    uint32_t sb = smem_to_u32(smem);
    const int b = blockIdx.x;
    const int t = threadIdx.x;
    const int w = t >> 5, lane = t & 31;
    const int ot2 = w >> 2, oy = (w >> 1) & 1, hx = w & 1;
    const int j = lane & 3, r4 = lane >> 2;

    // initial loads: feat[b] fp16 + Wt chunk 0
#pragma unroll
    for (int r = 0; r < 16; r++) {
        int idx = r * 256 + t;          // 4096 x 16B
        int row = idx >> 6, c = idx & 63;
        const __half* src = d_ft_h + ((size_t)(b * HWA2 + row) * D_ + c * 8);
        uint32_t dst = sb + FEAT_OFF + row * FEAT_ROWB + c * 16;
        CP_ASYNC16(dst, src);
    }
    fa_load_wt(sb, 0, 0, 0, t);
    CP_ASYNC_COMMIT();

    float acc[2][4][4];
#pragma unroll
    for (int mf = 0; mf < 2; mf++)
#pragma unroll
        for (int nf = 0; nf < 4; nf++)
#pragma unroll
            for (int q = 0; q < 4; q++) acc[mf][nf][q] = 0.f;

    const int oA = ot2 * 64 + oy * 32 + r4;
    const int hwB = hx * 32 + r4;

    for (int it = 0; it < 16; it++) {
        const int otp = it >> 2, kc = it & 3, buf = it & 1;
        if (it + 1 < 16) {
            fa_load_wt(sb, buf ^ 1, (it + 1) >> 2, (it + 1) & 3, t);
            CP_ASYNC_COMMIT();
            CP_ASYNC_WAIT1();
        } else {
            CP_ASYNC_WAIT0();
        }
        __syncthreads();

        const uint32_t wtb = sb + WT_OFF + buf * WT_BUFSZ;
#pragma unroll
        for (int kst = 0; kst < 8; kst++) {
            const int ks = kc * 8 + kst;
            uint32_t a[2][4];
#pragma unroll
            for (int mf = 0; mf < 2; mf++) {
                uint32_t base = wtb + (oA + mf * 16) * WT_ROWB + kst * 32 + j * 8;
                LDS64(a[mf][0], a[mf][2], base);
                LDS64(a[mf][1], a[mf][3], base + 8 * WT_ROWB);
            }
            uint32_t bh[4][2];
#pragma unroll
            for (int nf = 0; nf < 4; nf++) {
                uint32_t bb = sb + FEAT_OFF + (hwB + nf * 8) * FEAT_ROWB + ks * 32 + j * 8;
                LDS64(bh[nf][0], bh[nf][1], bb);
            }
#pragma unroll
            for (int mf = 0; mf < 2; mf++)
#pragma unroll
                for (int nf = 0; nf < 4; nf++)
                    MMA_F16(acc[mf][nf], a[mf], bh[nf]);
        }

        if (kc == 3) {
#pragma unroll
            for (int mf = 0; mf < 2; mf++) {
                float m0 = -3.4e38f, m1 = -3.4e38f;
#pragma unroll
                for (int nf = 0; nf < 4; nf++) {
                    m0 = fmaxf(m0, fmaxf(acc[mf][nf][0], acc[mf][nf][1]));
                    m1 = fmaxf(m1, fmaxf(acc[mf][nf][2], acc[mf][nf][3]));
                }
                m0 = fmaxf(m0, __shfl_xor_sync(0xffffffffu, m0, 1));
                m0 = fmaxf(m0, __shfl_xor_sync(0xffffffffu, m0, 2));
                m1 = fmaxf(m1, __shfl_xor_sync(0xffffffffu, m1, 1));
                m1 = fmaxf(m1, __shfl_xor_sync(0xffffffffu, m1, 2));
                if (j == 0) {
                    red[ot2 * 128 + hx * 64 + oy * 32 + mf * 16 + r4] = m0;
                    red[ot2 * 128 + hx * 64 + oy * 32 + mf * 16 + r4 + 8] = m1;
                }
            }
            __syncthreads();
            if (t < 128) {
                int o2 = t >> 6, ol = t & 63;
                float v = fmaxf(red[o2 * 128 + ol], red[o2 * 128 + 64 + ol]);
                int og = otp * 128 + o2 * 64 + ol;
                d_fa[(size_t)b * D_ + og] = v + bt[og];
            }
#pragma unroll
            for (int mf = 0; mf < 2; mf++)
#pragma unroll
                for (int nf = 0; nf < 4; nf++)
#pragma unroll
                    for (int q = 0; q < 4; q++) acc[mf][nf][q] = 0.f;
        }
        __syncthreads();
    }
}

// =====================================================================
// k_g_mma: g[b,c,i] = sum_hw cam[b,c,hw] * feat_v[b,i,hw]  (fp16 MMA)
// one CTA per b, 256 threads = 8 warps: my = c-tile(16), ix = i-sub(32).
// cam[b] resident; feat_v[b] streamed in 128-i chunks, dbl buffered. K=208.
// =====================================================================
#define GC_OFF   1024
#define G_ROWB   416                   // 208 fp16, ≡32 mod 128
#define GC_SZ    (32 * G_ROWB)         // 13312
#define GF_OFF   (GC_OFF + GC_SZ)      // 14336
#define GF_BUFSZ (128 * G_ROWB)        // 53248
#define KG_SMEM  (GF_OFF + 2 * GF_BUFSZ)  // 120832

__device__ __forceinline__ void g_load_fv(uint32_t sb, int buf, int b, int ic, int t) {
#pragma unroll
    for (int r = 0; r < 13; r++) {
        int idx = r * 256 + t;          // 3328 x 16B
        int row = idx / 26, c = idx % 26;
        const __half* src = d_fv_h + ((size_t)(b * D_) + ic * 128 + row) * HWP + c * 8;
        uint32_t dst = sb + GF_OFF + buf * GF_BUFSZ + row * G_ROWB + c * 16;
        CP_ASYNC16(dst, src);
    }
}

__global__ void __launch_bounds__(256, 1) k_g_mma() {
    extern __shared__ char smem[];
    uint32_t sb = smem_to_u32(smem);
    const int b = blockIdx.x;
    const int t = threadIdx.x;
    const int w = t >> 5, lane = t & 31;
    const int my = w & 1, ix = w >> 1;
    const int j = lane & 3, r4 = lane >> 2;

    // load cam[b] (832 x 16B) + feat chunk 0
#pragma unroll
    for (int r = 0; r < 4; r++) {
        int idx = r * 256 + t;
        if (idx < 832) {
            int row = idx / 26, c = idx % 26;
            const __half* src = d_cam_h + ((size_t)(b * CLS_) + row) * HWP + c * 8;
            CP_ASYNC16(sb + GC_OFF + row * G_ROWB + c * 16, src);
        }
    }
    g_load_fv(sb, 0, b, 0, t);
    CP_ASYNC_COMMIT();

    for (int ic = 0; ic < 4; ic++) {
        const int buf = ic & 1;
        if (ic + 1 < 4) {
            g_load_fv(sb, buf ^ 1, b, ic + 1, t);
            CP_ASYNC_COMMIT();
            CP_ASYNC_WAIT1();
        } else {
            CP_ASYNC_WAIT0();
        }
        __syncthreads();

        float acc[4][4];
#pragma unroll
        for (int nf = 0; nf < 4; nf++)
#pragma unroll
            for (int q = 0; q < 4; q++) acc[nf][q] = 0.f;

        const uint32_t fvb = sb + GF_OFF + buf * GF_BUFSZ;
#pragma unroll
        for (int kst = 0; kst < 13; kst++) {
            uint32_t a[4];
            uint32_t abase = sb + GC_OFF + (my * 16 + r4) * G_ROWB + kst * 32 + j * 8;
            LDS64(a[0], a[2], abase);
            LDS64(a[1], a[3], abase + 8 * G_ROWB);
            uint32_t bh[4][2];
#pragma unroll
            for (int nf = 0; nf < 4; nf++) {
                uint32_t bb = fvb + (ix * 32 + nf * 8 + r4) * G_ROWB + kst * 32 + j * 8;
                LDS64(bh[nf][0], bh[nf][1], bb);
            }
#pragma unroll
            for (int nf = 0; nf < 4; nf++)
                MMA_F16(acc[nf], a, bh[nf]);
        }

        // store this i-chunk's g slice
        const int c0 = my * 16 + r4;
#pragma unroll
        for (int nf = 0; nf < 4; nf++) {
            int ig = ic * 128 + ix * 32 + nf * 8 + 2 * j;
            float* g0 = d_g + ((size_t)b * CLS_ + c0) * D_ + ig;
            g0[0] = acc[nf][0]; g0[1] = acc[nf][1];
            float* g1 = d_g + ((size_t)b * CLS_ + c0 + 8) * D_ + ig;
            g1[0] = acc[nf][2]; g1[1] = acc[nf][3];
        }
        __syncthreads();
    }
}

__global__ void k_camsum(const float* __restrict__ cam) {
    int b = blockIdx.x;
    int w = threadIdx.x >> 5, lane = threadIdx.x & 31;
    for (int c = w; c < CLS_; c += 8) {
        const float* p = cam + ((size_t)b * CLS_ + c) * HWV2;
        float s = 0.f;
        for (int k = lane; k < HWV2; k += 32) s += p[k];
#pragma unroll
        for (int off = 16; off; off >>= 1) s += __shfl_xor_sync(0xffffffffu, s, off);
        if (!lane) d_camsum[b * CLS_ + c] = s;
    }
}

// =====================================================================
// Wvs[o,i] = sum_d Wv[o,d]*Ws[d,i]
// =====================================================================
__global__ __launch_bounds__(256) void k_wvs(const float* __restrict__ Wv,
                                             const float* __restrict__ Ws) {
    __shared__ float sV[32][65];
    __shared__ float sS[64][65];
    const int oT = blockIdx.x, iT = blockIdx.y;
    const int t = threadIdx.x;
    const int tx = t & 31, ty = t >> 5;

    float acc[4][2];
#pragma unroll
    for (int a = 0; a < 4; a++) { acc[a][0] = 0.f; acc[a][1] = 0.f; }

    for (int k0 = 0; k0 < D_; k0 += 64) {
#pragma unroll
        for (int r = 0; r < 8; r++) {
            int idx = r * 256 + t;
            int o = idx >> 6, kk = idx & 63;
            sV[o][kk] = Wv[(size_t)(oT * 32 + o) * D_ + k0 + kk];
        }
#pragma unroll
        for (int r = 0; r < 16; r++) {
            int idx = r * 256 + t;
            int kk = idx >> 6, i = idx & 63;
            sS[kk][i] = Ws[(size_t)(k0 + kk) * D_ + iT * 64 + i];
        }
        __syncthreads();
#pragma unroll
        for (int kk = 0; kk < 64; kk++) {
            float bb0 = sS[kk][tx], bb1 = sS[kk][tx + 32];
#pragma unroll
            for (int a = 0; a < 4; a++) {
                float av = sV[ty * 4 + a][kk];
                acc[a][0] = fmaf(av, bb0, acc[a][0]);
                acc[a][1] = fmaf(av, bb1, acc[a][1]);
            }
        }
        __syncthreads();
    }
#pragma unroll
    for (int a = 0; a < 4; a++) {
        int o = oT * 32 + ty * 4 + a;
        d_Wvs[(size_t)o * D_ + iT * 64 + tx] = acc[a][0];
        d_Wvs[(size_t)o * D_ + iT * 64 + tx + 32] = acc[a][1];
    }
}

__global__ void k_wbs(const float* __restrict__ Wv, const float* __restrict__ bs) {
    int o = blockIdx.x, lane = threadIdx.x;
    float s = 0.f;
    for (int d = lane; d < D_; d += 32) s = fmaf(Wv[(size_t)o * D_ + d], bs[d], s);
#pragma unroll
    for (int off = 16; off; off >>= 1) s += __shfl_xor_sync(0xffffffffu, s, off);
    if (!lane) d_wbs[o] = s;
}

// =====================================================================
// Generic C[m,o] = sum_i A[m,i]*B[o,i], N=128, K=512
// =====================================================================
__global__ __launch_bounds__(256) void k_gemm(int mode, const float* __restrict__ Bext,
                                              const float* __restrict__ bias) {
    __shared__ float sA[128][33];
    __shared__ float sB[128][33];

    const float* A = (mode == 0) ? d_fa : d_g;
    const float* B = (mode == 0) ? Bext : d_Wvs;
    float* C       = (mode == 0) ? d_ta : d_tv;

    const int m0 = blockIdx.x * 128;
    const int t  = threadIdx.x;
    const int tx = t & 15, ty = t >> 4;

    float acc[8][8];
#pragma unroll
    for (int i = 0; i < 8; i++)
#pragma unroll
        for (int jq = 0; jq < 8; jq++) acc[i][jq] = 0.f;

    for (int k0 = 0; k0 < D_; k0 += 32) {
#pragma unroll
        for (int r = 0; r < 16; r++) {
            int idx = r * 256 + t;
            int mm = idx >> 5, kk = idx & 31;
            sA[mm][kk] = A[(size_t)(m0 + mm) * D_ + k0 + kk];
            sB[mm][kk] = B[(size_t)mm * D_ + k0 + kk];
        }
        __syncthreads();
#pragma unroll
        for (int kk = 0; kk < 32; kk++) {
            float a[8], b[8];
#pragma unroll
            for (int mi = 0; mi < 8; mi++) a[mi] = sA[ty + 16 * mi][kk];
#pragma unroll
            for (int oj = 0; oj < 8; oj++) b[oj] = sB[tx + 16 * oj][kk];
#pragma unroll
            for (int mi = 0; mi < 8; mi++)
#pragma unroll
                for (int oj = 0; oj < 8; oj++)
                    acc[mi][oj] = fmaf(a[mi], b[oj], acc[mi][oj]);
        }
        __syncthreads();
    }
#pragma unroll
    for (int mi = 0; mi < 8; mi++) {
        int m = m0 + ty + 16 * mi;
        float cs = (mode == 1) ? d_camsum[m] : 0.f;
        float inv = (mode == 1) ? (1.f / (cs + 1e-10f)) : 0.f;
#pragma unroll
        for (int oj = 0; oj < 8; oj++) {
            int o = tx + 16 * oj;
            float v = acc[mi][oj];
            if (mode == 0) {
                C[(size_t)m * DOUT + o] = v + bias[o];
            } else {
                C[(size_t)m * DOUT + o] = (v + d_wbs[o] * cs) * inv + bias[o];
            }
        }
    }
}

// =====================================================================
// losses
// =====================================================================
__global__ void k_loss(const float* __restrict__ pred_a, const float* __restrict__ pred_v,
                       const int* __restrict__ rand_frames, const int* __restrict__ rand_classes,
                       float* __restrict__ out) {
    const int s = blockIdx.x, c = blockIdx.y;
    const int f = threadIdx.x >> 5, lane = threadIdx.x & 31;

    const float pa = pred_a[s * CLS_ + c];
    const bool aa = pa > 0.3f;
    const int num = (int)(pa * (float)FRM);

    const float* tap = d_ta + (size_t)(s * CLS_ + c) * DOUT;
    const float* tvp = d_tv + (size_t)((s * FRM + f) * CLS_ + c) * DOUT;
    const int rf = rand_frames[(s * CLS_ + c) * FRM + f];
    const int rc = rand_classes[(s * CLS_ + c) * FRM + f];
    const float* tvd = d_tv + (size_t)(((s ^ 1) * FRM + rf) * CLS_ + rc) * DOUT;

    float sco = 0.f, sdi = 0.f;
#pragma unroll
    for (int jq = 0; jq < 4; jq++) {
        int o = lane + 32 * jq;
        float t0 = tap[o];
        float d0 = t0 - tvp[o]; sco = fmaf(d0, d0, sco);
        float d1 = t0 - tvd[o]; sdi = fmaf(d1, d1, sdi);
    }
#pragma unroll
    for (int off = 16; off; off >>= 1) {
        sco += __shfl_xor_sync(0xffffffffu, sco, off);
        sdi += __shfl_xor_sync(0xffffffffu, sdi, off);
    }
    if (!lane) {
        float pv = 1.f / (1.f + expf(-pred_v[(s * FRM + f) * CLS_ + c]));
        bool av = pv > 0.3f;
        float mco = (aa && av) ? 1.f : 0.f;
        float mdi = (aa && (f < num)) ? 1.f : 0.f;
        out[((0 * S_ + s) * CLS_ + c) * FRM + f] = sco * (1.f / 128.f) * mco;
        out[((1 * S_ + s) * CLS_ + c) * FRM + f] = sdi * (1.f / 128.f) * mdi;
    }
}

// =====================================================================
extern "C" void kernel_launch(void* const* d_in, const int* in_sizes, int n_in,
                              void* d_out, int out_size) {
    const float* feat_a = (const float*)d_in[0];
    const float* pred_a = (const float*)d_in[1];
    const float* feat_v = (const float*)d_in[2];
    const float* pred_v = (const float*)d_in[3];
    const float* cam    = (const float*)d_in[4];
    const int* rand_frames  = (const int*)d_in[5];
    const int* rand_classes = (const int*)d_in[6];
    const float* Wt = (const float*)d_in[7];
    const float* bt = (const float*)d_in[8];
    const float* Ws = (const float*)d_in[9];
    const float* bs = (const float*)d_in[10];
    const float* Wa = (const float*)d_in[11];
    const float* ba = (const float*)d_in[12];
    const float* Wv = (const float*)d_in[13];
    const float* bv = (const float*)d_in[14];
    float* out = (float*)d_out;

    static bool attr_set = false;
    if (!attr_set) {
        cudaFuncSetAttribute(k_fa_mma, cudaFuncAttributeMaxDynamicSharedMemorySize, FA_SMEM);
        cudaFuncSetAttribute(k_g_mma, cudaFuncAttributeMaxDynamicSharedMemorySize, KG_SMEM);
        cudaFuncSetAttribute(k_prep_feat, cudaFuncAttributeMaxDynamicSharedMemorySize,
                             D_ * FT_PAD * 4);
        attr_set = true;
    }

    // prep (fp16 permuted layouts)
    k_cvt_wt<<<64, 256>>>(Wt);
    k_prep_feat<<<BA, 256, D_ * FT_PAD * 4>>>(feat_a);
    k_prep_fv<<<(BV * D_) / 16, 256>>>(feat_v);
    k_prep_cam<<<(BV * CLS_) / 16, 256>>>(cam);
    // main tensor-core kernels
    k_fa_mma<<<BA, 256, FA_SMEM>>>(bt);
    k_g_mma<<<BV, 256, KG_SMEM>>>();
    // small stuff
    k_camsum<<<BV, 256>>>(cam);
    k_wvs<<<dim3(4, 8), 256>>>(Wv, Ws);
    k_wbs<<<DOUT, 32>>>(Wv, bs);
    // projections
    k_gemm<<<BA / 128, 256>>>(0, Wa, ba);
    k_gemm<<<(BV * CLS_) / 128, 256>>>(1, nullptr, bv);
    // losses
    k_loss<<<dim3(S_, CLS_), 256>>>(pred_a, pred_v, rand_frames, rand_classes, out);
}

// round 6
// speedup vs baseline: 2.7784x; 1.2057x over previous
#include <cuda_runtime.h>
#include <cuda_fp16.h>
#include <math.h>
#include <cstdint>

// Problem constants
#define S_   32
#define FRM  8
#define CLS_ 32
#define D_   512
#define HWA2 64      // 8*8
#define HWV2 196     // 14*14
#define HWP  208     // padded to 13*16
#define DOUT 128
#define BA   (S_*CLS_)   // 1024
#define BV   (S_*FRM)    // 256

// ---------------- device scratch ----------------
__device__ float d_fa[BA * D_];
__device__ float d_ta[BA * DOUT];
__device__ float d_camsum[BV * CLS_];
__device__ float d_tv[BV * CLS_ * DOUT];
__device__ float d_Wvs[DOUT * D_];
__device__ float d_wbs[DOUT];
// fp16 permuted buffers
__device__ __half d_wt_h[D_ * D_];                      // [o][kperm]
__device__ __half d_ft_h[(size_t)BA * HWA2 * D_];       // [b][hw][kperm]
__device__ __half d_fv_h[(size_t)BV * D_ * HWP];        // [b][i][hwperm]
__device__ __half d_cam_h[(size_t)BV * CLS_ * HWP];     // [b][c][hwperm]
__device__ __half d_g_h[(size_t)BV * CLS_ * D_];        // [m][kperm]  m=b*32+c
__device__ __half d_wvs_h[DOUT * D_];                   // [o][kperm]

// =============== small asm helpers ===============
__device__ __forceinline__ uint32_t smem_to_u32(const void* p) {
    uint32_t a;
    asm("{ .reg .u64 t; cvta.to.shared.u64 t, %1; cvt.u32.u64 %0, t; }" : "=r"(a) : "l"(p));
    return a;
}
#define CP_ASYNC16(sm, g) \
    asm volatile("cp.async.cg.shared.global [%0], [%1], 16;" :: "r"((uint32_t)(sm)), "l"(g) : "memory")
#define CP_ASYNC_COMMIT() asm volatile("cp.async.commit_group;" ::: "memory")
#define CP_ASYNC_WAIT0()  asm volatile("cp.async.wait_group 0;" ::: "memory")
#define CP_ASYNC_WAIT1()  asm volatile("cp.async.wait_group 1;" ::: "memory")

#define LDS64(r0, r1, addr) \
    asm volatile("ld.shared.v2.b32 {%0,%1}, [%2];" : "=r"(r0), "=r"(r1) : "r"((uint32_t)(addr)))

#define MMA_F16(d, a, b) \
    asm volatile("mma.sync.aligned.m16n8k16.row.col.f32.f16.f16.f32 " \
        "{%0,%1,%2,%3}, {%4,%5,%6,%7}, {%8,%9}, {%0,%1,%2,%3};" \
        : "+f"((d)[0]), "+f"((d)[1]), "+f"((d)[2]), "+f"((d)[3]) \
        : "r"((a)[0]), "r"((a)[1]), "r"((a)[2]), "r"((a)[3]), "r"((b)[0]), "r"((b)[1]))

__device__ __forceinline__ uint32_t pack_h2(__half a, __half b) {
    __half2 p = __halves2half2(a, b);
    return *(uint32_t*)&p;
}

// k-permutation within a 16-group (matches m16n8k16 frag layout):
// word w (fp16 pair): w even -> k = w ; w odd -> k = w + 7.
// inverse (even k): w = (k%16 < 8) ? (k%16) : (k%16 - 7)

// =====================================================================
// Prep 1: Wt fp32 -> permuted fp16.
// =====================================================================
__global__ __launch_bounds__(256) void k_cvt_wt(const float* __restrict__ Wt) {
    int idx = blockIdx.x * 256 + threadIdx.x;
    int o = idx >> 5, g = idx & 31;
    const float* src = Wt + (size_t)o * D_ + g * 16;
    float v[16];
#pragma unroll
    for (int q = 0; q < 4; q++) {
        float4 f = *(const float4*)(src + q * 4);
        v[q * 4 + 0] = f.x; v[q * 4 + 1] = f.y; v[q * 4 + 2] = f.z; v[q * 4 + 3] = f.w;
    }
    uint32_t hw_[8];
#pragma unroll
    for (int w = 0; w < 8; w++) {
        int k = (w & 1) ? (w + 7) : w;
        hw_[w] = pack_h2(__float2half_rn(v[k]), __float2half_rn(v[k + 1]));
    }
    uint32_t* dh = (uint32_t*)d_wt_h + (size_t)o * 256 + g * 8;
    *(uint4*)(dh + 0) = make_uint4(hw_[0], hw_[1], hw_[2], hw_[3]);
    *(uint4*)(dh + 4) = make_uint4(hw_[4], hw_[5], hw_[6], hw_[7]);
}

// =====================================================================
// Prep 2: feat_a [b][k][hw] fp32 -> d_ft_h [b][hw][kperm] fp16
// =====================================================================
#define FT_PAD 68
__global__ __launch_bounds__(256) void k_prep_feat(const float* __restrict__ feat_a) {
    extern __shared__ float sm[];    // [512][68]
    const int b = blockIdx.x;
    const int t = threadIdx.x;
    const float* src = feat_a + (size_t)b * D_ * HWA2;
#pragma unroll
    for (int r = 0; r < 32; r++) {
        int fi = r * 256 + t;
        int row = fi >> 4, c4 = fi & 15;
        float4 f = *(const float4*)(src + fi * 4);
        *(float4*)(sm + row * FT_PAD + c4 * 4) = f;
    }
    __syncthreads();
    const int hw = t >> 2, kseg = t & 3;
    uint32_t* dh = (uint32_t*)d_ft_h + ((size_t)b * HWA2 + hw) * 256;
#pragma unroll
    for (int g = 0; g < 8; g++) {
        int kbase = kseg * 128 + g * 16;
        uint32_t hw_[8];
#pragma unroll
        for (int w = 0; w < 8; w++) {
            int k = (w & 1) ? (w + 7) : w;
            hw_[w] = pack_h2(__float2half_rn(sm[(kbase + k) * FT_PAD + hw]),
                             __float2half_rn(sm[(kbase + k + 1) * FT_PAD + hw]));
        }
        int wbase = (kbase >> 1);
        *(uint4*)(dh + wbase + 0) = make_uint4(hw_[0], hw_[1], hw_[2], hw_[3]);
        *(uint4*)(dh + wbase + 4) = make_uint4(hw_[4], hw_[5], hw_[6], hw_[7]);
    }
}

// =====================================================================
// Prep 3: feat_v -> d_fv_h [b][i][hwperm] (pad 208)
// =====================================================================
__global__ __launch_bounds__(256) void k_prep_fv(const float* __restrict__ feat_v) {
    const int t = threadIdx.x;
    const int g = t & 15, rloc = t >> 4;
    const long row = (long)blockIdx.x * 16 + rloc;
    if (g >= 13) return;
    const float* src = feat_v + row * HWV2 + g * 16;
    float v[16];
#pragma unroll
    for (int q = 0; q < 16; q++) {
        int hw = g * 16 + q;
        v[q] = (hw < HWV2) ? src[q] : 0.f;
    }
    uint32_t wv[8];
#pragma unroll
    for (int w = 0; w < 8; w++) {
        int k = (w & 1) ? (w + 7) : w;
        wv[w] = pack_h2(__float2half_rn(v[k]), __float2half_rn(v[k + 1]));
    }
    uint32_t* dst = (uint32_t*)d_fv_h + row * (HWP / 2) + g * 8;
    *(uint4*)(dst + 0) = make_uint4(wv[0], wv[1], wv[2], wv[3]);
    *(uint4*)(dst + 4) = make_uint4(wv[4], wv[5], wv[6], wv[7]);
}

// Prep 4: cam -> d_cam_h
__global__ __launch_bounds__(256) void k_prep_cam(const float* __restrict__ cam) {
    const int t = threadIdx.x;
    const int g = t & 15, rloc = t >> 4;
    const long row = (long)blockIdx.x * 16 + rloc;
    if (g >= 13) return;
    const float* src = cam + row * HWV2 + g * 16;
    float v[16];
#pragma unroll
    for (int q = 0; q < 16; q++) {
        int hw = g * 16 + q;
        v[q] = (hw < HWV2) ? src[q] : 0.f;
    }
    uint32_t wv[8];
#pragma unroll
    for (int w = 0; w < 8; w++) {
        int k = (w & 1) ? (w + 7) : w;
        wv[w] = pack_h2(__float2half_rn(v[k]), __float2half_rn(v[k + 1]));
    }
    uint32_t* dst = (uint32_t*)d_cam_h + row * (HWP / 2) + g * 8;
    *(uint4*)(dst + 0) = make_uint4(wv[0], wv[1], wv[2], wv[3]);
    *(uint4*)(dst + 4) = make_uint4(wv[4], wv[5], wv[6], wv[7]);
}

// =====================================================================
// k_fa_mma: fa[b,o] = max_hw( feat[b,:,hw] . Wt[o,:] ) + bt[o]
// =====================================================================
#define FEAT_OFF  1024
#define FEAT_ROWB 1056
#define FEAT_SZ   (64 * FEAT_ROWB)
#define WT_OFF    (FEAT_OFF + FEAT_SZ)
#define WT_ROWB   288
#define WT_BUFSZ  (128 * WT_ROWB)
#define FA_SMEM   (WT_OFF + 2 * WT_BUFSZ)

__device__ __forceinline__ void fa_load_wt(uint32_t sb, int buf, int otp, int kc, int t) {
#pragma unroll
    for (int r = 0; r < 8; r++) {
        int idx = r * 256 + t;
        int row = idx >> 4, c = idx & 15;
        const __half* src = d_wt_h + ((size_t)(otp * 128 + row) * D_ + kc * 128 + c * 8);
        uint32_t dst = sb + WT_OFF + buf * WT_BUFSZ + row * WT_ROWB + c * 16;
        CP_ASYNC16(dst, src);
    }
}

__global__ void __launch_bounds__(256, 1) k_fa_mma(const float* __restrict__ bt) {
    extern __shared__ char smem[];
    float* red = (float*)smem;
    uint32_t sb = smem_to_u32(smem);
    const int b = blockIdx.x;
    const int t = threadIdx.x;
    const int w = t >> 5, lane = t & 31;
    const int ot2 = w >> 2, oy = (w >> 1) & 1, hx = w & 1;
    const int j = lane & 3, r4 = lane >> 2;

#pragma unroll
    for (int r = 0; r < 16; r++) {
        int idx = r * 256 + t;
        int row = idx >> 6, c = idx & 63;
        const __half* src = d_ft_h + ((size_t)(b * HWA2 + row) * D_ + c * 8);
        uint32_t dst = sb + FEAT_OFF + row * FEAT_ROWB + c * 16;
        CP_ASYNC16(dst, src);
    }
    fa_load_wt(sb, 0, 0, 0, t);
    CP_ASYNC_COMMIT();

    float acc[2][4][4];
#pragma unroll
    for (int mf = 0; mf < 2; mf++)
#pragma unroll
        for (int nf = 0; nf < 4; nf++)
#pragma unroll
            for (int q = 0; q < 4; q++) acc[mf][nf][q] = 0.f;

    const int oA = ot2 * 64 + oy * 32 + r4;
    const int hwB = hx * 32 + r4;

    for (int it = 0; it < 16; it++) {
        const int otp = it >> 2, kc = it & 3, buf = it & 1;
        if (it + 1 < 16) {
            fa_load_wt(sb, buf ^ 1, (it + 1) >> 2, (it + 1) & 3, t);
            CP_ASYNC_COMMIT();
            CP_ASYNC_WAIT1();
        } else {
            CP_ASYNC_WAIT0();
        }
        __syncthreads();

        const uint32_t wtb = sb + WT_OFF + buf * WT_BUFSZ;
#pragma unroll
        for (int kst = 0; kst < 8; kst++) {
            const int ks = kc * 8 + kst;
            uint32_t a[2][4];
#pragma unroll
            for (int mf = 0; mf < 2; mf++) {
                uint32_t base = wtb + (oA + mf * 16) * WT_ROWB + kst * 32 + j * 8;
                LDS64(a[mf][0], a[mf][2], base);
                LDS64(a[mf][1], a[mf][3], base + 8 * WT_ROWB);
            }
            uint32_t bh[4][2];
#pragma unroll
            for (int nf = 0; nf < 4; nf++) {
                uint32_t bb = sb + FEAT_OFF + (hwB + nf * 8) * FEAT_ROWB + ks * 32 + j * 8;
                LDS64(bh[nf][0], bh[nf][1], bb);
            }
#pragma unroll
            for (int mf = 0; mf < 2; mf++)
#pragma unroll
                for (int nf = 0; nf < 4; nf++)
                    MMA_F16(acc[mf][nf], a[mf], bh[nf]);
        }

        if (kc == 3) {
#pragma unroll
            for (int mf = 0; mf < 2; mf++) {
                float m0 = -3.4e38f, m1 = -3.4e38f;
#pragma unroll
                for (int nf = 0; nf < 4; nf++) {
                    m0 = fmaxf(m0, fmaxf(acc[mf][nf][0], acc[mf][nf][1]));
                    m1 = fmaxf(m1, fmaxf(acc[mf][nf][2], acc[mf][nf][3]));
                }
                m0 = fmaxf(m0, __shfl_xor_sync(0xffffffffu, m0, 1));
                m0 = fmaxf(m0, __shfl_xor_sync(0xffffffffu, m0, 2));
                m1 = fmaxf(m1, __shfl_xor_sync(0xffffffffu, m1, 1));
                m1 = fmaxf(m1, __shfl_xor_sync(0xffffffffu, m1, 2));
                if (j == 0) {
                    red[ot2 * 128 + hx * 64 + oy * 32 + mf * 16 + r4] = m0;
                    red[ot2 * 128 + hx * 64 + oy * 32 + mf * 16 + r4 + 8] = m1;
                }
            }
            __syncthreads();
            if (t < 128) {
                int o2 = t >> 6, ol = t & 63;
                float v = fmaxf(red[o2 * 128 + ol], red[o2 * 128 + 64 + ol]);
                int og = otp * 128 + o2 * 64 + ol;
                d_fa[(size_t)b * D_ + og] = v + bt[og];
            }
#pragma unroll
            for (int mf = 0; mf < 2; mf++)
#pragma unroll
                for (int nf = 0; nf < 4; nf++)
#pragma unroll
                    for (int q = 0; q < 4; q++) acc[mf][nf][q] = 0.f;
        }
        __syncthreads();
    }
}

// =====================================================================
// k_g_mma: g[b,c,i] = sum_hw cam*feat_v -> writes fp16 k-permuted d_g_h
// =====================================================================
#define GC_OFF   1024
#define G_ROWB   416
#define GC_SZ    (32 * G_ROWB)
#define GF_OFF   (GC_OFF + GC_SZ)
#define GF_BUFSZ (128 * G_ROWB)
#define KG_SMEM  (GF_OFF + 2 * GF_BUFSZ)

__device__ __forceinline__ void g_load_fv(uint32_t sb, int buf, int b, int ic, int t) {
#pragma unroll
    for (int r = 0; r < 13; r++) {
        int idx = r * 256 + t;
        int row = idx / 26, c = idx % 26;
        const __half* src = d_fv_h + ((size_t)(b * D_) + ic * 128 + row) * HWP + c * 8;
        uint32_t dst = sb + GF_OFF + buf * GF_BUFSZ + row * G_ROWB + c * 16;
        CP_ASYNC16(dst, src);
    }
}

__global__ void __launch_bounds__(256, 1) k_g_mma() {
    extern __shared__ char smem[];
    uint32_t sb = smem_to_u32(smem);
    const int b = blockIdx.x;
    const int t = threadIdx.x;
    const int w = t >> 5, lane = t & 31;
    const int my = w & 1, ix = w >> 1;
    const int j = lane & 3, r4 = lane >> 2;

#pragma unroll
    for (int r = 0; r < 4; r++) {
        int idx = r * 256 + t;
        if (idx < 832) {
            int row = idx / 26, c = idx % 26;
            const __half* src = d_cam_h + ((size_t)(b * CLS_) + row) * HWP + c * 8;
            CP_ASYNC16(sb + GC_OFF + row * G_ROWB + c * 16, src);
        }
    }
    g_load_fv(sb, 0, b, 0, t);
    CP_ASYNC_COMMIT();

    for (int ic = 0; ic < 4; ic++) {
        const int buf = ic & 1;
        if (ic + 1 < 4) {
            g_load_fv(sb, buf ^ 1, b, ic + 1, t);
            CP_ASYNC_COMMIT();
            CP_ASYNC_WAIT1();
        } else {
            CP_ASYNC_WAIT0();
        }
        __syncthreads();

        float acc[4][4];
#pragma unroll
        for (int nf = 0; nf < 4; nf++)
#pragma unroll
            for (int q = 0; q < 4; q++) acc[nf][q] = 0.f;

        const uint32_t fvb = sb + GF_OFF + buf * GF_BUFSZ;
#pragma unroll
        for (int kst = 0; kst < 13; kst++) {
            uint32_t a[4];
            uint32_t abase = sb + GC_OFF + (my * 16 + r4) * G_ROWB + kst * 32 + j * 8;
            LDS64(a[0], a[2], abase);
            LDS64(a[1], a[3], abase + 8 * G_ROWB);
            uint32_t bh[4][2];
#pragma unroll
            for (int nf = 0; nf < 4; nf++) {
                uint32_t bb = fvb + (ix * 32 + nf * 8 + r4) * G_ROWB + kst * 32 + j * 8;
                LDS64(bh[nf][0], bh[nf][1], bb);
            }
#pragma unroll
            for (int nf = 0; nf < 4; nf++)
                MMA_F16(acc[nf], a, bh[nf]);
        }

        // store fp16 k-permuted g slice: m = b*32 + c, k = i
        const int c0 = my * 16 + r4;
#pragma unroll
        for (int nf = 0; nf < 4; nf++) {
            int ig = ic * 128 + ix * 32 + nf * 8 + 2 * j;      // even pair base
            int gg = ig >> 4, rm = ig & 15;
            int wd = (rm < 8) ? rm : (rm - 7);
            int word = gg * 8 + wd;
            uint32_t* g0 = (uint32_t*)d_g_h + ((size_t)b * CLS_ + c0) * 256 + word;
            *g0 = pack_h2(__float2half_rn(acc[nf][0]), __float2half_rn(acc[nf][1]));
            uint32_t* g1 = (uint32_t*)d_g_h + ((size_t)b * CLS_ + c0 + 8) * 256 + word;
            *g1 = pack_h2(__float2half_rn(acc[nf][2]), __float2half_rn(acc[nf][3]));
        }
        __syncthreads();
    }
}

// =====================================================================
// camsum (blocks 0..255) + wbs (blocks 256..383)
// =====================================================================
__global__ void k_small(const float* __restrict__ cam, const float* __restrict__ Wv,
                        const float* __restrict__ bs) {
    if (blockIdx.x < 256) {
        int b = blockIdx.x;
        int w = threadIdx.x >> 5, lane = threadIdx.x & 31;
        for (int c = w; c < CLS_; c += 8) {
            const float* p = cam + ((size_t)b * CLS_ + c) * HWV2;
            float s = 0.f;
            for (int k = lane; k < HWV2; k += 32) s += p[k];
#pragma unroll
            for (int off = 16; off; off >>= 1) s += __shfl_xor_sync(0xffffffffu, s, off);
            if (!lane) d_camsum[b * CLS_ + c] = s;
        }
    } else {
        int o = blockIdx.x - 256;
        if (threadIdx.x < 32) {
            int lane = threadIdx.x;
            float s = 0.f;
            for (int d = lane; d < D_; d += 32) s = fmaf(Wv[(size_t)o * D_ + d], bs[d], s);
#pragma unroll
            for (int off = 16; off; off >>= 1) s += __shfl_xor_sync(0xffffffffu, s, off);
            if (!lane) d_wbs[o] = s;
        }
    }
}

// =====================================================================
// Wvs[o,i] = sum_d Wv[o,d]*Ws[d,i]  (fp32 out + fp16 permuted out)
// =====================================================================
__global__ __launch_bounds__(256) void k_wvs(const float* __restrict__ Wv,
                                             const float* __restrict__ Ws) {
    __shared__ float sV[32][65];
    __shared__ float sS[64][65];
    const int oT = blockIdx.x, iT = blockIdx.y;
    const int t = threadIdx.x;
    const int tx = t & 31, ty = t >> 5;

    float acc[4][2];
#pragma unroll
    for (int a = 0; a < 4; a++) { acc[a][0] = 0.f; acc[a][1] = 0.f; }

    for (int k0 = 0; k0 < D_; k0 += 64) {
#pragma unroll
        for (int r = 0; r < 8; r++) {
            int idx = r * 256 + t;
            int o = idx >> 6, kk = idx & 63;
            sV[o][kk] = Wv[(size_t)(oT * 32 + o) * D_ + k0 + kk];
        }
#pragma unroll
        for (int r = 0; r < 16; r++) {
            int idx = r * 256 + t;
            int kk = idx >> 6, i = idx & 63;
            sS[kk][i] = Ws[(size_t)(k0 + kk) * D_ + iT * 64 + i];
        }
        __syncthreads();
#pragma unroll
        for (int kk = 0; kk < 64; kk++) {
            float bb0 = sS[kk][tx], bb1 = sS[kk][tx + 32];
#pragma unroll
            for (int a = 0; a < 4; a++) {
                float av = sV[ty * 4 + a][kk];
                acc[a][0] = fmaf(av, bb0, acc[a][0]);
                acc[a][1] = fmaf(av, bb1, acc[a][1]);
            }
        }
        __syncthreads();
    }
#pragma unroll
    for (int a = 0; a < 4; a++) {
        int o = oT * 32 + ty * 4 + a;
#pragma unroll
        for (int half_ = 0; half_ < 2; half_++) {
            int i = iT * 64 + tx + 32 * half_;
            float v = acc[a][half_];
            d_Wvs[(size_t)o * D_ + i] = v;
            // fp16 permuted write
            int gg = i >> 4;
            int ke = (i & ~1) & 15;
            int wd = (ke < 8) ? ke : (ke - 7);
            d_wvs_h[(size_t)o * D_ + gg * 16 + wd * 2 + (i & 1)] = __float2half_rn(v);
        }
    }
}

// =====================================================================
// k_tv_mma: tv[m,o] = (g[m,:].Wvs[o,:] + wbs[o]*cs[m]) / (cs[m]+1e-10) + bv[o]
// fp16 MMA: A = d_g_h (M=8192), B = d_wvs_h resident. grid 64, 256 thr.
// =====================================================================
#define TV_B_OFF   0
#define TV_B_ROWB  1056
#define TV_A_OFF   (128 * TV_B_ROWB)          // 135168
#define TV_A_ROWB  288
#define TV_A_BUFSZ (128 * TV_A_ROWB)          // 36864
#define TV_SMEM    (TV_A_OFF + 2 * TV_A_BUFSZ)  // 208896

__device__ __forceinline__ void tv_load_a(uint32_t sb, int buf, int m0, int kc, int t) {
#pragma unroll
    for (int r = 0; r < 8; r++) {
        int idx = r * 256 + t;
        int row = idx >> 4, c = idx & 15;
        const __half* src = d_g_h + ((size_t)(m0 + row) * D_ + kc * 128 + c * 8);
        uint32_t dst = sb + TV_A_OFF + buf * TV_A_BUFSZ + row * TV_A_ROWB + c * 16;
        CP_ASYNC16(dst, src);
    }
}

__global__ void __launch_bounds__(256, 1) k_tv_mma(const float* __restrict__ bv) {
    extern __shared__ char smem[];
    uint32_t sb = smem_to_u32(smem);
    const int m0 = blockIdx.x * 128;
    const int t = threadIdx.x;
    const int w = t >> 5, lane = t & 31;
    const int mgrp = w & 3, ogrp = w >> 2;
    const int j = lane & 3, r4 = lane >> 2;

    // load B (Wvs fp16, 128 rows x 1024 B) resident
#pragma unroll
    for (int r = 0; r < 32; r++) {
        int idx = r * 256 + t;
        int row = idx >> 6, c = idx & 63;
        const __half* src = d_wvs_h + ((size_t)row * D_ + c * 8);
        CP_ASYNC16(sb + TV_B_OFF + row * TV_B_ROWB + c * 16, src);
    }
    tv_load_a(sb, 0, m0, 0, t);
    CP_ASYNC_COMMIT();

    float acc[2][8][4];
#pragma unroll
    for (int mf = 0; mf < 2; mf++)
#pragma unroll
        for (int nf = 0; nf < 8; nf++)
#pragma unroll
            for (int q = 0; q < 4; q++) acc[mf][nf][q] = 0.f;

    for (int kc = 0; kc < 4; kc++) {
        const int buf = kc & 1;
        if (kc + 1 < 4) {
            tv_load_a(sb, buf ^ 1, m0, kc + 1, t);
            CP_ASYNC_COMMIT();
            CP_ASYNC_WAIT1();
        } else {
            CP_ASYNC_WAIT0();
        }
        __syncthreads();

#pragma unroll
        for (int kst = 0; kst < 8; kst++) {
            const int ks = kc * 8 + kst;
            uint32_t a[2][4];
#pragma unroll
            for (int mf = 0; mf < 2; mf++) {
                uint32_t base = sb + TV_A_OFF + buf * TV_A_BUFSZ
                              + (mgrp * 32 + mf * 16 + r4) * TV_A_ROWB + kst * 32 + j * 8;
                LDS64(a[mf][0], a[mf][2], base);
                LDS64(a[mf][1], a[mf][3], base + 8 * TV_A_ROWB);
            }
            uint32_t bh[8][2];
#pragma unroll
            for (int nf = 0; nf < 8; nf++) {
                uint32_t bb = sb + TV_B_OFF + (ogrp * 64 + nf * 8 + r4) * TV_B_ROWB
                            + ks * 32 + j * 8;
                LDS64(bh[nf][0], bh[nf][1], bb);
            }
#pragma unroll
            for (int mf = 0; mf < 2; mf++)
#pragma unroll
                for (int nf = 0; nf < 8; nf++)
                    MMA_F16(acc[mf][nf], a[mf], bh[nf]);
        }
        __syncthreads();
    }

    // epilogue
#pragma unroll
    for (int mf = 0; mf < 2; mf++) {
        int mr0 = m0 + mgrp * 32 + mf * 16 + r4;
        int mr1 = mr0 + 8;
        float cs0 = d_camsum[mr0], cs1 = d_camsum[mr1];
        float inv0 = 1.f / (cs0 + 1e-10f), inv1 = 1.f / (cs1 + 1e-10f);
#pragma unroll
        for (int nf = 0; nf < 8; nf++) {
            int o0 = ogrp * 64 + nf * 8 + 2 * j;
            float wb0 = d_wbs[o0], wb1 = d_wbs[o0 + 1];
            float bv0 = bv[o0], bv1 = bv[o0 + 1];
            d_tv[(size_t)mr0 * DOUT + o0]     = (acc[mf][nf][0] + wb0 * cs0) * inv0 + bv0;
            d_tv[(size_t)mr0 * DOUT + o0 + 1] = (acc[mf][nf][1] + wb1 * cs0) * inv0 + bv1;
            d_tv[(size_t)mr1 * DOUT + o0]     = (acc[mf][nf][2] + wb0 * cs1) * inv1 + bv0;
            d_tv[(size_t)mr1 * DOUT + o0 + 1] = (acc[mf][nf][3] + wb1 * cs1) * inv1 + bv1;
        }
    }
}

// =====================================================================
// k_ta: ta[m,o] = fa[m,:].Wa[o,:] + ba[o]   (fp32, M=1024 small)
// =====================================================================
__global__ __launch_bounds__(256) void k_ta(const float* __restrict__ Wa,
                                            const float* __restrict__ ba) {
    __shared__ float sA[128][33];
    __shared__ float sB[128][33];

    const int m0 = blockIdx.x * 128;
    const int t  = threadIdx.x;
    const int tx = t & 15, ty = t >> 4;

    float acc[8][8];
#pragma unroll
    for (int i = 0; i < 8; i++)
#pragma unroll
        for (int jq = 0; jq < 8; jq++) acc[i][jq] = 0.f;

    for (int k0 = 0; k0 < D_; k0 += 32) {
#pragma unroll
        for (int r = 0; r < 16; r++) {
            int idx = r * 256 + t;
            int mm = idx >> 5, kk = idx & 31;
            sA[mm][kk] = d_fa[(size_t)(m0 + mm) * D_ + k0 + kk];
            sB[mm][kk] = Wa[(size_t)mm * D_ + k0 + kk];
        }
        __syncthreads();
#pragma unroll
        for (int kk = 0; kk < 32; kk++) {
            float a[8], b[8];
#pragma unroll
            for (int mi = 0; mi < 8; mi++) a[mi] = sA[ty + 16 * mi][kk];
#pragma unroll
            for (int oj = 0; oj < 8; oj++) b[oj] = sB[tx + 16 * oj][kk];
#pragma unroll
            for (int mi = 0; mi < 8; mi++)
#pragma unroll
                for (int oj = 0; oj < 8; oj++)
                    acc[mi][oj] = fmaf(a[mi], b[oj], acc[mi][oj]);
        }
        __syncthreads();
    }
#pragma unroll
    for (int mi = 0; mi < 8; mi++) {
        int m = m0 + ty + 16 * mi;
#pragma unroll
        for (int oj = 0; oj < 8; oj++) {
            int o = tx + 16 * oj;
            d_ta[(size_t)m * DOUT + o] = acc[mi][oj] + ba[o];
        }
    }
}

// =====================================================================
// losses
// =====================================================================
__global__ void k_loss(const float* __restrict__ pred_a, const float* __restrict__ pred_v,
                       const int* __restrict__ rand_frames, const int* __restrict__ rand_classes,
                       float* __restrict__ out) {
    const int s = blockIdx.x, c = blockIdx.y;
    const int f = threadIdx.x >> 5, lane = threadIdx.x & 31;

    const float pa = pred_a[s * CLS_ + c];
    const bool aa = pa > 0.3f;
    const int num = (int)(pa * (float)FRM);

    const float* tap = d_ta + (size_t)(s * CLS_ + c) * DOUT;
    const float* tvp = d_tv + (size_t)((s * FRM + f) * CLS_ + c) * DOUT;
    const int rf = rand_frames[(s * CLS_ + c) * FRM + f];
    const int rc = rand_classes[(s * CLS_ + c) * FRM + f];
    const float* tvd = d_tv + (size_t)(((s ^ 1) * FRM + rf) * CLS_ + rc) * DOUT;

    float sco = 0.f, sdi = 0.f;
#pragma unroll
    for (int jq = 0; jq < 4; jq++) {
        int o = lane + 32 * jq;
        float t0 = tap[o];
        float d0 = t0 - tvp[o]; sco = fmaf(d0, d0, sco);
        float d1 = t0 - tvd[o]; sdi = fmaf(d1, d1, sdi);
    }
#pragma unroll
    for (int off = 16; off; off >>= 1) {
        sco += __shfl_xor_sync(0xffffffffu, sco, off);
        sdi += __shfl_xor_sync(0xffffffffu, sdi, off);
    }
    if (!lane) {
        float pv = 1.f / (1.f + expf(-pred_v[(s * FRM + f) * CLS_ + c]));
        bool av = pv > 0.3f;
        float mco = (aa && av) ? 1.f : 0.f;
        float mdi = (aa && (f < num)) ? 1.f : 0.f;
        out[((0 * S_ + s) * CLS_ + c) * FRM + f] = sco * (1.f / 128.f) * mco;
        out[((1 * S_ + s) * CLS_ + c) * FRM + f] = sdi * (1.f / 128.f) * mdi;
    }
}

// =====================================================================
extern "C" void kernel_launch(void* const* d_in, const int* in_sizes, int n_in,
                              void* d_out, int out_size) {
    const float* feat_a = (const float*)d_in[0];
    const float* pred_a = (const float*)d_in[1];
    const float* feat_v = (const float*)d_in[2];
    const float* pred_v = (const float*)d_in[3];
    const float* cam    = (const float*)d_in[4];
    const int* rand_frames  = (const int*)d_in[5];
    const int* rand_classes = (const int*)d_in[6];
    const float* Wt = (const float*)d_in[7];
    const float* bt = (const float*)d_in[8];
    const float* Ws = (const float*)d_in[9];
    const float* bs = (const float*)d_in[10];
    const float* Wa = (const float*)d_in[11];
    const float* ba = (const float*)d_in[12];
    const float* Wv = (const float*)d_in[13];
    const float* bv = (const float*)d_in[14];
    float* out = (float*)d_out;

    static bool attr_set = false;
    if (!attr_set) {
        cudaFuncSetAttribute(k_fa_mma, cudaFuncAttributeMaxDynamicSharedMemorySize, FA_SMEM);
        cudaFuncSetAttribute(k_g_mma, cudaFuncAttributeMaxDynamicSharedMemorySize, KG_SMEM);
        cudaFuncSetAttribute(k_tv_mma, cudaFuncAttributeMaxDynamicSharedMemorySize, TV_SMEM);
        cudaFuncSetAttribute(k_prep_feat, cudaFuncAttributeMaxDynamicSharedMemorySize,
                             D_ * FT_PAD * 4);
        attr_set = true;
    }

    // launch order chosen so k_fa_mma is the 4th launch (ncu profiles #4)
    k_cvt_wt<<<64, 256>>>(Wt);                                // 1
    k_prep_feat<<<BA, 256, D_ * FT_PAD * 4>>>(feat_a);        // 2
    k_prep_fv<<<(BV * D_) / 16, 256>>>(feat_v);               // 3
    k_fa_mma<<<BA, 256, FA_SMEM>>>(bt);                       // 4  <- profiled
    k_prep_cam<<<(BV * CLS_) / 16, 256>>>(cam);               // 5
    k_g_mma<<<BV, 256, KG_SMEM>>>();                          // 6
    k_small<<<384, 256>>>(cam, Wv, bs);                       // 7
    k_wvs<<<dim3(4, 8), 256>>>(Wv, Ws);                       // 8
    k_ta<<<BA / 128, 256>>>(Wa, ba);                          // 9
    k_tv_mma<<<(BV * CLS_) / 128, 256, TV_SMEM>>>(bv);        // 10
    k_loss<<<dim3(S_, CLS_), 256>>>(pred_a, pred_v, rand_frames, rand_classes, out); // 11
}

// round 7
// speedup vs baseline: 3.0066x; 1.0821x over previous
#include <cuda_runtime.h>
#include <cuda_fp16.h>
#include <math.h>
#include <cstdint>

// Problem constants
#define S_   32
#define FRM  8
#define CLS_ 32
#define D_   512
#define HWA2 64      // 8*8
#define HWV2 196     // 14*14
#define HWP  208     // padded to 13*16
#define DOUT 128
#define BA   (S_*CLS_)   // 1024
#define BV   (S_*FRM)    // 256

// ---------------- device scratch ----------------
__device__ float d_fa[BA * D_];
__device__ float d_ta[BA * DOUT];
__device__ float d_camsum[BV * CLS_];
__device__ float d_tv[BV * CLS_ * DOUT];
__device__ float d_Wvs[DOUT * D_];
__device__ float d_wbs[DOUT];
// fp16 permuted buffers
__device__ __half d_wt_h[D_ * D_];                      // [o][kperm]
__device__ __half d_ft_h[(size_t)BA * HWA2 * D_];       // [b][hw][kperm]
__device__ __half d_fv_h[(size_t)BV * D_ * HWP];        // [b][i][hwperm]
__device__ __half d_cam_h[(size_t)BV * CLS_ * HWP];     // [b][c][hwperm]
__device__ __half d_g_h[(size_t)BV * CLS_ * D_];        // [m][kperm]
__device__ __half d_wvs_h[DOUT * D_];                   // [o][kperm]

// =============== small asm helpers ===============
__device__ __forceinline__ uint32_t smem_to_u32(const void* p) {
    uint32_t a;
    asm("{ .reg .u64 t; cvta.to.shared.u64 t, %1; cvt.u32.u64 %0, t; }" : "=r"(a) : "l"(p));
    return a;
}
#define CP_ASYNC16(sm, g) \
    asm volatile("cp.async.cg.shared.global [%0], [%1], 16;" :: "r"((uint32_t)(sm)), "l"(g) : "memory")
#define CP_ASYNC_COMMIT() asm volatile("cp.async.commit_group;" ::: "memory")
#define CP_ASYNC_WAIT0()  asm volatile("cp.async.wait_group 0;" ::: "memory")
#define CP_ASYNC_WAIT1()  asm volatile("cp.async.wait_group 1;" ::: "memory")

#define LDS64(r0, r1, addr) \
    asm volatile("ld.shared.v2.b32 {%0,%1}, [%2];" : "=r"(r0), "=r"(r1) : "r"((uint32_t)(addr)))

#define MMA_F16(d, a, b) \
    asm volatile("mma.sync.aligned.m16n8k16.row.col.f32.f16.f16.f32 " \
        "{%0,%1,%2,%3}, {%4,%5,%6,%7}, {%8,%9}, {%0,%1,%2,%3};" \
        : "+f"((d)[0]), "+f"((d)[1]), "+f"((d)[2]), "+f"((d)[3]) \
        : "r"((a)[0]), "r"((a)[1]), "r"((a)[2]), "r"((a)[3]), "r"((b)[0]), "r"((b)[1]))

__device__ __forceinline__ uint32_t pack_h2(__half a, __half b) {
    __half2 p = __halves2half2(a, b);
    return *(uint32_t*)&p;
}

// k-permutation within a 16-group (m16n8k16 frag layout):
// word w (fp16 pair): w even -> k = w ; w odd -> k = w + 7.

// =====================================================================
// Prep 1: Wt fp32 -> permuted fp16.
// =====================================================================
__global__ __launch_bounds__(256) void k_cvt_wt(const float* __restrict__ Wt) {
    int idx = blockIdx.x * 256 + threadIdx.x;
    int o = idx >> 5, g = idx & 31;
    const float* src = Wt + (size_t)o * D_ + g * 16;
    float v[16];
#pragma unroll
    for (int q = 0; q < 4; q++) {
        float4 f = *(const float4*)(src + q * 4);
        v[q * 4 + 0] = f.x; v[q * 4 + 1] = f.y; v[q * 4 + 2] = f.z; v[q * 4 + 3] = f.w;
    }
    uint32_t hw_[8];
#pragma unroll
    for (int w = 0; w < 8; w++) {
        int k = (w & 1) ? (w + 7) : w;
        hw_[w] = pack_h2(__float2half_rn(v[k]), __float2half_rn(v[k + 1]));
    }
    uint32_t* dh = (uint32_t*)d_wt_h + (size_t)o * 256 + g * 8;
    *(uint4*)(dh + 0) = make_uint4(hw_[0], hw_[1], hw_[2], hw_[3]);
    *(uint4*)(dh + 4) = make_uint4(hw_[4], hw_[5], hw_[6], hw_[7]);
}

// =====================================================================
// Prep 2 (tiled): feat_a [b][k][hw] fp32 -> d_ft_h [b][hw][kperm] fp16
// grid (1024, 4): b, k-chunk of 128.  34.8 KB static smem -> high occ.
// =====================================================================
__global__ __launch_bounds__(256) void k_prep_feat(const float* __restrict__ feat_a) {
    __shared__ float sm[128][68];
    const int b = blockIdx.x, kc = blockIdx.y;
    const int t = threadIdx.x;
    const float* src = feat_a + ((size_t)b * D_ + kc * 128) * HWA2;
#pragma unroll
    for (int r = 0; r < 8; r++) {
        int fi = r * 256 + t;            // 2048 float4
        int row = fi >> 4, c4 = fi & 15;
        float4 f = *(const float4*)(src + fi * 4);
        *(float4*)(&sm[row][c4 * 4]) = f;
    }
    __syncthreads();
    // warp = 32 consecutive hw (conflict-free smem reads); kseg = t>>6
    const int hw = t & 63, kseg = t >> 6;     // kseg covers 32 local k
    uint32_t* dh = (uint32_t*)d_ft_h + ((size_t)b * HWA2 + hw) * 256 + kc * 64;
#pragma unroll
    for (int g = 0; g < 2; g++) {
        int kbase = kseg * 32 + g * 16;       // local k group base
        uint32_t hw_[8];
#pragma unroll
        for (int w = 0; w < 8; w++) {
            int k = (w & 1) ? (w + 7) : w;
            hw_[w] = pack_h2(__float2half_rn(sm[kbase + k][hw]),
                             __float2half_rn(sm[kbase + k + 1][hw]));
        }
        uint32_t* dst = dh + (kseg * 2 + g) * 8;
        *(uint4*)(dst + 0) = make_uint4(hw_[0], hw_[1], hw_[2], hw_[3]);
        *(uint4*)(dst + 4) = make_uint4(hw_[4], hw_[5], hw_[6], hw_[7]);
    }
}

// =====================================================================
// Prep 3: feat_v -> d_fv_h [b][i][hwperm] (pad 208)
// =====================================================================
__global__ __launch_bounds__(256) void k_prep_fv(const float* __restrict__ feat_v) {
    const int t = threadIdx.x;
    const int g = t & 15, rloc = t >> 4;
    const long row = (long)blockIdx.x * 16 + rloc;
    if (g >= 13) return;
    const float* src = feat_v + row * HWV2 + g * 16;
    float v[16];
#pragma unroll
    for (int q = 0; q < 16; q++) {
        int hw = g * 16 + q;
        v[q] = (hw < HWV2) ? src[q] : 0.f;
    }
    uint32_t wv[8];
#pragma unroll
    for (int w = 0; w < 8; w++) {
        int k = (w & 1) ? (w + 7) : w;
        wv[w] = pack_h2(__float2half_rn(v[k]), __float2half_rn(v[k + 1]));
    }
    uint32_t* dst = (uint32_t*)d_fv_h + row * (HWP / 2) + g * 8;
    *(uint4*)(dst + 0) = make_uint4(wv[0], wv[1], wv[2], wv[3]);
    *(uint4*)(dst + 4) = make_uint4(wv[4], wv[5], wv[6], wv[7]);
}

// Prep 4: cam -> d_cam_h
__global__ __launch_bounds__(256) void k_prep_cam(const float* __restrict__ cam) {
    const int t = threadIdx.x;
    const int g = t & 15, rloc = t >> 4;
    const long row = (long)blockIdx.x * 16 + rloc;
    if (g >= 13) return;
    const float* src = cam + row * HWV2 + g * 16;
    float v[16];
#pragma unroll
    for (int q = 0; q < 16; q++) {
        int hw = g * 16 + q;
        v[q] = (hw < HWV2) ? src[q] : 0.f;
    }
    uint32_t wv[8];
#pragma unroll
    for (int w = 0; w < 8; w++) {
        int k = (w & 1) ? (w + 7) : w;
        wv[w] = pack_h2(__float2half_rn(v[k]), __float2half_rn(v[k + 1]));
    }
    uint32_t* dst = (uint32_t*)d_cam_h + row * (HWP / 2) + g * 8;
    *(uint4*)(dst + 0) = make_uint4(wv[0], wv[1], wv[2], wv[3]);
    *(uint4*)(dst + 4) = make_uint4(wv[4], wv[5], wv[6], wv[7]);
}

// =====================================================================
// k_fa_mma: fa[b,o] = max_hw( feat[b,:,hw] . Wt[o,:] ) + bt[o]
// 2 CTAs/SM: feat resident (66 KB), Wt streamed in 128o x 64k chunks.
// =====================================================================
#define FEAT_OFF  1024
#define FEAT_ROWB 1056                  // 1024 B data + 32 pad (≡32 mod 128)
#define FEAT_SZ   (64 * FEAT_ROWB)      // 67584
#define WT_OFF    (FEAT_OFF + FEAT_SZ)  // 68608
#define WT_ROWB   160                   // 128 B data + 32 pad
#define WT_BUFSZ  (128 * WT_ROWB)       // 20480
#define FA_SMEM   (WT_OFF + 2 * WT_BUFSZ)   // 109568

__device__ __forceinline__ void fa_load_wt(uint32_t sb, int buf, int otp, int kc, int t) {
#pragma unroll
    for (int r = 0; r < 4; r++) {
        int idx = r * 256 + t;          // 1024 x 16B
        int row = idx >> 3, c = idx & 7;
        const __half* src = d_wt_h + ((size_t)(otp * 128 + row) * D_ + kc * 64 + c * 8);
        uint32_t dst = sb + WT_OFF + buf * WT_BUFSZ + row * WT_ROWB + c * 16;
        CP_ASYNC16(dst, src);
    }
}

__global__ void __launch_bounds__(256, 2) k_fa_mma(const float* __restrict__ bt) {
    extern __shared__ char smem[];
    float* red = (float*)smem;
    uint32_t sb = smem_to_u32(smem);
    const int b = blockIdx.x;
    const int t = threadIdx.x;
    const int w = t >> 5, lane = t & 31;
    const int ot2 = w >> 2, oy = (w >> 1) & 1, hx = w & 1;
    const int j = lane & 3, r4 = lane >> 2;

    // prologue: feat[b] fp16 resident + Wt chunk 0
#pragma unroll
    for (int r = 0; r < 16; r++) {
        int idx = r * 256 + t;          // 4096 x 16B
        int row = idx >> 6, c = idx & 63;
        const __half* src = d_ft_h + ((size_t)(b * HWA2 + row) * D_ + c * 8);
        uint32_t dst = sb + FEAT_OFF + row * FEAT_ROWB + c * 16;
        CP_ASYNC16(dst, src);
    }
    fa_load_wt(sb, 0, 0, 0, t);
    CP_ASYNC_COMMIT();

    float acc[2][4][4];
#pragma unroll
    for (int mf = 0; mf < 2; mf++)
#pragma unroll
        for (int nf = 0; nf < 4; nf++)
#pragma unroll
            for (int q = 0; q < 4; q++) acc[mf][nf][q] = 0.f;

    const int oA = ot2 * 64 + oy * 32 + r4;
    const int hwB = hx * 32 + r4;

    for (int it = 0; it < 32; it++) {
        const int otp = it >> 3, kc = it & 7, buf = it & 1;
        if (it + 1 < 32) {
            fa_load_wt(sb, buf ^ 1, (it + 1) >> 3, (it + 1) & 7, t);
            CP_ASYNC_COMMIT();
            CP_ASYNC_WAIT1();
        } else {
            CP_ASYNC_WAIT0();
        }
        __syncthreads();

        const uint32_t wtb = sb + WT_OFF + buf * WT_BUFSZ;
#pragma unroll
        for (int kst = 0; kst < 4; kst++) {
            const int ks = kc * 4 + kst;
            uint32_t a[2][4];
#pragma unroll
            for (int mf = 0; mf < 2; mf++) {
                uint32_t base = wtb + (oA + mf * 16) * WT_ROWB + kst * 32 + j * 8;
                LDS64(a[mf][0], a[mf][2], base);
                LDS64(a[mf][1], a[mf][3], base + 8 * WT_ROWB);
            }
            uint32_t bh[4][2];
#pragma unroll
            for (int nf = 0; nf < 4; nf++) {
                uint32_t bb = sb + FEAT_OFF + (hwB + nf * 8) * FEAT_ROWB + ks * 32 + j * 8;
                LDS64(bh[nf][0], bh[nf][1], bb);
            }
#pragma unroll
            for (int mf = 0; mf < 2; mf++)
#pragma unroll
                for (int nf = 0; nf < 4; nf++)
                    MMA_F16(acc[mf][nf], a[mf], bh[nf]);
        }

        if (kc == 7) {
#pragma unroll
            for (int mf = 0; mf < 2; mf++) {
                float m0 = -3.4e38f, m1 = -3.4e38f;
#pragma unroll
                for (int nf = 0; nf < 4; nf++) {
                    m0 = fmaxf(m0, fmaxf(acc[mf][nf][0], acc[mf][nf][1]));
                    m1 = fmaxf(m1, fmaxf(acc[mf][nf][2], acc[mf][nf][3]));
                }
                m0 = fmaxf(m0, __shfl_xor_sync(0xffffffffu, m0, 1));
                m0 = fmaxf(m0, __shfl_xor_sync(0xffffffffu, m0, 2));
                m1 = fmaxf(m1, __shfl_xor_sync(0xffffffffu, m1, 1));
                m1 = fmaxf(m1, __shfl_xor_sync(0xffffffffu, m1, 2));
                if (j == 0) {
                    red[ot2 * 128 + hx * 64 + oy * 32 + mf * 16 + r4] = m0;
                    red[ot2 * 128 + hx * 64 + oy * 32 + mf * 16 + r4 + 8] = m1;
                }
            }
            __syncthreads();
            if (t < 128) {
                int o2 = t >> 6, ol = t & 63;
                float v = fmaxf(red[o2 * 128 + ol], red[o2 * 128 + 64 + ol]);
                int og = otp * 128 + o2 * 64 + ol;
                d_fa[(size_t)b * D_ + og] = v + bt[og];
            }
#pragma unroll
            for (int mf = 0; mf < 2; mf++)
#pragma unroll
                for (int nf = 0; nf < 4; nf++)
#pragma unroll
                    for (int q = 0; q < 4; q++) acc[mf][nf][q] = 0.f;
        }
        __syncthreads();
    }
}

// =====================================================================
// k_g_mma: g[b,c,i] = sum_hw cam*feat_v -> fp16 k-permuted d_g_h
// =====================================================================
#define GC_OFF   1024
#define G_ROWB   416
#define GC_SZ    (32 * G_ROWB)
#define GF_OFF   (GC_OFF + GC_SZ)
#define GF_BUFSZ (128 * G_ROWB)
#define KG_SMEM  (GF_OFF + 2 * GF_BUFSZ)

__device__ __forceinline__ void g_load_fv(uint32_t sb, int buf, int b, int ic, int t) {
#pragma unroll
    for (int r = 0; r < 13; r++) {
        int idx = r * 256 + t;
        int row = idx / 26, c = idx % 26;
        const __half* src = d_fv_h + ((size_t)(b * D_) + ic * 128 + row) * HWP + c * 8;
        uint32_t dst = sb + GF_OFF + buf * GF_BUFSZ + row * G_ROWB + c * 16;
        CP_ASYNC16(dst, src);
    }
}

__global__ void __launch_bounds__(256, 1) k_g_mma() {
    extern __shared__ char smem[];
    uint32_t sb = smem_to_u32(smem);
    const int b = blockIdx.x;
    const int t = threadIdx.x;
    const int w = t >> 5, lane = t & 31;
    const int my = w & 1, ix = w >> 1;
    const int j = lane & 3, r4 = lane >> 2;

#pragma unroll
    for (int r = 0; r < 4; r++) {
        int idx = r * 256 + t;
        if (idx < 832) {
            int row = idx / 26, c = idx % 26;
            const __half* src = d_cam_h + ((size_t)(b * CLS_) + row) * HWP + c * 8;
            CP_ASYNC16(sb + GC_OFF + row * G_ROWB + c * 16, src);
        }
    }
    g_load_fv(sb, 0, b, 0, t);
    CP_ASYNC_COMMIT();

    for (int ic = 0; ic < 4; ic++) {
        const int buf = ic & 1;
        if (ic + 1 < 4) {
            g_load_fv(sb, buf ^ 1, b, ic + 1, t);
            CP_ASYNC_COMMIT();
            CP_ASYNC_WAIT1();
        } else {
            CP_ASYNC_WAIT0();
        }
        __syncthreads();

        float acc[4][4];
#pragma unroll
        for (int nf = 0; nf < 4; nf++)
#pragma unroll
            for (int q = 0; q < 4; q++) acc[nf][q] = 0.f;

        const uint32_t fvb = sb + GF_OFF + buf * GF_BUFSZ;
#pragma unroll
        for (int kst = 0; kst < 13; kst++) {
            uint32_t a[4];
            uint32_t abase = sb + GC_OFF + (my * 16 + r4) * G_ROWB + kst * 32 + j * 8;
            LDS64(a[0], a[2], abase);
            LDS64(a[1], a[3], abase + 8 * G_ROWB);
            uint32_t bh[4][2];
#pragma unroll
            for (int nf = 0; nf < 4; nf++) {
                uint32_t bb = fvb + (ix * 32 + nf * 8 + r4) * G_ROWB + kst * 32 + j * 8;
                LDS64(bh[nf][0], bh[nf][1], bb);
            }
#pragma unroll
            for (int nf = 0; nf < 4; nf++)
                MMA_F16(acc[nf], a, bh[nf]);
        }

        const int c0 = my * 16 + r4;
#pragma unroll
        for (int nf = 0; nf < 4; nf++) {
            int ig = ic * 128 + ix * 32 + nf * 8 + 2 * j;
            int gg = ig >> 4, rm = ig & 15;
            int wd = (rm < 8) ? rm : (rm - 7);
            int word = gg * 8 + wd;
            uint32_t* g0 = (uint32_t*)d_g_h + ((size_t)b * CLS_ + c0) * 256 + word;
            *g0 = pack_h2(__float2half_rn(acc[nf][0]), __float2half_rn(acc[nf][1]));
            uint32_t* g1 = (uint32_t*)d_g_h + ((size_t)b * CLS_ + c0 + 8) * 256 + word;
            *g1 = pack_h2(__float2half_rn(acc[nf][2]), __float2half_rn(acc[nf][3]));
        }
        __syncthreads();
    }
}

// =====================================================================
// camsum (blocks 0..255) + wbs (blocks 256..383)
// =====================================================================
__global__ void k_small(const float* __restrict__ cam, const float* __restrict__ Wv,
                        const float* __restrict__ bs) {
    if (blockIdx.x < 256) {
        int b = blockIdx.x;
        int w = threadIdx.x >> 5, lane = threadIdx.x & 31;
        for (int c = w; c < CLS_; c += 8) {
            const float* p = cam + ((size_t)b * CLS_ + c) * HWV2;
            float s = 0.f;
            for (int k = lane; k < HWV2; k += 32) s += p[k];
#pragma unroll
            for (int off = 16; off; off >>= 1) s += __shfl_xor_sync(0xffffffffu, s, off);
            if (!lane) d_camsum[b * CLS_ + c] = s;
        }
    } else {
        int o = blockIdx.x - 256;
        if (threadIdx.x < 32) {
            int lane = threadIdx.x;
            float s = 0.f;
            for (int d = lane; d < D_; d += 32) s = fmaf(Wv[(size_t)o * D_ + d], bs[d], s);
#pragma unroll
            for (int off = 16; off; off >>= 1) s += __shfl_xor_sync(0xffffffffu, s, off);
            if (!lane) d_wbs[o] = s;
        }
    }
}

// =====================================================================
// Wvs[o,i] = sum_d Wv[o,d]*Ws[d,i]  (fp32 out + fp16 permuted out)
// =====================================================================
__global__ __launch_bounds__(256) void k_wvs(const float* __restrict__ Wv,
                                             const float* __restrict__ Ws) {
    __shared__ float sV[32][65];
    __shared__ float sS[64][65];
    const int oT = blockIdx.x, iT = blockIdx.y;
    const int t = threadIdx.x;
    const int tx = t & 31, ty = t >> 5;

    float acc[4][2];
#pragma unroll
    for (int a = 0; a < 4; a++) { acc[a][0] = 0.f; acc[a][1] = 0.f; }

    for (int k0 = 0; k0 < D_; k0 += 64) {
#pragma unroll
        for (int r = 0; r < 8; r++) {
            int idx = r * 256 + t;
            int o = idx >> 6, kk = idx & 63;
            sV[o][kk] = Wv[(size_t)(oT * 32 + o) * D_ + k0 + kk];
        }
#pragma unroll
        for (int r = 0; r < 16; r++) {
            int idx = r * 256 + t;
            int kk = idx >> 6, i = idx & 63;
            sS[kk][i] = Ws[(size_t)(k0 + kk) * D_ + iT * 64 + i];
        }
        __syncthreads();
#pragma unroll
        for (int kk = 0; kk < 64; kk++) {
            float bb0 = sS[kk][tx], bb1 = sS[kk][tx + 32];
#pragma unroll
            for (int a = 0; a < 4; a++) {
                float av = sV[ty * 4 + a][kk];
                acc[a][0] = fmaf(av, bb0, acc[a][0]);
                acc[a][1] = fmaf(av, bb1, acc[a][1]);
            }
        }
        __syncthreads();
    }
#pragma unroll
    for (int a = 0; a < 4; a++) {
        int o = oT * 32 + ty * 4 + a;
#pragma unroll
        for (int half_ = 0; half_ < 2; half_++) {
            int i = iT * 64 + tx + 32 * half_;
            float v = acc[a][half_];
            d_Wvs[(size_t)o * D_ + i] = v;
            int gg = i >> 4;
            int ke = (i & ~1) & 15;
            int wd = (ke < 8) ? ke : (ke - 7);
            d_wvs_h[(size_t)o * D_ + gg * 16 + wd * 2 + (i & 1)] = __float2half_rn(v);
        }
    }
}

// =====================================================================
// k_tv_mma: tv = (g.Wvs + wbs*cs)/(cs+1e-10) + bv   (fp16 MMA)
// =====================================================================
#define TV_B_OFF   0
#define TV_B_ROWB  1056
#define TV_A_OFF   (128 * TV_B_ROWB)
#define TV_A_ROWB  288
#define TV_A_BUFSZ (128 * TV_A_ROWB)
#define TV_SMEM    (TV_A_OFF + 2 * TV_A_BUFSZ)

__device__ __forceinline__ void tv_load_a(uint32_t sb, int buf, int m0, int kc, int t) {
#pragma unroll
    for (int r = 0; r < 8; r++) {
        int idx = r * 256 + t;
        int row = idx >> 4, c = idx & 15;
        const __half* src = d_g_h + ((size_t)(m0 + row) * D_ + kc * 128 + c * 8);
        uint32_t dst = sb + TV_A_OFF + buf * TV_A_BUFSZ + row * TV_A_ROWB + c * 16;
        CP_ASYNC16(dst, src);
    }
}

__global__ void __launch_bounds__(256, 1) k_tv_mma(const float* __restrict__ bv) {
    extern __shared__ char smem[];
    uint32_t sb = smem_to_u32(smem);
    const int m0 = blockIdx.x * 128;
    const int t = threadIdx.x;
    const int w = t >> 5, lane = t & 31;
    const int mgrp = w & 3, ogrp = w >> 2;
    const int j = lane & 3, r4 = lane >> 2;

#pragma unroll
    for (int r = 0; r < 32; r++) {
        int idx = r * 256 + t;
        int row = idx >> 6, c = idx & 63;
        const __half* src = d_wvs_h + ((size_t)row * D_ + c * 8);
        CP_ASYNC16(sb + TV_B_OFF + row * TV_B_ROWB + c * 16, src);
    }
    tv_load_a(sb, 0, m0, 0, t);
    CP_ASYNC_COMMIT();

    float acc[2][8][4];
#pragma unroll
    for (int mf = 0; mf < 2; mf++)
#pragma unroll
        for (int nf = 0; nf < 8; nf++)
#pragma unroll
            for (int q = 0; q < 4; q++) acc[mf][nf][q] = 0.f;

    for (int kc = 0; kc < 4; kc++) {
        const int buf = kc & 1;
        if (kc + 1 < 4) {
            tv_load_a(sb, buf ^ 1, m0, kc + 1, t);
            CP_ASYNC_COMMIT();
            CP_ASYNC_WAIT1();
        } else {
            CP_ASYNC_WAIT0();
        }
        __syncthreads();

#pragma unroll
        for (int kst = 0; kst < 8; kst++) {
            const int ks = kc * 8 + kst;
            uint32_t a[2][4];
#pragma unroll
            for (int mf = 0; mf < 2; mf++) {
                uint32_t base = sb + TV_A_OFF + buf * TV_A_BUFSZ
                              + (mgrp * 32 + mf * 16 + r4) * TV_A_ROWB + kst * 32 + j * 8;
                LDS64(a[mf][0], a[mf][2], base);
                LDS64(a[mf][1], a[mf][3], base + 8 * TV_A_ROWB);
            }
            uint32_t bh[8][2];
#pragma unroll
            for (int nf = 0; nf < 8; nf++) {
                uint32_t bb = sb + TV_B_OFF + (ogrp * 64 + nf * 8 + r4) * TV_B_ROWB
                            + ks * 32 + j * 8;
                LDS64(bh[nf][0], bh[nf][1], bb);
            }
#pragma unroll
            for (int mf = 0; mf < 2; mf++)
#pragma unroll
                for (int nf = 0; nf < 8; nf++)
                    MMA_F16(acc[mf][nf], a[mf], bh[nf]);
        }
        __syncthreads();
    }

#pragma unroll
    for (int mf = 0; mf < 2; mf++) {
        int mr0 = m0 + mgrp * 32 + mf * 16 + r4;
        int mr1 = mr0 + 8;
        float cs0 = d_camsum[mr0], cs1 = d_camsum[mr1];
        float inv0 = 1.f / (cs0 + 1e-10f), inv1 = 1.f / (cs1 + 1e-10f);
#pragma unroll
        for (int nf = 0; nf < 8; nf++) {
            int o0 = ogrp * 64 + nf * 8 + 2 * j;
            float wb0 = d_wbs[o0], wb1 = d_wbs[o0 + 1];
            float bv0 = bv[o0], bv1 = bv[o0 + 1];
            d_tv[(size_t)mr0 * DOUT + o0]     = (acc[mf][nf][0] + wb0 * cs0) * inv0 + bv0;
            d_tv[(size_t)mr0 * DOUT + o0 + 1] = (acc[mf][nf][1] + wb1 * cs0) * inv0 + bv1;
            d_tv[(size_t)mr1 * DOUT + o0]     = (acc[mf][nf][2] + wb0 * cs1) * inv1 + bv0;
            d_tv[(size_t)mr1 * DOUT + o0 + 1] = (acc[mf][nf][3] + wb1 * cs1) * inv1 + bv1;
        }
    }
}

// =====================================================================
// k_ta: ta[m,o] = fa[m,:].Wa[o,:] + ba[o]
// =====================================================================
__global__ __launch_bounds__(256) void k_ta(const float* __restrict__ Wa,
                                            const float* __restrict__ ba) {
    __shared__ float sA[128][33];
    __shared__ float sB[128][33];

    const int m0 = blockIdx.x * 128;
    const int t  = threadIdx.x;
    const int tx = t & 15, ty = t >> 4;

    float acc[8][8];
#pragma unroll
    for (int i = 0; i < 8; i++)
#pragma unroll
        for (int jq = 0; jq < 8; jq++) acc[i][jq] = 0.f;

    for (int k0 = 0; k0 < D_; k0 += 32) {
#pragma unroll
        for (int r = 0; r < 16; r++) {
            int idx = r * 256 + t;
            int mm = idx >> 5, kk = idx & 31;
            sA[mm][kk] = d_fa[(size_t)(m0 + mm) * D_ + k0 + kk];
            sB[mm][kk] = Wa[(size_t)mm * D_ + k0 + kk];
        }
        __syncthreads();
#pragma unroll
        for (int kk = 0; kk < 32; kk++) {
            float a[8], b[8];
#pragma unroll
            for (int mi = 0; mi < 8; mi++) a[mi] = sA[ty + 16 * mi][kk];
#pragma unroll
            for (int oj = 0; oj < 8; oj++) b[oj] = sB[tx + 16 * oj][kk];
#pragma unroll
            for (int mi = 0; mi < 8; mi++)
#pragma unroll
                for (int oj = 0; oj < 8; oj++)
                    acc[mi][oj] = fmaf(a[mi], b[oj], acc[mi][oj]);
        }
        __syncthreads();
    }
#pragma unroll
    for (int mi = 0; mi < 8; mi++) {
        int m = m0 + ty + 16 * mi;
#pragma unroll
        for (int oj = 0; oj < 8; oj++) {
            int o = tx + 16 * oj;
            d_ta[(size_t)m * DOUT + o] = acc[mi][oj] + ba[o];
        }
    }
}

// =====================================================================
// losses
// =====================================================================
__global__ void k_loss(const float* __restrict__ pred_a, const float* __restrict__ pred_v,
                       const int* __restrict__ rand_frames, const int* __restrict__ rand_classes,
                       float* __restrict__ out) {
    const int s = blockIdx.x, c = blockIdx.y;
    const int f = threadIdx.x >> 5, lane = threadIdx.x & 31;

    const float pa = pred_a[s * CLS_ + c];
    const bool aa = pa > 0.3f;
    const int num = (int)(pa * (float)FRM);

    const float* tap = d_ta + (size_t)(s * CLS_ + c) * DOUT;
    const float* tvp = d_tv + (size_t)((s * FRM + f) * CLS_ + c) * DOUT;
    const int rf = rand_frames[(s * CLS_ + c) * FRM + f];
    const int rc = rand_classes[(s * CLS_ + c) * FRM + f];
    const float* tvd = d_tv + (size_t)(((s ^ 1) * FRM + rf) * CLS_ + rc) * DOUT;

    float sco = 0.f, sdi = 0.f;
#pragma unroll
    for (int jq = 0; jq < 4; jq++) {
        int o = lane + 32 * jq;
        float t0 = tap[o];
        float d0 = t0 - tvp[o]; sco = fmaf(d0, d0, sco);
        float d1 = t0 - tvd[o]; sdi = fmaf(d1, d1, sdi);
    }
#pragma unroll
    for (int off = 16; off; off >>= 1) {
        sco += __shfl_xor_sync(0xffffffffu, sco, off);
        sdi += __shfl_xor_sync(0xffffffffu, sdi, off);
    }
    if (!lane) {
        float pv = 1.f / (1.f + expf(-pred_v[(s * FRM + f) * CLS_ + c]));
        bool av = pv > 0.3f;
        float mco = (aa && av) ? 1.f : 0.f;
        float mdi = (aa && (f < num)) ? 1.f : 0.f;
        out[((0 * S_ + s) * CLS_ + c) * FRM + f] = sco * (1.f / 128.f) * mco;
        out[((1 * S_ + s) * CLS_ + c) * FRM + f] = sdi * (1.f / 128.f) * mdi;
    }
}

// =====================================================================
extern "C" void kernel_launch(void* const* d_in, const int* in_sizes, int n_in,
                              void* d_out, int out_size) {
    const float* feat_a = (const float*)d_in[0];
    const float* pred_a = (const float*)d_in[1];
    const float* feat_v = (const float*)d_in[2];
    const float* pred_v = (const float*)d_in[3];
    const float* cam    = (const float*)d_in[4];
    const int* rand_frames  = (const int*)d_in[5];
    const int* rand_classes = (const int*)d_in[6];
    const float* Wt = (const float*)d_in[7];
    const float* bt = (const float*)d_in[8];
    const float* Ws = (const float*)d_in[9];
    const float* bs = (const float*)d_in[10];
    const float* Wa = (const float*)d_in[11];
    const float* ba = (const float*)d_in[12];
    const float* Wv = (const float*)d_in[13];
    const float* bv = (const float*)d_in[14];
    float* out = (float*)d_out;

    static bool attr_set = false;
    if (!attr_set) {
        cudaFuncSetAttribute(k_fa_mma, cudaFuncAttributeMaxDynamicSharedMemorySize, FA_SMEM);
        cudaFuncSetAttribute(k_g_mma, cudaFuncAttributeMaxDynamicSharedMemorySize, KG_SMEM);
        cudaFuncSetAttribute(k_tv_mma, cudaFuncAttributeMaxDynamicSharedMemorySize, TV_SMEM);
        attr_set = true;
    }

    // k_fa_mma kept as 4th launch (ncu profiles #4)
    k_cvt_wt<<<64, 256>>>(Wt);                                // 1
    k_prep_feat<<<dim3(BA, 4), 256>>>(feat_a);                // 2
    k_prep_fv<<<(BV * D_) / 16, 256>>>(feat_v);               // 3
    k_fa_mma<<<BA, 256, FA_SMEM>>>(bt);                       // 4  <- profiled
    k_prep_cam<<<(BV * CLS_) / 16, 256>>>(cam);               // 5
    k_g_mma<<<BV, 256, KG_SMEM>>>();                          // 6
    k_small<<<384, 256>>>(cam, Wv, bs);                       // 7
    k_wvs<<<dim3(4, 8), 256>>>(Wv, Ws);                       // 8
    k_ta<<<BA / 128, 256>>>(Wa, ba);                          // 9
    k_tv_mma<<<(BV * CLS_) / 128, 256, TV_SMEM>>>(bv);        // 10
    k_loss<<<dim3(S_, CLS_), 256>>>(pred_a, pred_v, rand_frames, rand_classes, out); // 11
}

// round 8
// speedup vs baseline: 4.1950x; 1.3953x over previous
#include <cuda_runtime.h>
#include <cuda_fp16.h>
#include <math.h>
#include <cstdint>

// Problem constants
#define S_   32
#define FRM  8
#define CLS_ 32
#define D_   512
#define HWA2 64      // 8*8
#define HWV2 196     // 14*14
#define HWP  208     // padded to 13*16
#define DOUT 128
#define BA   (S_*CLS_)   // 1024
#define BV   (S_*FRM)    // 256

// ---------------- device scratch ----------------
__device__ float d_ta[BA * DOUT];
__device__ float d_camsum[BV * CLS_];
__device__ float d_tv[BV * CLS_ * DOUT];
__device__ float d_wbs[DOUT];
// fp16 permuted buffers
__device__ __half d_wt_h[D_ * D_];                      // [o][kperm]
__device__ __half d_wa_h[DOUT * D_];                    // [o][kperm]
__device__ __half d_ft_h[(size_t)BA * HWA2 * D_];       // [b][hw][kperm]
__device__ __half d_fa_h[BA * D_];                      // [b][kperm(o)]
__device__ __half d_fv_h[(size_t)BV * D_ * HWP];        // [b][i][hwperm]
__device__ __half d_cam_h[(size_t)BV * CLS_ * HWP];     // [b][c][hwperm]
__device__ __half d_g_h[(size_t)BV * CLS_ * D_];        // [m][kperm]
__device__ __half d_wvs_h[DOUT * D_];                   // [o][kperm]

// =============== small asm helpers ===============
__device__ __forceinline__ uint32_t smem_to_u32(const void* p) {
    uint32_t a;
    asm("{ .reg .u64 t; cvta.to.shared.u64 t, %1; cvt.u32.u64 %0, t; }" : "=r"(a) : "l"(p));
    return a;
}
#define CP_ASYNC16(sm, g) \
    asm volatile("cp.async.cg.shared.global [%0], [%1], 16;" :: "r"((uint32_t)(sm)), "l"(g) : "memory")
#define CP_ASYNC_COMMIT() asm volatile("cp.async.commit_group;" ::: "memory")
#define CP_ASYNC_WAIT0()  asm volatile("cp.async.wait_group 0;" ::: "memory")
#define CP_ASYNC_WAIT1()  asm volatile("cp.async.wait_group 1;" ::: "memory")

#define LDS64(r0, r1, addr) \
    asm volatile("ld.shared.v2.b32 {%0,%1}, [%2];" : "=r"(r0), "=r"(r1) : "r"((uint32_t)(addr)))

#define MMA_F16(d, a, b) \
    asm volatile("mma.sync.aligned.m16n8k16.row.col.f32.f16.f16.f32 " \
        "{%0,%1,%2,%3}, {%4,%5,%6,%7}, {%8,%9}, {%0,%1,%2,%3};" \
        : "+f"((d)[0]), "+f"((d)[1]), "+f"((d)[2]), "+f"((d)[3]) \
        : "r"((a)[0]), "r"((a)[1]), "r"((a)[2]), "r"((a)[3]), "r"((b)[0]), "r"((b)[1]))

__device__ __forceinline__ uint32_t pack_h2(__half a, __half b) {
    __half2 p = __halves2half2(a, b);
    return *(uint32_t*)&p;
}

// k-permutation within a 16-group (m16n8k16 frag layout):
// word w (fp16 pair): w even -> k = w ; w odd -> k = w + 7.
// inverse (even k e): w = (e < 8) ? e : e - 7.

// =====================================================================
// Prep 1: W fp32 -> permuted fp16 (which=0 -> d_wt_h, which=1 -> d_wa_h)
// =====================================================================
__global__ __launch_bounds__(256) void k_cvt_w(const float* __restrict__ W, int which) {
    int idx = blockIdx.x * 256 + threadIdx.x;
    int o = idx >> 5, g = idx & 31;
    const float* src = W + (size_t)o * D_ + g * 16;
    float v[16];
#pragma unroll
    for (int q = 0; q < 4; q++) {
        float4 f = *(const float4*)(src + q * 4);
        v[q * 4 + 0] = f.x; v[q * 4 + 1] = f.y; v[q * 4 + 2] = f.z; v[q * 4 + 3] = f.w;
    }
    uint32_t hw_[8];
#pragma unroll
    for (int w = 0; w < 8; w++) {
        int k = (w & 1) ? (w + 7) : w;
        hw_[w] = pack_h2(__float2half_rn(v[k]), __float2half_rn(v[k + 1]));
    }
    uint32_t* dh = (uint32_t*)(which ? d_wa_h : d_wt_h) + (size_t)o * 256 + g * 8;
    *(uint4*)(dh + 0) = make_uint4(hw_[0], hw_[1], hw_[2], hw_[3]);
    *(uint4*)(dh + 4) = make_uint4(hw_[4], hw_[5], hw_[6], hw_[7]);
}

// =====================================================================
// Prep 2 (tiled): feat_a [b][k][hw] fp32 -> d_ft_h [b][hw][kperm] fp16
// =====================================================================
__global__ __launch_bounds__(256) void k_prep_feat(const float* __restrict__ feat_a) {
    __shared__ float sm[128][68];
    const int b = blockIdx.x, kc = blockIdx.y;
    const int t = threadIdx.x;
    const float* src = feat_a + ((size_t)b * D_ + kc * 128) * HWA2;
#pragma unroll
    for (int r = 0; r < 8; r++) {
        int fi = r * 256 + t;
        int row = fi >> 4, c4 = fi & 15;
        float4 f = *(const float4*)(src + fi * 4);
        *(float4*)(&sm[row][c4 * 4]) = f;
    }
    __syncthreads();
    const int hw = t & 63, kseg = t >> 6;
    uint32_t* dh = (uint32_t*)d_ft_h + ((size_t)b * HWA2 + hw) * 256 + kc * 64;
#pragma unroll
    for (int g = 0; g < 2; g++) {
        int kbase = kseg * 32 + g * 16;
        uint32_t hw_[8];
#pragma unroll
        for (int w = 0; w < 8; w++) {
            int k = (w & 1) ? (w + 7) : w;
            hw_[w] = pack_h2(__float2half_rn(sm[kbase + k][hw]),
                             __float2half_rn(sm[kbase + k + 1][hw]));
        }
        uint32_t* dst = dh + (kseg * 2 + g) * 8;
        *(uint4*)(dst + 0) = make_uint4(hw_[0], hw_[1], hw_[2], hw_[3]);
        *(uint4*)(dst + 4) = make_uint4(hw_[4], hw_[5], hw_[6], hw_[7]);
    }
}

// =====================================================================
// Prep 3 (merged): feat_v rows then cam rows -> fp16 hw-permuted (pad 208)
// rows [0, BV*D) -> d_fv_h ; rows [BV*D, BV*D + BV*CLS) -> d_cam_h
// =====================================================================
__global__ __launch_bounds__(256) void k_prep_fvcam(const float* __restrict__ feat_v,
                                                    const float* __restrict__ cam) {
    const int t = threadIdx.x;
    const int g = t & 15, rloc = t >> 4;
    const long row = (long)blockIdx.x * 16 + rloc;
    if (g >= 13) return;
    const float* src;
    uint32_t* dst;
    if (row < (long)BV * D_) {
        src = feat_v + row * HWV2 + g * 16;
        dst = (uint32_t*)d_fv_h + row * (HWP / 2) + g * 8;
    } else {
        long r2 = row - (long)BV * D_;
        src = cam + r2 * HWV2 + g * 16;
        dst = (uint32_t*)d_cam_h + r2 * (HWP / 2) + g * 8;
    }
    float v[16];
#pragma unroll
    for (int q = 0; q < 16; q++) {
        int hw = g * 16 + q;
        v[q] = (hw < HWV2) ? src[q] : 0.f;
    }
    uint32_t wv[8];
#pragma unroll
    for (int w = 0; w < 8; w++) {
        int k = (w & 1) ? (w + 7) : w;
        wv[w] = pack_h2(__float2half_rn(v[k]), __float2half_rn(v[k + 1]));
    }
    *(uint4*)(dst + 0) = make_uint4(wv[0], wv[1], wv[2], wv[3]);
    *(uint4*)(dst + 4) = make_uint4(wv[4], wv[5], wv[6], wv[7]);
}

// =====================================================================
// k_fa_mma: fa[b,o] = max_hw( feat[b,:,hw] . Wt[o,:] ) + bt[o]
// 2 CTAs/SM. Epilogue writes fa as k-permuted fp16 (d_fa_h).
// =====================================================================
#define FEAT_OFF  1024
#define FEAT_ROWB 1056
#define FEAT_SZ   (64 * FEAT_ROWB)
#define WT_OFF    (FEAT_OFF + FEAT_SZ)
#define WT_ROWB   160
#define WT_BUFSZ  (128 * WT_ROWB)
#define FA_SMEM   (WT_OFF + 2 * WT_BUFSZ)   // 109568

__device__ __forceinline__ void fa_load_wt(uint32_t sb, int buf, int otp, int kc, int t) {
#pragma unroll
    for (int r = 0; r < 4; r++) {
        int idx = r * 256 + t;
        int row = idx >> 3, c = idx & 7;
        const __half* src = d_wt_h + ((size_t)(otp * 128 + row) * D_ + kc * 64 + c * 8);
        uint32_t dst = sb + WT_OFF + buf * WT_BUFSZ + row * WT_ROWB + c * 16;
        CP_ASYNC16(dst, src);
    }
}

__global__ void __launch_bounds__(256, 2) k_fa_mma(const float* __restrict__ bt) {
    extern __shared__ char smem[];
    float* red = (float*)smem;
    uint32_t sb = smem_to_u32(smem);
    const int b = blockIdx.x;
    const int t = threadIdx.x;
    const int w = t >> 5, lane = t & 31;
    const int ot2 = w >> 2, oy = (w >> 1) & 1, hx = w & 1;
    const int j = lane & 3, r4 = lane >> 2;

#pragma unroll
    for (int r = 0; r < 16; r++) {
        int idx = r * 256 + t;
        int row = idx >> 6, c = idx & 63;
        const __half* src = d_ft_h + ((size_t)(b * HWA2 + row) * D_ + c * 8);
        uint32_t dst = sb + FEAT_OFF + row * FEAT_ROWB + c * 16;
        CP_ASYNC16(dst, src);
    }
    fa_load_wt(sb, 0, 0, 0, t);
    CP_ASYNC_COMMIT();

    float acc[2][4][4];
#pragma unroll
    for (int mf = 0; mf < 2; mf++)
#pragma unroll
        for (int nf = 0; nf < 4; nf++)
#pragma unroll
            for (int q = 0; q < 4; q++) acc[mf][nf][q] = 0.f;

    const int oA = ot2 * 64 + oy * 32 + r4;
    const int hwB = hx * 32 + r4;

    for (int it = 0; it < 32; it++) {
        const int otp = it >> 3, kc = it & 7, buf = it & 1;
        if (it + 1 < 32) {
            fa_load_wt(sb, buf ^ 1, (it + 1) >> 3, (it + 1) & 7, t);
            CP_ASYNC_COMMIT();
            CP_ASYNC_WAIT1();
        } else {
            CP_ASYNC_WAIT0();
        }
        __syncthreads();

        const uint32_t wtb = sb + WT_OFF + buf * WT_BUFSZ;
#pragma unroll
        for (int kst = 0; kst < 4; kst++) {
            const int ks = kc * 4 + kst;
            uint32_t a[2][4];
#pragma unroll
            for (int mf = 0; mf < 2; mf++) {
                uint32_t base = wtb + (oA + mf * 16) * WT_ROWB + kst * 32 + j * 8;
                LDS64(a[mf][0], a[mf][2], base);
                LDS64(a[mf][1], a[mf][3], base + 8 * WT_ROWB);
            }
            uint32_t bh[4][2];
#pragma unroll
            for (int nf = 0; nf < 4; nf++) {
                uint32_t bb = sb + FEAT_OFF + (hwB + nf * 8) * FEAT_ROWB + ks * 32 + j * 8;
                LDS64(bh[nf][0], bh[nf][1], bb);
            }
#pragma unroll
            for (int mf = 0; mf < 2; mf++)
#pragma unroll
                for (int nf = 0; nf < 4; nf++)
                    MMA_F16(acc[mf][nf], a[mf], bh[nf]);
        }

        if (kc == 7) {
#pragma unroll
            for (int mf = 0; mf < 2; mf++) {
                float m0 = -3.4e38f, m1 = -3.4e38f;
#pragma unroll
                for (int nf = 0; nf < 4; nf++) {
                    m0 = fmaxf(m0, fmaxf(acc[mf][nf][0], acc[mf][nf][1]));
                    m1 = fmaxf(m1, fmaxf(acc[mf][nf][2], acc[mf][nf][3]));
                }
                m0 = fmaxf(m0, __shfl_xor_sync(0xffffffffu, m0, 1));
                m0 = fmaxf(m0, __shfl_xor_sync(0xffffffffu, m0, 2));
                m1 = fmaxf(m1, __shfl_xor_sync(0xffffffffu, m1, 1));
                m1 = fmaxf(m1, __shfl_xor_sync(0xffffffffu, m1, 2));
                if (j == 0) {
                    red[ot2 * 128 + hx * 64 + oy * 32 + mf * 16 + r4] = m0;
                    red[ot2 * 128 + hx * 64 + oy * 32 + mf * 16 + r4 + 8] = m1;
                }
            }
            __syncthreads();
            if (t < 128) {
                int o2 = t >> 6, ol = t & 63;
                float v = fmaxf(red[o2 * 128 + ol], red[o2 * 128 + 64 + ol]);
                int og = otp * 128 + o2 * 64 + ol;
                v += bt[og];
                // permuted fp16 write for k_ta_mma
                int gg = og >> 4, ke = og & 15;
                int kel = ke & ~1;
                int wd = (kel < 8) ? kel : (kel - 7);
                d_fa_h[(size_t)b * D_ + gg * 16 + wd * 2 + (ke & 1)] = __float2half_rn(v);
            }
#pragma unroll
            for (int mf = 0; mf < 2; mf++)
#pragma unroll
                for (int nf = 0; nf < 4; nf++)
#pragma unroll
                    for (int q = 0; q < 4; q++) acc[mf][nf][q] = 0.f;
        }
        __syncthreads();
    }
}

// =====================================================================
// k_g_mma: g[b,c,i] = sum_hw cam*feat_v -> fp16 k-permuted d_g_h
// =====================================================================
#define GC_OFF   1024
#define G_ROWB   416
#define GC_SZ    (32 * G_ROWB)
#define GF_OFF   (GC_OFF + GC_SZ)
#define GF_BUFSZ (128 * G_ROWB)
#define KG_SMEM  (GF_OFF + 2 * GF_BUFSZ)

__device__ __forceinline__ void g_load_fv(uint32_t sb, int buf, int b, int ic, int t) {
#pragma unroll
    for (int r = 0; r < 13; r++) {
        int idx = r * 256 + t;
        int row = idx / 26, c = idx % 26;
        const __half* src = d_fv_h + ((size_t)(b * D_) + ic * 128 + row) * HWP + c * 8;
        uint32_t dst = sb + GF_OFF + buf * GF_BUFSZ + row * G_ROWB + c * 16;
        CP_ASYNC16(dst, src);
    }
}

__global__ void __launch_bounds__(256, 1) k_g_mma() {
    extern __shared__ char smem[];
    uint32_t sb = smem_to_u32(smem);
    const int b = blockIdx.x;
    const int t = threadIdx.x;
    const int w = t >> 5, lane = t & 31;
    const int my = w & 1, ix = w >> 1;
    const int j = lane & 3, r4 = lane >> 2;

#pragma unroll
    for (int r = 0; r < 4; r++) {
        int idx = r * 256 + t;
        if (idx < 832) {
            int row = idx / 26, c = idx % 26;
            const __half* src = d_cam_h + ((size_t)(b * CLS_) + row) * HWP + c * 8;
            CP_ASYNC16(sb + GC_OFF + row * G_ROWB + c * 16, src);
        }
    }
    g_load_fv(sb, 0, b, 0, t);
    CP_ASYNC_COMMIT();

    for (int ic = 0; ic < 4; ic++) {
        const int buf = ic & 1;
        if (ic + 1 < 4) {
            g_load_fv(sb, buf ^ 1, b, ic + 1, t);
            CP_ASYNC_COMMIT();
            CP_ASYNC_WAIT1();
        } else {
            CP_ASYNC_WAIT0();
        }
        __syncthreads();

        float acc[4][4];
#pragma unroll
        for (int nf = 0; nf < 4; nf++)
#pragma unroll
            for (int q = 0; q < 4; q++) acc[nf][q] = 0.f;

        const uint32_t fvb = sb + GF_OFF + buf * GF_BUFSZ;
#pragma unroll
        for (int kst = 0; kst < 13; kst++) {
            uint32_t a[4];
            uint32_t abase = sb + GC_OFF + (my * 16 + r4) * G_ROWB + kst * 32 + j * 8;
            LDS64(a[0], a[2], abase);
            LDS64(a[1], a[3], abase + 8 * G_ROWB);
            uint32_t bh[4][2];
#pragma unroll
            for (int nf = 0; nf < 4; nf++) {
                uint32_t bb = fvb + (ix * 32 + nf * 8 + r4) * G_ROWB + kst * 32 + j * 8;
                LDS64(bh[nf][0], bh[nf][1], bb);
            }
#pragma unroll
            for (int nf = 0; nf < 4; nf++)
                MMA_F16(acc[nf], a, bh[nf]);
        }

        const int c0 = my * 16 + r4;
#pragma unroll
        for (int nf = 0; nf < 4; nf++) {
            int ig = ic * 128 + ix * 32 + nf * 8 + 2 * j;
            int gg = ig >> 4, rm = ig & 15;
            int wd = (rm < 8) ? rm : (rm - 7);
            int word = gg * 8 + wd;
            uint32_t* g0 = (uint32_t*)d_g_h + ((size_t)b * CLS_ + c0) * 256 + word;
            *g0 = pack_h2(__float2half_rn(acc[nf][0]), __float2half_rn(acc[nf][1]));
            uint32_t* g1 = (uint32_t*)d_g_h + ((size_t)b * CLS_ + c0 + 8) * 256 + word;
            *g1 = pack_h2(__float2half_rn(acc[nf][2]), __float2half_rn(acc[nf][3]));
        }
        __syncthreads();
    }
}

// =====================================================================
// camsum (blocks 0..255) + wbs (blocks 256..383)
// =====================================================================
__global__ void k_small(const float* __restrict__ cam, const float* __restrict__ Wv,
                        const float* __restrict__ bs) {
    if (blockIdx.x < 256) {
        int b = blockIdx.x;
        int w = threadIdx.x >> 5, lane = threadIdx.x & 31;
        for (int c = w; c < CLS_; c += 8) {
            const float* p = cam + ((size_t)b * CLS_ + c) * HWV2;
            float s = 0.f;
            for (int k = lane; k < HWV2; k += 32) s += p[k];
#pragma unroll
            for (int off = 16; off; off >>= 1) s += __shfl_xor_sync(0xffffffffu, s, off);
            if (!lane) d_camsum[b * CLS_ + c] = s;
        }
    } else {
        int o = blockIdx.x - 256;
        if (threadIdx.x < 32) {
            int lane = threadIdx.x;
            float s = 0.f;
            for (int d = lane; d < D_; d += 32) s = fmaf(Wv[(size_t)o * D_ + d], bs[d], s);
#pragma unroll
            for (int off = 16; off; off >>= 1) s += __shfl_xor_sync(0xffffffffu, s, off);
            if (!lane) d_wbs[o] = s;
        }
    }
}

// =====================================================================
// Wvs[o,i] = sum_d Wv[o,d]*Ws[d,i]  (fp16 permuted out only)
// =====================================================================
__global__ __launch_bounds__(256) void k_wvs(const float* __restrict__ Wv,
                                             const float* __restrict__ Ws) {
    __shared__ float sV[32][65];
    __shared__ float sS[64][65];
    const int oT = blockIdx.x, iT = blockIdx.y;
    const int t = threadIdx.x;
    const int tx = t & 31, ty = t >> 5;

    float acc[4][2];
#pragma unroll
    for (int a = 0; a < 4; a++) { acc[a][0] = 0.f; acc[a][1] = 0.f; }

    for (int k0 = 0; k0 < D_; k0 += 64) {
#pragma unroll
        for (int r = 0; r < 8; r++) {
            int idx = r * 256 + t;
            int o = idx >> 6, kk = idx & 63;
            sV[o][kk] = Wv[(size_t)(oT * 32 + o) * D_ + k0 + kk];
        }
#pragma unroll
        for (int r = 0; r < 16; r++) {
            int idx = r * 256 + t;
            int kk = idx >> 6, i = idx & 63;
            sS[kk][i] = Ws[(size_t)(k0 + kk) * D_ + iT * 64 + i];
        }
        __syncthreads();
#pragma unroll
        for (int kk = 0; kk < 64; kk++) {
            float bb0 = sS[kk][tx], bb1 = sS[kk][tx + 32];
#pragma unroll
            for (int a = 0; a < 4; a++) {
                float av = sV[ty * 4 + a][kk];
                acc[a][0] = fmaf(av, bb0, acc[a][0]);
                acc[a][1] = fmaf(av, bb1, acc[a][1]);
            }
        }
        __syncthreads();
    }
#pragma unroll
    for (int a = 0; a < 4; a++) {
        int o = oT * 32 + ty * 4 + a;
#pragma unroll
        for (int half_ = 0; half_ < 2; half_++) {
            int i = iT * 64 + tx + 32 * half_;
            float v = acc[a][half_];
            int gg = i >> 4;
            int ke = (i & ~1) & 15;
            int wd = (ke < 8) ? ke : (ke - 7);
            d_wvs_h[(size_t)o * D_ + gg * 16 + wd * 2 + (i & 1)] = __float2half_rn(v);
        }
    }
}

// =====================================================================
// shared 128xK GEMM body used by k_tv_mma / k_ta_mma
// =====================================================================
#define TV_B_OFF   0
#define TV_B_ROWB  1056
#define TV_A_OFF   (128 * TV_B_ROWB)
#define TV_A_ROWB  288
#define TV_A_BUFSZ (128 * TV_A_ROWB)
#define TV_SMEM    (TV_A_OFF + 2 * TV_A_BUFSZ)

__device__ __forceinline__ void tv_load_a(uint32_t sb, int buf, const __half* A,
                                          int m0, int kc, int t) {
#pragma unroll
    for (int r = 0; r < 8; r++) {
        int idx = r * 256 + t;
        int row = idx >> 4, c = idx & 15;
        const __half* src = A + ((size_t)(m0 + row) * D_ + kc * 128 + c * 8);
        uint32_t dst = sb + TV_A_OFF + buf * TV_A_BUFSZ + row * TV_A_ROWB + c * 16;
        CP_ASYNC16(dst, src);
    }
}

__device__ __forceinline__ void tv_gemm_body(uint32_t sb, const __half* A, const __half* B,
                                             int m0, int t, float acc[2][8][4]) {
    const int w = t >> 5, lane = t & 31;
    const int mgrp = w & 3, ogrp = w >> 2;
    const int j = lane & 3, r4 = lane >> 2;

#pragma unroll
    for (int r = 0; r < 32; r++) {
        int idx = r * 256 + t;
        int row = idx >> 6, c = idx & 63;
        CP_ASYNC16(sb + TV_B_OFF + row * TV_B_ROWB + c * 16, B + ((size_t)row * D_ + c * 8));
    }
    tv_load_a(sb, 0, A, m0, 0, t);
    CP_ASYNC_COMMIT();

    for (int kc = 0; kc < 4; kc++) {
        const int buf = kc & 1;
        if (kc + 1 < 4) {
            tv_load_a(sb, buf ^ 1, A, m0, kc + 1, t);
            CP_ASYNC_COMMIT();
            CP_ASYNC_WAIT1();
        } else {
            CP_ASYNC_WAIT0();
        }
        __syncthreads();

#pragma unroll
        for (int kst = 0; kst < 8; kst++) {
            const int ks = kc * 8 + kst;
            uint32_t a[2][4];
#pragma unroll
            for (int mf = 0; mf < 2; mf++) {
                uint32_t base = sb + TV_A_OFF + buf * TV_A_BUFSZ
                              + (mgrp * 32 + mf * 16 + r4) * TV_A_ROWB + kst * 32 + j * 8;
                LDS64(a[mf][0], a[mf][2], base);
                LDS64(a[mf][1], a[mf][3], base + 8 * TV_A_ROWB);
            }
            uint32_t bh[8][2];
#pragma unroll
            for (int nf = 0; nf < 8; nf++) {
                uint32_t bb = sb + TV_B_OFF + (ogrp * 64 + nf * 8 + r4) * TV_B_ROWB
                            + ks * 32 + j * 8;
                LDS64(bh[nf][0], bh[nf][1], bb);
            }
#pragma unroll
            for (int mf = 0; mf < 2; mf++)
#pragma unroll
                for (int nf = 0; nf < 8; nf++)
                    MMA_F16(acc[mf][nf], a[mf], bh[nf]);
        }
        __syncthreads();
    }
}

__global__ void __launch_bounds__(256, 1) k_tv_mma(const float* __restrict__ bv) {
    extern __shared__ char smem[];
    uint32_t sb = smem_to_u32(smem);
    const int m0 = blockIdx.x * 128;
    const int t = threadIdx.x;
    const int w = t >> 5, lane = t & 31;
    const int mgrp = w & 3, ogrp = w >> 2;
    const int j = lane & 3, r4 = lane >> 2;

    float acc[2][8][4];
#pragma unroll
    for (int mf = 0; mf < 2; mf++)
#pragma unroll
        for (int nf = 0; nf < 8; nf++)
#pragma unroll
            for (int q = 0; q < 4; q++) acc[mf][nf][q] = 0.f;

    tv_gemm_body(sb, d_g_h, d_wvs_h, m0, t, acc);

#pragma unroll
    for (int mf = 0; mf < 2; mf++) {
        int mr0 = m0 + mgrp * 32 + mf * 16 + r4;
        int mr1 = mr0 + 8;
        float cs0 = d_camsum[mr0], cs1 = d_camsum[mr1];
        float inv0 = 1.f / (cs0 + 1e-10f), inv1 = 1.f / (cs1 + 1e-10f);
#pragma unroll
        for (int nf = 0; nf < 8; nf++) {
            int o0 = ogrp * 64 + nf * 8 + 2 * j;
            float wb0 = d_wbs[o0], wb1 = d_wbs[o0 + 1];
            float bv0 = bv[o0], bv1 = bv[o0 + 1];
            d_tv[(size_t)mr0 * DOUT + o0]     = (acc[mf][nf][0] + wb0 * cs0) * inv0 + bv0;
            d_tv[(size_t)mr0 * DOUT + o0 + 1] = (acc[mf][nf][1] + wb1 * cs0) * inv0 + bv1;
            d_tv[(size_t)mr1 * DOUT + o0]     = (acc[mf][nf][2] + wb0 * cs1) * inv1 + bv0;
            d_tv[(size_t)mr1 * DOUT + o0 + 1] = (acc[mf][nf][3] + wb1 * cs1) * inv1 + bv1;
        }
    }
}

__global__ void __launch_bounds__(256, 1) k_ta_mma(const float* __restrict__ ba) {
    extern __shared__ char smem[];
    uint32_t sb = smem_to_u32(smem);
    const int m0 = blockIdx.x * 128;
    const int t = threadIdx.x;
    const int w = t >> 5, lane = t & 31;
    const int mgrp = w & 3, ogrp = w >> 2;
    const int j = lane & 3, r4 = lane >> 2;

    float acc[2][8][4];
#pragma unroll
    for (int mf = 0; mf < 2; mf++)
#pragma unroll
        for (int nf = 0; nf < 8; nf++)
#pragma unroll
            for (int q = 0; q < 4; q++) acc[mf][nf][q] = 0.f;

    tv_gemm_body(sb, d_fa_h, d_wa_h, m0, t, acc);

#pragma unroll
    for (int mf = 0; mf < 2; mf++) {
        int mr0 = m0 + mgrp * 32 + mf * 16 + r4;
        int mr1 = mr0 + 8;
#pragma unroll
        for (int nf = 0; nf < 8; nf++) {
            int o0 = ogrp * 64 + nf * 8 + 2 * j;
            float ba0 = ba[o0], ba1 = ba[o0 + 1];
            d_ta[(size_t)mr0 * DOUT + o0]     = acc[mf][nf][0] + ba0;
            d_ta[(size_t)mr0 * DOUT + o0 + 1] = acc[mf][nf][1] + ba1;
            d_ta[(size_t)mr1 * DOUT + o0]     = acc[mf][nf][2] + ba0;
            d_ta[(size_t)mr1 * DOUT + o0 + 1] = acc[mf][nf][3] + ba1;
        }
    }
}

// =====================================================================
// losses
// =====================================================================
__global__ void k_loss(const float* __restrict__ pred_a, const float* __restrict__ pred_v,
                       const int* __restrict__ rand_frames, const int* __restrict__ rand_classes,
                       float* __restrict__ out) {
    const int s = blockIdx.x, c = blockIdx.y;
    const int f = threadIdx.x >> 5, lane = threadIdx.x & 31;

    const float pa = pred_a[s * CLS_ + c];
    const bool aa = pa > 0.3f;
    const int num = (int)(pa * (float)FRM);

    const float* tap = d_ta + (size_t)(s * CLS_ + c) * DOUT;
    const float* tvp = d_tv + (size_t)((s * FRM + f) * CLS_ + c) * DOUT;
    const int rf = rand_frames[(s * CLS_ + c) * FRM + f];
    const int rc = rand_classes[(s * CLS_ + c) * FRM + f];
    const float* tvd = d_tv + (size_t)(((s ^ 1) * FRM + rf) * CLS_ + rc) * DOUT;

    float sco = 0.f, sdi = 0.f;
#pragma unroll
    for (int jq = 0; jq < 4; jq++) {
        int o = lane + 32 * jq;
        float t0 = tap[o];
        float d0 = t0 - tvp[o]; sco = fmaf(d0, d0, sco);
        float d1 = t0 - tvd[o]; sdi = fmaf(d1, d1, sdi);
    }
#pragma unroll
    for (int off = 16; off; off >>= 1) {
        sco += __shfl_xor_sync(0xffffffffu, sco, off);
        sdi += __shfl_xor_sync(0xffffffffu, sdi, off);
    }
    if (!lane) {
        float pv = 1.f / (1.f + expf(-pred_v[(s * FRM + f) * CLS_ + c]));
        bool av = pv > 0.3f;
        float mco = (aa && av) ? 1.f : 0.f;
        float mdi = (aa && (f < num)) ? 1.f : 0.f;
        out[((0 * S_ + s) * CLS_ + c) * FRM + f] = sco * (1.f / 128.f) * mco;
        out[((1 * S_ + s) * CLS_ + c) * FRM + f] = sdi * (1.f / 128.f) * mdi;
    }
}

// =====================================================================
extern "C" void kernel_launch(void* const* d_in, const int* in_sizes, int n_in,
                              void* d_out, int out_size) {
    const float* feat_a = (const float*)d_in[0];
    const float* pred_a = (const float*)d_in[1];
    const float* feat_v = (const float*)d_in[2];
    const float* pred_v = (const float*)d_in[3];
    const float* cam    = (const float*)d_in[4];
    const int* rand_frames  = (const int*)d_in[5];
    const int* rand_classes = (const int*)d_in[6];
    const float* Wt = (const float*)d_in[7];
    const float* bt = (const float*)d_in[8];
    const float* Ws = (const float*)d_in[9];
    const float* bs = (const float*)d_in[10];
    const float* Wa = (const float*)d_in[11];
    const float* ba = (const float*)d_in[12];
    const float* Wv = (const float*)d_in[13];
    const float* bv = (const float*)d_in[14];
    float* out = (float*)d_out;

    static int inited = 0;
    static cudaStream_t s2 = 0;
    static cudaEvent_t eF = 0, eJ = 0;
    if (!inited) {
        inited = 1;
        cudaFuncSetAttribute(k_fa_mma, cudaFuncAttributeMaxDynamicSharedMemorySize, FA_SMEM);
        cudaFuncSetAttribute(k_g_mma, cudaFuncAttributeMaxDynamicSharedMemorySize, KG_SMEM);
        cudaFuncSetAttribute(k_tv_mma, cudaFuncAttributeMaxDynamicSharedMemorySize, TV_SMEM);
        cudaFuncSetAttribute(k_ta_mma, cudaFuncAttributeMaxDynamicSharedMemorySize, TV_SMEM);
        if (cudaStreamCreateWithFlags(&s2, cudaStreamNonBlocking) != cudaSuccess) s2 = 0;
        if (s2) {
            if (cudaEventCreateWithFlags(&eF, cudaEventDisableTiming) != cudaSuccess) { eF = 0; }
            if (cudaEventCreateWithFlags(&eJ, cudaEventDisableTiming) != cudaSuccess) { eJ = 0; }
        }
    }
    const bool fork = (s2 != 0) && (eF != 0) && (eJ != 0);
    cudaStream_t vs = fork ? s2 : (cudaStream_t)0;

    if (fork) {
        cudaEventRecord(eF, 0);
        cudaStreamWaitEvent(s2, eF, 0);
    }

    // ---- audio chain (capture/default stream) ----
    k_cvt_w<<<64, 256>>>(Wt, 0);
    k_cvt_w<<<16, 256>>>(Wa, 1);
    k_prep_feat<<<dim3(BA, 4), 256>>>(feat_a);
    k_fa_mma<<<BA, 256, FA_SMEM>>>(bt);
    k_ta_mma<<<BA / 128, 256, TV_SMEM>>>(ba);

    // ---- video chain (s2 when available) ----
    k_prep_fvcam<<<(BV * D_ + BV * CLS_) / 16, 256, 0, vs>>>(feat_v, cam);
    k_small<<<384, 256, 0, vs>>>(cam, Wv, bs);
    k_wvs<<<dim3(4, 8), 256, 0, vs>>>(Wv, Ws);
    k_g_mma<<<BV, 256, KG_SMEM, vs>>>();
    k_tv_mma<<<(BV * CLS_) / 128, 256, TV_SMEM, vs>>>(bv);

    if (fork) {
        cudaEventRecord(eJ, s2);
        cudaStreamWaitEvent(0, eJ, 0);
    }

    k_loss<<<dim3(S_, CLS_), 256>>>(pred_a, pred_v, rand_frames, rand_classes, out);
}

// round 9
// speedup vs baseline: 4.7873x; 1.1412x over previous
#include <cuda_runtime.h>
#include <cuda_fp16.h>
#include <math.h>
#include <cstdint>

// Problem constants
#define S_   32
#define FRM  8
#define CLS_ 32
#define D_   512
#define HWA2 64      // 8*8
#define HWV2 196     // 14*14
#define HWP  208     // padded to 13*16
#define DOUT 128
#define BA   (S_*CLS_)   // 1024
#define BV   (S_*FRM)    // 256

// ---------------- device scratch ----------------
__device__ float d_ta[BA * DOUT];
__device__ float d_camsum[BV * CLS_];
__device__ float d_tv[BV * CLS_ * DOUT];
__device__ float d_wbs[DOUT];
// fp16 permuted buffers
__device__ __half d_wt_h[D_ * D_];                      // [o][kperm]
__device__ __half d_wa_h[DOUT * D_];                    // [o][kperm]
__device__ __half d_fa_h[BA * D_];                      // [b][kperm(o)]
__device__ __half d_fv_h[(size_t)BV * D_ * HWP];        // [b][i][hwperm]
__device__ __half d_cam_h[(size_t)BV * CLS_ * HWP];     // [b][c][hwperm]
__device__ __half d_g_h[(size_t)BV * CLS_ * D_];        // [m][kperm]
__device__ __half d_wvs_h[DOUT * D_];                   // [o][kperm]

// =============== small asm helpers ===============
__device__ __forceinline__ uint32_t smem_to_u32(const void* p) {
    uint32_t a;
    asm("{ .reg .u64 t; cvta.to.shared.u64 t, %1; cvt.u32.u64 %0, t; }" : "=r"(a) : "l"(p));
    return a;
}
#define CP_ASYNC16(sm, g) \
    asm volatile("cp.async.cg.shared.global [%0], [%1], 16;" :: "r"((uint32_t)(sm)), "l"(g) : "memory")
#define CP_ASYNC_COMMIT() asm volatile("cp.async.commit_group;" ::: "memory")
#define CP_ASYNC_WAIT0()  asm volatile("cp.async.wait_group 0;" ::: "memory")
#define CP_ASYNC_WAIT1()  asm volatile("cp.async.wait_group 1;" ::: "memory")

#define LDS64(r0, r1, addr) \
    asm volatile("ld.shared.v2.b32 {%0,%1}, [%2];" : "=r"(r0), "=r"(r1) : "r"((uint32_t)(addr)))

#define MMA_F16(d, a, b) \
    asm volatile("mma.sync.aligned.m16n8k16.row.col.f32.f16.f16.f32 " \
        "{%0,%1,%2,%3}, {%4,%5,%6,%7}, {%8,%9}, {%0,%1,%2,%3};" \
        : "+f"((d)[0]), "+f"((d)[1]), "+f"((d)[2]), "+f"((d)[3]) \
        : "r"((a)[0]), "r"((a)[1]), "r"((a)[2]), "r"((a)[3]), "r"((b)[0]), "r"((b)[1]))

__device__ __forceinline__ uint32_t pack_h2(__half a, __half b) {
    __half2 p = __halves2half2(a, b);
    return *(uint32_t*)&p;
}

// k-permutation within a 16-group (m16n8k16 frag layout):
// word w (fp16 pair): w even -> k = w ; w odd -> k = w + 7.
// inverse (even k e): w = (e < 8) ? e : e - 7.

// =====================================================================
// Prep 1: W fp32 -> permuted fp16 (which=0 -> d_wt_h, which=1 -> d_wa_h)
// =====================================================================
__global__ __launch_bounds__(256) void k_cvt_w(const float* __restrict__ W, int which) {
    int idx = blockIdx.x * 256 + threadIdx.x;
    int o = idx >> 5, g = idx & 31;
    const float* src = W + (size_t)o * D_ + g * 16;
    float v[16];
#pragma unroll
    for (int q = 0; q < 4; q++) {
        float4 f = *(const float4*)(src + q * 4);
        v[q * 4 + 0] = f.x; v[q * 4 + 1] = f.y; v[q * 4 + 2] = f.z; v[q * 4 + 3] = f.w;
    }
    uint32_t hw_[8];
#pragma unroll
    for (int w = 0; w < 8; w++) {
        int k = (w & 1) ? (w + 7) : w;
        hw_[w] = pack_h2(__float2half_rn(v[k]), __float2half_rn(v[k + 1]));
    }
    uint32_t* dh = (uint32_t*)(which ? d_wa_h : d_wt_h) + (size_t)o * 256 + g * 8;
    *(uint4*)(dh + 0) = make_uint4(hw_[0], hw_[1], hw_[2], hw_[3]);
    *(uint4*)(dh + 4) = make_uint4(hw_[4], hw_[5], hw_[6], hw_[7]);
}

// =====================================================================
// Prep (video): feat_v rows then cam rows -> fp16 hw-permuted (pad 208)
// =====================================================================
__global__ __launch_bounds__(256) void k_prep_fvcam(const float* __restrict__ feat_v,
                                                    const float* __restrict__ cam) {
    const int t = threadIdx.x;
    const int g = t & 15, rloc = t >> 4;
    const long row = (long)blockIdx.x * 16 + rloc;
    if (g >= 13) return;
    const float* src;
    uint32_t* dst;
    if (row < (long)BV * D_) {
        src = feat_v + row * HWV2 + g * 16;
        dst = (uint32_t*)d_fv_h + row * (HWP / 2) + g * 8;
    } else {
        long r2 = row - (long)BV * D_;
        src = cam + r2 * HWV2 + g * 16;
        dst = (uint32_t*)d_cam_h + r2 * (HWP / 2) + g * 8;
    }
    float v[16];
#pragma unroll
    for (int q = 0; q < 16; q++) {
        int hw = g * 16 + q;
        v[q] = (hw < HWV2) ? src[q] : 0.f;
    }
    uint32_t wv[8];
#pragma unroll
    for (int w = 0; w < 8; w++) {
        int k = (w & 1) ? (w + 7) : w;
        wv[w] = pack_h2(__float2half_rn(v[k]), __float2half_rn(v[k + 1]));
    }
    *(uint4*)(dst + 0) = make_uint4(wv[0], wv[1], wv[2], wv[3]);
    *(uint4*)(dst + 4) = make_uint4(wv[4], wv[5], wv[6], wv[7]);
}

// =====================================================================
// k_fa_mma: fa[b,o] = max_hw( feat[b,:,hw] . Wt[o,:] ) + bt[o]
// 2 CTAs/SM. FUSED prologue: reads feat_a fp32 directly, converts/permutes
// into resident feat smem (staged through the Wt buffer region).
// Epilogue writes fa as k-permuted fp16 (d_fa_h).
// =====================================================================
#define FEAT_OFF  1024
#define FEAT_ROWB 1056
#define FEAT_SZ   (64 * FEAT_ROWB)
#define WT_OFF    (FEAT_OFF + FEAT_SZ)
#define WT_ROWB   160
#define WT_BUFSZ  (128 * WT_ROWB)
#define FA_SMEM   (WT_OFF + 2 * WT_BUFSZ)   // 109568

__device__ __forceinline__ void fa_load_wt(uint32_t sb, int buf, int otp, int kc, int t) {
#pragma unroll
    for (int r = 0; r < 4; r++) {
        int idx = r * 256 + t;
        int row = idx >> 3, c = idx & 7;
        const __half* src = d_wt_h + ((size_t)(otp * 128 + row) * D_ + kc * 64 + c * 8);
        uint32_t dst = sb + WT_OFF + buf * WT_BUFSZ + row * WT_ROWB + c * 16;
        CP_ASYNC16(dst, src);
    }
}

__global__ void __launch_bounds__(256, 2) k_fa_mma(const float* __restrict__ feat_a,
                                                   const float* __restrict__ bt) {
    extern __shared__ char smem[];
    float* red = (float*)smem;
    uint32_t sb = smem_to_u32(smem);
    const int b = blockIdx.x;
    const int t = threadIdx.x;
    const int w = t >> 5, lane = t & 31;
    const int ot2 = w >> 2, oy = (w >> 1) & 1, hx = w & 1;
    const int j = lane & 3, r4 = lane >> 2;

    // ---- fused conversion prologue: feat_a fp32 -> feat smem fp16 ----
    {
        const float* fsrc = feat_a + (size_t)b * (D_ * HWA2);
        const int hw = t & 63, kseg = t >> 6;
        for (int kc4 = 0; kc4 < 4; kc4++) {
            // stage 128k x 64hw fp32 (32 KB) into Wt buffer region
#pragma unroll
            for (int r = 0; r < 8; r++) {
                int idx = r * 256 + t;                // 2048 x float4
                int row = idx >> 4, c4 = idx & 15;
                CP_ASYNC16(sb + WT_OFF + row * 272 + c4 * 16,
                           fsrc + (size_t)(kc4 * 128 + row) * HWA2 + c4 * 4);
            }
            CP_ASYNC_COMMIT();
            CP_ASYNC_WAIT0();
            __syncthreads();
            const float* stg = (const float*)(smem + WT_OFF);
#pragma unroll
            for (int g = 0; g < 2; g++) {
                int kbase = kseg * 32 + g * 16;
                uint32_t pk[8];
#pragma unroll
                for (int ww = 0; ww < 8; ww++) {
                    int k = (ww & 1) ? (ww + 7) : ww;
                    pk[ww] = pack_h2(__float2half_rn(stg[(kbase + k) * 68 + hw]),
                                     __float2half_rn(stg[(kbase + k + 1) * 68 + hw]));
                }
                char* dst = smem + FEAT_OFF + hw * FEAT_ROWB
                          + (kc4 * 128 + (kseg * 2 + g) * 16) * 2;
                *(uint4*)dst = make_uint4(pk[0], pk[1], pk[2], pk[3]);
                *(uint4*)(dst + 16) = make_uint4(pk[4], pk[5], pk[6], pk[7]);
            }
            __syncthreads();
        }
    }

    fa_load_wt(sb, 0, 0, 0, t);
    CP_ASYNC_COMMIT();

    float acc[2][4][4];
#pragma unroll
    for (int mf = 0; mf < 2; mf++)
#pragma unroll
        for (int nf = 0; nf < 4; nf++)
#pragma unroll
            for (int q = 0; q < 4; q++) acc[mf][nf][q] = 0.f;

    const int oA = ot2 * 64 + oy * 32 + r4;
    const int hwB = hx * 32 + r4;

    for (int it = 0; it < 32; it++) {
        const int otp = it >> 3, kc = it & 7, buf = it & 1;
        if (it + 1 < 32) {
            fa_load_wt(sb, buf ^ 1, (it + 1) >> 3, (it + 1) & 7, t);
            CP_ASYNC_COMMIT();
            CP_ASYNC_WAIT1();
        } else {
            CP_ASYNC_WAIT0();
        }
        __syncthreads();

        const uint32_t wtb = sb + WT_OFF + buf * WT_BUFSZ;
#pragma unroll
        for (int kst = 0; kst < 4; kst++) {
            const int ks = kc * 4 + kst;
            uint32_t a[2][4];
#pragma unroll
            for (int mf = 0; mf < 2; mf++) {
                uint32_t base = wtb + (oA + mf * 16) * WT_ROWB + kst * 32 + j * 8;
                LDS64(a[mf][0], a[mf][2], base);
                LDS64(a[mf][1], a[mf][3], base + 8 * WT_ROWB);
            }
            uint32_t bh[4][2];
#pragma unroll
            for (int nf = 0; nf < 4; nf++) {
                uint32_t bb = sb + FEAT_OFF + (hwB + nf * 8) * FEAT_ROWB + ks * 32 + j * 8;
                LDS64(bh[nf][0], bh[nf][1], bb);
            }
#pragma unroll
            for (int mf = 0; mf < 2; mf++)
#pragma unroll
                for (int nf = 0; nf < 4; nf++)
                    MMA_F16(acc[mf][nf], a[mf], bh[nf]);
        }

        if (kc == 7) {
#pragma unroll
            for (int mf = 0; mf < 2; mf++) {
                float m0 = -3.4e38f, m1 = -3.4e38f;
#pragma unroll
                for (int nf = 0; nf < 4; nf++) {
                    m0 = fmaxf(m0, fmaxf(acc[mf][nf][0], acc[mf][nf][1]));
                    m1 = fmaxf(m1, fmaxf(acc[mf][nf][2], acc[mf][nf][3]));
                }
                m0 = fmaxf(m0, __shfl_xor_sync(0xffffffffu, m0, 1));
                m0 = fmaxf(m0, __shfl_xor_sync(0xffffffffu, m0, 2));
                m1 = fmaxf(m1, __shfl_xor_sync(0xffffffffu, m1, 1));
                m1 = fmaxf(m1, __shfl_xor_sync(0xffffffffu, m1, 2));
                if (j == 0) {
                    red[ot2 * 128 + hx * 64 + oy * 32 + mf * 16 + r4] = m0;
                    red[ot2 * 128 + hx * 64 + oy * 32 + mf * 16 + r4 + 8] = m1;
                }
            }
            __syncthreads();
            if (t < 128) {
                int o2 = t >> 6, ol = t & 63;
                float v = fmaxf(red[o2 * 128 + ol], red[o2 * 128 + 64 + ol]);
                int og = otp * 128 + o2 * 64 + ol;
                v += bt[og];
                int gg = og >> 4, ke = og & 15;
                int kel = ke & ~1;
                int wd = (kel < 8) ? kel : (kel - 7);
                d_fa_h[(size_t)b * D_ + gg * 16 + wd * 2 + (ke & 1)] = __float2half_rn(v);
            }
#pragma unroll
            for (int mf = 0; mf < 2; mf++)
#pragma unroll
                for (int nf = 0; nf < 4; nf++)
#pragma unroll
                    for (int q = 0; q < 4; q++) acc[mf][nf][q] = 0.f;
        }
        __syncthreads();
    }
}

// =====================================================================
// k_g_mma: g[b,c,i] = sum_hw cam*feat_v -> fp16 k-permuted d_g_h
// =====================================================================
#define GC_OFF   1024
#define G_ROWB   416
#define GC_SZ    (32 * G_ROWB)
#define GF_OFF   (GC_OFF + GC_SZ)
#define GF_BUFSZ (128 * G_ROWB)
#define KG_SMEM  (GF_OFF + 2 * GF_BUFSZ)

__device__ __forceinline__ void g_load_fv(uint32_t sb, int buf, int b, int ic, int t) {
#pragma unroll
    for (int r = 0; r < 13; r++) {
        int idx = r * 256 + t;
        int row = idx / 26, c = idx % 26;
        const __half* src = d_fv_h + ((size_t)(b * D_) + ic * 128 + row) * HWP + c * 8;
        uint32_t dst = sb + GF_OFF + buf * GF_BUFSZ + row * G_ROWB + c * 16;
        CP_ASYNC16(dst, src);
    }
}

__global__ void __launch_bounds__(256, 1) k_g_mma() {
    extern __shared__ char smem[];
    uint32_t sb = smem_to_u32(smem);
    const int b = blockIdx.x;
    const int t = threadIdx.x;
    const int w = t >> 5, lane = t & 31;
    const int my = w & 1, ix = w >> 1;
    const int j = lane & 3, r4 = lane >> 2;

#pragma unroll
    for (int r = 0; r < 4; r++) {
        int idx = r * 256 + t;
        if (idx < 832) {
            int row = idx / 26, c = idx % 26;
            const __half* src = d_cam_h + ((size_t)(b * CLS_) + row) * HWP + c * 8;
            CP_ASYNC16(sb + GC_OFF + row * G_ROWB + c * 16, src);
        }
    }
    g_load_fv(sb, 0, b, 0, t);
    CP_ASYNC_COMMIT();

    for (int ic = 0; ic < 4; ic++) {
        const int buf = ic & 1;
        if (ic + 1 < 4) {
            g_load_fv(sb, buf ^ 1, b, ic + 1, t);
            CP_ASYNC_COMMIT();
            CP_ASYNC_WAIT1();
        } else {
            CP_ASYNC_WAIT0();
        }
        __syncthreads();

        float acc[4][4];
#pragma unroll
        for (int nf = 0; nf < 4; nf++)
#pragma unroll
            for (int q = 0; q < 4; q++) acc[nf][q] = 0.f;

        const uint32_t fvb = sb + GF_OFF + buf * GF_BUFSZ;
#pragma unroll
        for (int kst = 0; kst < 13; kst++) {
            uint32_t a[4];
            uint32_t abase = sb + GC_OFF + (my * 16 + r4) * G_ROWB + kst * 32 + j * 8;
            LDS64(a[0], a[2], abase);
            LDS64(a[1], a[3], abase + 8 * G_ROWB);
            uint32_t bh[4][2];
#pragma unroll
            for (int nf = 0; nf < 4; nf++) {
                uint32_t bb = fvb + (ix * 32 + nf * 8 + r4) * G_ROWB + kst * 32 + j * 8;
                LDS64(bh[nf][0], bh[nf][1], bb);
            }
#pragma unroll
            for (int nf = 0; nf < 4; nf++)
                MMA_F16(acc[nf], a, bh[nf]);
        }

        const int c0 = my * 16 + r4;
#pragma unroll
        for (int nf = 0; nf < 4; nf++) {
            int ig = ic * 128 + ix * 32 + nf * 8 + 2 * j;
            int gg = ig >> 4, rm = ig & 15;
            int wd = (rm < 8) ? rm : (rm - 7);
            int word = gg * 8 + wd;
            uint32_t* g0 = (uint32_t*)d_g_h + ((size_t)b * CLS_ + c0) * 256 + word;
            *g0 = pack_h2(__float2half_rn(acc[nf][0]), __float2half_rn(acc[nf][1]));
            uint32_t* g1 = (uint32_t*)d_g_h + ((size_t)b * CLS_ + c0 + 8) * 256 + word;
            *g1 = pack_h2(__float2half_rn(acc[nf][2]), __float2half_rn(acc[nf][3]));
        }
        __syncthreads();
    }
}

// =====================================================================
// camsum (blocks 0..255) + wbs (blocks 256..383)
// =====================================================================
__global__ void k_small(const float* __restrict__ cam, const float* __restrict__ Wv,
                        const float* __restrict__ bs) {
    if (blockIdx.x < 256) {
        int b = blockIdx.x;
        int w = threadIdx.x >> 5, lane = threadIdx.x & 31;
        for (int c = w; c < CLS_; c += 8) {
            const float* p = cam + ((size_t)b * CLS_ + c) * HWV2;
            float s = 0.f;
            for (int k = lane; k < HWV2; k += 32) s += p[k];
#pragma unroll
            for (int off = 16; off; off >>= 1) s += __shfl_xor_sync(0xffffffffu, s, off);
            if (!lane) d_camsum[b * CLS_ + c] = s;
        }
    } else {
        int o = blockIdx.x - 256;
        if (threadIdx.x < 32) {
            int lane = threadIdx.x;
            float s = 0.f;
            for (int d = lane; d < D_; d += 32) s = fmaf(Wv[(size_t)o * D_ + d], bs[d], s);
#pragma unroll
            for (int off = 16; off; off >>= 1) s += __shfl_xor_sync(0xffffffffu, s, off);
            if (!lane) d_wbs[o] = s;
        }
    }
}

// =====================================================================
// Wvs[o,i] = sum_d Wv[o,d]*Ws[d,i]  (fp16 permuted out)
// =====================================================================
__global__ __launch_bounds__(256) void k_wvs(const float* __restrict__ Wv,
                                             const float* __restrict__ Ws) {
    __shared__ float sV[32][65];
    __shared__ float sS[64][65];
    const int oT = blockIdx.x, iT = blockIdx.y;
    const int t = threadIdx.x;
    const int tx = t & 31, ty = t >> 5;

    float acc[4][2];
#pragma unroll
    for (int a = 0; a < 4; a++) { acc[a][0] = 0.f; acc[a][1] = 0.f; }

    for (int k0 = 0; k0 < D_; k0 += 64) {
#pragma unroll
        for (int r = 0; r < 8; r++) {
            int idx = r * 256 + t;
            int o = idx >> 6, kk = idx & 63;
            sV[o][kk] = Wv[(size_t)(oT * 32 + o) * D_ + k0 + kk];
        }
#pragma unroll
        for (int r = 0; r < 16; r++) {
            int idx = r * 256 + t;
            int kk = idx >> 6, i = idx & 63;
            sS[kk][i] = Ws[(size_t)(k0 + kk) * D_ + iT * 64 + i];
        }
        __syncthreads();
#pragma unroll
        for (int kk = 0; kk < 64; kk++) {
            float bb0 = sS[kk][tx], bb1 = sS[kk][tx + 32];
#pragma unroll
            for (int a = 0; a < 4; a++) {
                float av = sV[ty * 4 + a][kk];
                acc[a][0] = fmaf(av, bb0, acc[a][0]);
                acc[a][1] = fmaf(av, bb1, acc[a][1]);
            }
        }
        __syncthreads();
    }
#pragma unroll
    for (int a = 0; a < 4; a++) {
        int o = oT * 32 + ty * 4 + a;
#pragma unroll
        for (int half_ = 0; half_ < 2; half_++) {
            int i = iT * 64 + tx + 32 * half_;
            float v = acc[a][half_];
            int gg = i >> 4;
            int ke = (i & ~1) & 15;
            int wd = (ke < 8) ? ke : (ke - 7);
            d_wvs_h[(size_t)o * D_ + gg * 16 + wd * 2 + (i & 1)] = __float2half_rn(v);
        }
    }
}

// =====================================================================
// shared 128xK GEMM body used by k_tv_mma / k_ta_mma
// =====================================================================
#define TV_B_OFF   0
#define TV_B_ROWB  1056
#define TV_A_OFF   (128 * TV_B_ROWB)
#define TV_A_ROWB  288
#define TV_A_BUFSZ (128 * TV_A_ROWB)
#define TV_SMEM    (TV_A_OFF + 2 * TV_A_BUFSZ)

__device__ __forceinline__ void tv_load_a(uint32_t sb, int buf, const __half* A,
                                          int m0, int kc, int t) {
#pragma unroll
    for (int r = 0; r < 8; r++) {
        int idx = r * 256 + t;
        int row = idx >> 4, c = idx & 15;
        const __half* src = A + ((size_t)(m0 + row) * D_ + kc * 128 + c * 8);
        uint32_t dst = sb + TV_A_OFF + buf * TV_A_BUFSZ + row * TV_A_ROWB + c * 16;
        CP_ASYNC16(dst, src);
    }
}

__device__ __forceinline__ void tv_gemm_body(uint32_t sb, const __half* A, const __half* B,
                                             int m0, int t, float acc[2][8][4]) {
    const int w = t >> 5, lane = t & 31;
    const int mgrp = w & 3, ogrp = w >> 2;
    const int j = lane & 3, r4 = lane >> 2;

#pragma unroll
    for (int r = 0; r < 32; r++) {
        int idx = r * 256 + t;
        int row = idx >> 6, c = idx & 63;
        CP_ASYNC16(sb + TV_B_OFF + row * TV_B_ROWB + c * 16, B + ((size_t)row * D_ + c * 8));
    }
    tv_load_a(sb, 0, A, m0, 0, t);
    CP_ASYNC_COMMIT();

    for (int kc = 0; kc < 4; kc++) {
        const int buf = kc & 1;
        if (kc + 1 < 4) {
            tv_load_a(sb, buf ^ 1, A, m0, kc + 1, t);
            CP_ASYNC_COMMIT();
            CP_ASYNC_WAIT1();
        } else {
            CP_ASYNC_WAIT0();
        }
        __syncthreads();

#pragma unroll
        for (int kst = 0; kst < 8; kst++) {
            const int ks = kc * 8 + kst;
            uint32_t a[2][4];
#pragma unroll
            for (int mf = 0; mf < 2; mf++) {
                uint32_t base = sb + TV_A_OFF + buf * TV_A_BUFSZ
                              + (mgrp * 32 + mf * 16 + r4) * TV_A_ROWB + kst * 32 + j * 8;
                LDS64(a[mf][0], a[mf][2], base);
                LDS64(a[mf][1], a[mf][3], base + 8 * TV_A_ROWB);
            }
            uint32_t bh[8][2];
#pragma unroll
            for (int nf = 0; nf < 8; nf++) {
                uint32_t bb = sb + TV_B_OFF + (ogrp * 64 + nf * 8 + r4) * TV_B_ROWB
                            + ks * 32 + j * 8;
                LDS64(bh[nf][0], bh[nf][1], bb);
            }
#pragma unroll
            for (int mf = 0; mf < 2; mf++)
#pragma unroll
                for (int nf = 0; nf < 8; nf++)
                    MMA_F16(acc[mf][nf], a[mf], bh[nf]);
        }
        __syncthreads();
    }
}

__global__ void __launch_bounds__(256, 1) k_tv_mma(const float* __restrict__ bv) {
    extern __shared__ char smem[];
    uint32_t sb = smem_to_u32(smem);
    const int m0 = blockIdx.x * 128;
    const int t = threadIdx.x;
    const int w = t >> 5, lane = t & 31;
    const int mgrp = w & 3, ogrp = w >> 2;
    const int j = lane & 3, r4 = lane >> 2;

    float acc[2][8][4];
#pragma unroll
    for (int mf = 0; mf < 2; mf++)
#pragma unroll
        for (int nf = 0; nf < 8; nf++)
#pragma unroll
            for (int q = 0; q < 4; q++) acc[mf][nf][q] = 0.f;

    tv_gemm_body(sb, d_g_h, d_wvs_h, m0, t, acc);

#pragma unroll
    for (int mf = 0; mf < 2; mf++) {
        int mr0 = m0 + mgrp * 32 + mf * 16 + r4;
        int mr1 = mr0 + 8;
        float cs0 = d_camsum[mr0], cs1 = d_camsum[mr1];
        float inv0 = 1.f / (cs0 + 1e-10f), inv1 = 1.f / (cs1 + 1e-10f);
#pragma unroll
        for (int nf = 0; nf < 8; nf++) {
            int o0 = ogrp * 64 + nf * 8 + 2 * j;
            float wb0 = d_wbs[o0], wb1 = d_wbs[o0 + 1];
            float bv0 = bv[o0], bv1 = bv[o0 + 1];
            d_tv[(size_t)mr0 * DOUT + o0]     = (acc[mf][nf][0] + wb0 * cs0) * inv0 + bv0;
            d_tv[(size_t)mr0 * DOUT + o0 + 1] = (acc[mf][nf][1] + wb1 * cs0) * inv0 + bv1;
            d_tv[(size_t)mr1 * DOUT + o0]     = (acc[mf][nf][2] + wb0 * cs1) * inv1 + bv0;
            d_tv[(size_t)mr1 * DOUT + o0 + 1] = (acc[mf][nf][3] + wb1 * cs1) * inv1 + bv1;
        }
    }
}

__global__ void __launch_bounds__(256, 1) k_ta_mma(const float* __restrict__ ba) {
    extern __shared__ char smem[];
    uint32_t sb = smem_to_u32(smem);
    const int m0 = blockIdx.x * 128;
    const int t = threadIdx.x;
    const int w = t >> 5, lane = t & 31;
    const int mgrp = w & 3, ogrp = w >> 2;
    const int j = lane & 3, r4 = lane >> 2;

    float acc[2][8][4];
#pragma unroll
    for (int mf = 0; mf < 2; mf++)
#pragma unroll
        for (int nf = 0; nf < 8; nf++)
#pragma unroll
            for (int q = 0; q < 4; q++) acc[mf][nf][q] = 0.f;

    tv_gemm_body(sb, d_fa_h, d_wa_h, m0, t, acc);

#pragma unroll
    for (int mf = 0; mf < 2; mf++) {
        int mr0 = m0 + mgrp * 32 + mf * 16 + r4;
        int mr1 = mr0 + 8;
#pragma unroll
        for (int nf = 0; nf < 8; nf++) {
            int o0 = ogrp * 64 + nf * 8 + 2 * j;
            float ba0 = ba[o0], ba1 = ba[o0 + 1];
            d_ta[(size_t)mr0 * DOUT + o0]     = acc[mf][nf][0] + ba0;
            d_ta[(size_t)mr0 * DOUT + o0 + 1] = acc[mf][nf][1] + ba1;
            d_ta[(size_t)mr1 * DOUT + o0]     = acc[mf][nf][2] + ba0;
            d_ta[(size_t)mr1 * DOUT + o0 + 1] = acc[mf][nf][3] + ba1;
        }
    }
}

// =====================================================================
// losses
// =====================================================================
__global__ void k_loss(const float* __restrict__ pred_a, const float* __restrict__ pred_v,
                       const int* __restrict__ rand_frames, const int* __restrict__ rand_classes,
                       float* __restrict__ out) {
    const int s = blockIdx.x, c = blockIdx.y;
    const int f = threadIdx.x >> 5, lane = threadIdx.x & 31;

    const float pa = pred_a[s * CLS_ + c];
    const bool aa = pa > 0.3f;
    const int num = (int)(pa * (float)FRM);

    const float* tap = d_ta + (size_t)(s * CLS_ + c) * DOUT;
    const float* tvp = d_tv + (size_t)((s * FRM + f) * CLS_ + c) * DOUT;
    const int rf = rand_frames[(s * CLS_ + c) * FRM + f];
    const int rc = rand_classes[(s * CLS_ + c) * FRM + f];
    const float* tvd = d_tv + (size_t)(((s ^ 1) * FRM + rf) * CLS_ + rc) * DOUT;

    float sco = 0.f, sdi = 0.f;
#pragma unroll
    for (int jq = 0; jq < 4; jq++) {
        int o = lane + 32 * jq;
        float t0 = tap[o];
        float d0 = t0 - tvp[o]; sco = fmaf(d0, d0, sco);
        float d1 = t0 - tvd[o]; sdi = fmaf(d1, d1, sdi);
    }
#pragma unroll
    for (int off = 16; off; off >>= 1) {
        sco += __shfl_xor_sync(0xffffffffu, sco, off);
        sdi += __shfl_xor_sync(0xffffffffu, sdi, off);
    }
    if (!lane) {
        float pv = 1.f / (1.f + expf(-pred_v[(s * FRM + f) * CLS_ + c]));
        bool av = pv > 0.3f;
        float mco = (aa && av) ? 1.f : 0.f;
        float mdi = (aa && (f < num)) ? 1.f : 0.f;
        out[((0 * S_ + s) * CLS_ + c) * FRM + f] = sco * (1.f / 128.f) * mco;
        out[((1 * S_ + s) * CLS_ + c) * FRM + f] = sdi * (1.f / 128.f) * mdi;
    }
}

// =====================================================================
extern "C" void kernel_launch(void* const* d_in, const int* in_sizes, int n_in,
                              void* d_out, int out_size) {
    const float* feat_a = (const float*)d_in[0];
    const float* pred_a = (const float*)d_in[1];
    const float* feat_v = (const float*)d_in[2];
    const float* pred_v = (const float*)d_in[3];
    const float* cam    = (const float*)d_in[4];
    const int* rand_frames  = (const int*)d_in[5];
    const int* rand_classes = (const int*)d_in[6];
    const float* Wt = (const float*)d_in[7];
    const float* bt = (const float*)d_in[8];
    const float* Ws = (const float*)d_in[9];
    const float* bs = (const float*)d_in[10];
    const float* Wa = (const float*)d_in[11];
    const float* ba = (const float*)d_in[12];
    const float* Wv = (const float*)d_in[13];
    const float* bv = (const float*)d_in[14];
    float* out = (float*)d_out;

    static int inited = 0;
    static cudaStream_t s2 = 0;
    static cudaEvent_t eF = 0, eJ = 0;
    if (!inited) {
        inited = 1;
        cudaFuncSetAttribute(k_fa_mma, cudaFuncAttributeMaxDynamicSharedMemorySize, FA_SMEM);
        cudaFuncSetAttribute(k_g_mma, cudaFuncAttributeMaxDynamicSharedMemorySize, KG_SMEM);
        cudaFuncSetAttribute(k_tv_mma, cudaFuncAttributeMaxDynamicSharedMemorySize, TV_SMEM);
        cudaFuncSetAttribute(k_ta_mma, cudaFuncAttributeMaxDynamicSharedMemorySize, TV_SMEM);
        if (cudaStreamCreateWithFlags(&s2, cudaStreamNonBlocking) != cudaSuccess) s2 = 0;
        if (s2) {
            if (cudaEventCreateWithFlags(&eF, cudaEventDisableTiming) != cudaSuccess) { eF = 0; }
            if (cudaEventCreateWithFlags(&eJ, cudaEventDisableTiming) != cudaSuccess) { eJ = 0; }
        }
    }
    const bool fork = (s2 != 0) && (eF != 0) && (eJ != 0);
    cudaStream_t vs = fork ? s2 : (cudaStream_t)0;

    if (fork) {
        cudaEventRecord(eF, 0);
        cudaStreamWaitEvent(s2, eF, 0);
    }

    // ---- audio chain (capture/default stream) ----
    k_cvt_w<<<64, 256>>>(Wt, 0);                              // 1
    k_cvt_w<<<16, 256>>>(Wa, 1);                              // 2
    // ---- video chain start (s2) ----
    k_prep_fvcam<<<(BV * D_ + BV * CLS_) / 16, 256, 0, vs>>>(feat_v, cam);  // 3
    // ---- audio main ----
    k_fa_mma<<<BA, 256, FA_SMEM>>>(feat_a, bt);               // 4 <- profiled
    k_ta_mma<<<BA / 128, 256, TV_SMEM>>>(ba);                 // 5

    // ---- video chain rest (s2) ----
    k_small<<<384, 256, 0, vs>>>(cam, Wv, bs);
    k_wvs<<<dim3(4, 8), 256, 0, vs>>>(Wv, Ws);
    k_g_mma<<<BV, 256, KG_SMEM, vs>>>();
    k_tv_mma<<<(BV * CLS_) / 128, 256, TV_SMEM, vs>>>(bv);

    if (fork) {
        cudaEventRecord(eJ, s2);
        cudaStreamWaitEvent(0, eJ, 0);
    }

    k_loss<<<dim3(S_, CLS_), 256>>>(pred_a, pred_v, rand_frames, rand_classes, out);
}

// round 10
// speedup vs baseline: 5.6270x; 1.1754x over previous
#include <cuda_runtime.h>
#include <cuda_fp16.h>
#include <math.h>
#include <cstdint>

// Problem constants
#define S_   32
#define FRM  8
#define CLS_ 32
#define D_   512
#define HWA2 64      // 8*8
#define HWV2 196     // 14*14
#define HWP  208     // padded to 13*16
#define DOUT 128
#define BA   (S_*CLS_)   // 1024
#define BV   (S_*FRM)    // 256

// ---------------- device scratch ----------------
__device__ float d_ta[BA * DOUT];
__device__ float d_camsum[BV * CLS_];
__device__ float d_tv[BV * CLS_ * DOUT];
__device__ float d_wbs[DOUT];
// fp16 permuted buffers
__device__ __half d_wt_h[D_ * D_];                      // [o][kperm]
__device__ __half d_wa_h[DOUT * D_];                    // [o][kperm]
__device__ __half d_fa_h[BA * D_];                      // [b][kperm(o)]
__device__ __half d_fv_h[(size_t)BV * D_ * HWP];        // [b][i][hwperm]
__device__ __half d_cam_h[(size_t)BV * CLS_ * HWP];     // [b][c][hwperm]
__device__ __half d_g_h[(size_t)BV * CLS_ * D_];        // [m][kperm]
__device__ __half d_wvs_h[DOUT * D_];                   // [o][kperm]

// =============== small asm helpers ===============
__device__ __forceinline__ uint32_t smem_to_u32(const void* p) {
    uint32_t a;
    asm("{ .reg .u64 t; cvta.to.shared.u64 t, %1; cvt.u32.u64 %0, t; }" : "=r"(a) : "l"(p));
    return a;
}
#define CP_ASYNC16(sm, g) \
    asm volatile("cp.async.cg.shared.global [%0], [%1], 16;" :: "r"((uint32_t)(sm)), "l"(g) : "memory")
#define CP_ASYNC_COMMIT() asm volatile("cp.async.commit_group;" ::: "memory")
#define CP_ASYNC_WAIT0()  asm volatile("cp.async.wait_group 0;" ::: "memory")
#define CP_ASYNC_WAIT1()  asm volatile("cp.async.wait_group 1;" ::: "memory")

#define LDS64(r0, r1, addr) \
    asm volatile("ld.shared.v2.b32 {%0,%1}, [%2];" : "=r"(r0), "=r"(r1) : "r"((uint32_t)(addr)))

#define MMA_F16(d, a, b) \
    asm volatile("mma.sync.aligned.m16n8k16.row.col.f32.f16.f16.f32 " \
        "{%0,%1,%2,%3}, {%4,%5,%6,%7}, {%8,%9}, {%0,%1,%2,%3};" \
        : "+f"((d)[0]), "+f"((d)[1]), "+f"((d)[2]), "+f"((d)[3]) \
        : "r"((a)[0]), "r"((a)[1]), "r"((a)[2]), "r"((a)[3]), "r"((b)[0]), "r"((b)[1]))

__device__ __forceinline__ uint32_t pack_h2(__half a, __half b) {
    __half2 p = __halves2half2(a, b);
    return *(uint32_t*)&p;
}

// k-permutation within a 16-group (m16n8k16 frag layout):
// word w (fp16 pair): w even -> k = w ; w odd -> k = w + 7.
// inverse (even k e): w = (e < 8) ? e : e - 7.

// =====================================================================
// Prep 1: W fp32 -> permuted fp16 (which=0 -> d_wt_h, which=1 -> d_wa_h)
// =====================================================================
__global__ __launch_bounds__(256) void k_cvt_w(const float* __restrict__ W, int which) {
    int idx = blockIdx.x * 256 + threadIdx.x;
    int o = idx >> 5, g = idx & 31;
    const float* src = W + (size_t)o * D_ + g * 16;
    float v[16];
#pragma unroll
    for (int q = 0; q < 4; q++) {
        float4 f = *(const float4*)(src + q * 4);
        v[q * 4 + 0] = f.x; v[q * 4 + 1] = f.y; v[q * 4 + 2] = f.z; v[q * 4 + 3] = f.w;
    }
    uint32_t hw_[8];
#pragma unroll
    for (int w = 0; w < 8; w++) {
        int k = (w & 1) ? (w + 7) : w;
        hw_[w] = pack_h2(__float2half_rn(v[k]), __float2half_rn(v[k + 1]));
    }
    uint32_t* dh = (uint32_t*)(which ? d_wa_h : d_wt_h) + (size_t)o * 256 + g * 8;
    *(uint4*)(dh + 0) = make_uint4(hw_[0], hw_[1], hw_[2], hw_[3]);
    *(uint4*)(dh + 4) = make_uint4(hw_[4], hw_[5], hw_[6], hw_[7]);
}

// =====================================================================
// Prep (video): feat_v rows then cam rows -> fp16 hw-permuted (pad 208)
// float4 vector loads (rows = 49 exact float4s). Cam rows also produce
// camsum via intra-halfwarp shfl reduction.
// =====================================================================
__global__ __launch_bounds__(256) void k_prep_fvcam(const float* __restrict__ feat_v,
                                                    const float* __restrict__ cam) {
    const int t = threadIdx.x;
    const int g = t & 15, rloc = t >> 4;
    const long row = (long)blockIdx.x * 16 + rloc;
    const bool is_cam = (row >= (long)BV * D_);
    long r2 = 0;
    const float* src;
    uint32_t* dst;
    if (!is_cam) {
        src = feat_v + row * HWV2;
        dst = (uint32_t*)d_fv_h + row * (HWP / 2) + g * 8;
    } else {
        r2 = row - (long)BV * D_;
        src = cam + r2 * HWV2;
        dst = (uint32_t*)d_cam_h + r2 * (HWP / 2) + g * 8;
    }
    const bool active = (g < 13);
    float v[16];
#pragma unroll
    for (int qq = 0; qq < 4; qq++) {
        int idx4 = g * 4 + qq;
        if (active && idx4 < 49) {
            float4 f = *(const float4*)(src + idx4 * 4);
            v[qq * 4 + 0] = f.x; v[qq * 4 + 1] = f.y;
            v[qq * 4 + 2] = f.z; v[qq * 4 + 3] = f.w;
        } else {
            v[qq * 4 + 0] = 0.f; v[qq * 4 + 1] = 0.f;
            v[qq * 4 + 2] = 0.f; v[qq * 4 + 3] = 0.f;
        }
    }
    if (active) {
        uint32_t wv[8];
#pragma unroll
        for (int w = 0; w < 8; w++) {
            int k = (w & 1) ? (w + 7) : w;
            wv[w] = pack_h2(__float2half_rn(v[k]), __float2half_rn(v[k + 1]));
        }
        *(uint4*)(dst + 0) = make_uint4(wv[0], wv[1], wv[2], wv[3]);
        *(uint4*)(dst + 4) = make_uint4(wv[4], wv[5], wv[6], wv[7]);
    }
    if (is_cam) {
        float s = 0.f;
#pragma unroll
        for (int q = 0; q < 16; q++) s += v[q];
        s += __shfl_xor_sync(0xffffffffu, s, 1);
        s += __shfl_xor_sync(0xffffffffu, s, 2);
        s += __shfl_xor_sync(0xffffffffu, s, 4);
        s += __shfl_xor_sync(0xffffffffu, s, 8);
        if (g == 0) d_camsum[r2] = s;
    }
}

// =====================================================================
// k_fa_mma: fa[b,o] = max_hw( feat[b,:,hw] . Wt[o,:] ) + bt[o]
// 2 CTAs/SM. Pipelined fused prologue: 8 sub-chunks of 64 k-rows,
// double-buffered through the two Wt buffer slots.
// Epilogue writes fa as k-permuted fp16 (d_fa_h).
// =====================================================================
#define FEAT_OFF  1024
#define FEAT_ROWB 1056
#define FEAT_SZ   (64 * FEAT_ROWB)
#define WT_OFF    (FEAT_OFF + FEAT_SZ)
#define WT_ROWB   160
#define WT_BUFSZ  (128 * WT_ROWB)
#define FA_SMEM   (WT_OFF + 2 * WT_BUFSZ)   // 109568

__device__ __forceinline__ void fa_load_wt(uint32_t sb, int buf, int otp, int kc, int t) {
#pragma unroll
    for (int r = 0; r < 4; r++) {
        int idx = r * 256 + t;
        int row = idx >> 3, c = idx & 7;
        const __half* src = d_wt_h + ((size_t)(otp * 128 + row) * D_ + kc * 64 + c * 8);
        uint32_t dst = sb + WT_OFF + buf * WT_BUFSZ + row * WT_ROWB + c * 16;
        CP_ASYNC16(dst, src);
    }
}

__global__ void __launch_bounds__(256, 2) k_fa_mma(const float* __restrict__ feat_a,
                                                   const float* __restrict__ bt) {
    extern __shared__ char smem[];
    float* red = (float*)smem;
    uint32_t sb = smem_to_u32(smem);
    const int b = blockIdx.x;
    const int t = threadIdx.x;
    const int w = t >> 5, lane = t & 31;
    const int ot2 = w >> 2, oy = (w >> 1) & 1, hx = w & 1;
    const int j = lane & 3, r4 = lane >> 2;

    // ---- pipelined fused prologue: feat_a fp32 -> feat smem fp16 ----
    {
        const float* fsrc = feat_a + (size_t)b * (D_ * HWA2);
        const int hw = t & 63, kseg = t >> 6;
        // stage chunk 0 (64 k-rows x 64 hw fp32 = 16 KB)
#pragma unroll
        for (int r = 0; r < 4; r++) {
            int idx = r * 256 + t;
            int row = idx >> 4, c4 = idx & 15;
            CP_ASYNC16(sb + WT_OFF + row * 272 + c4 * 16,
                       fsrc + (size_t)row * HWA2 + c4 * 4);
        }
        CP_ASYNC_COMMIT();
        for (int c = 0; c < 8; c++) {
            if (c + 1 < 8) {
                uint32_t bb = sb + WT_OFF + ((c + 1) & 1) * WT_BUFSZ;
#pragma unroll
                for (int r = 0; r < 4; r++) {
                    int idx = r * 256 + t;
                    int row = idx >> 4, c4 = idx & 15;
                    CP_ASYNC16(bb + row * 272 + c4 * 16,
                               fsrc + (size_t)((c + 1) * 64 + row) * HWA2 + c4 * 4);
                }
                CP_ASYNC_COMMIT();
                CP_ASYNC_WAIT1();
            } else {
                CP_ASYNC_WAIT0();
            }
            __syncthreads();
            const float* stg = (const float*)(smem + WT_OFF + (c & 1) * WT_BUFSZ);
            const int kbase = kseg * 16;
            uint32_t pk[8];
#pragma unroll
            for (int ww = 0; ww < 8; ww++) {
                int k = (ww & 1) ? (ww + 7) : ww;
                pk[ww] = pack_h2(__float2half_rn(stg[(kbase + k) * 68 + hw]),
                                 __float2half_rn(stg[(kbase + k + 1) * 68 + hw]));
            }
            char* dst = smem + FEAT_OFF + hw * FEAT_ROWB + (c * 128 + kseg * 32);
            *(uint4*)dst = make_uint4(pk[0], pk[1], pk[2], pk[3]);
            *(uint4*)(dst + 16) = make_uint4(pk[4], pk[5], pk[6], pk[7]);
            __syncthreads();
        }
    }

    fa_load_wt(sb, 0, 0, 0, t);
    CP_ASYNC_COMMIT();

    float acc[2][4][4];
#pragma unroll
    for (int mf = 0; mf < 2; mf++)
#pragma unroll
        for (int nf = 0; nf < 4; nf++)
#pragma unroll
            for (int q = 0; q < 4; q++) acc[mf][nf][q] = 0.f;

    const int oA = ot2 * 64 + oy * 32 + r4;
    const int hwB = hx * 32 + r4;

    for (int it = 0; it < 32; it++) {
        const int otp = it >> 3, kc = it & 7, buf = it & 1;
        if (it + 1 < 32) {
            fa_load_wt(sb, buf ^ 1, (it + 1) >> 3, (it + 1) & 7, t);
            CP_ASYNC_COMMIT();
            CP_ASYNC_WAIT1();
        } else {
            CP_ASYNC_WAIT0();
        }
        __syncthreads();

        const uint32_t wtb = sb + WT_OFF + buf * WT_BUFSZ;
#pragma unroll
        for (int kst = 0; kst < 4; kst++) {
            const int ks = kc * 4 + kst;
            uint32_t a[2][4];
#pragma unroll
            for (int mf = 0; mf < 2; mf++) {
                uint32_t base = wtb + (oA + mf * 16) * WT_ROWB + kst * 32 + j * 8;
                LDS64(a[mf][0], a[mf][2], base);
                LDS64(a[mf][1], a[mf][3], base + 8 * WT_ROWB);
            }
            uint32_t bh[4][2];
#pragma unroll
            for (int nf = 0; nf < 4; nf++) {
                uint32_t bb = sb + FEAT_OFF + (hwB + nf * 8) * FEAT_ROWB + ks * 32 + j * 8;
                LDS64(bh[nf][0], bh[nf][1], bb);
            }
#pragma unroll
            for (int mf = 0; mf < 2; mf++)
#pragma unroll
                for (int nf = 0; nf < 4; nf++)
                    MMA_F16(acc[mf][nf], a[mf], bh[nf]);
        }

        if (kc == 7) {
#pragma unroll
            for (int mf = 0; mf < 2; mf++) {
                float m0 = -3.4e38f, m1 = -3.4e38f;
#pragma unroll
                for (int nf = 0; nf < 4; nf++) {
                    m0 = fmaxf(m0, fmaxf(acc[mf][nf][0], acc[mf][nf][1]));
                    m1 = fmaxf(m1, fmaxf(acc[mf][nf][2], acc[mf][nf][3]));
                }
                m0 = fmaxf(m0, __shfl_xor_sync(0xffffffffu, m0, 1));
                m0 = fmaxf(m0, __shfl_xor_sync(0xffffffffu, m0, 2));
                m1 = fmaxf(m1, __shfl_xor_sync(0xffffffffu, m1, 1));
                m1 = fmaxf(m1, __shfl_xor_sync(0xffffffffu, m1, 2));
                if (j == 0) {
                    red[ot2 * 128 + hx * 64 + oy * 32 + mf * 16 + r4] = m0;
                    red[ot2 * 128 + hx * 64 + oy * 32 + mf * 16 + r4 + 8] = m1;
                }
            }
            __syncthreads();
            if (t < 128) {
                int o2 = t >> 6, ol = t & 63;
                float v = fmaxf(red[o2 * 128 + ol], red[o2 * 128 + 64 + ol]);
                int og = otp * 128 + o2 * 64 + ol;
                v += bt[og];
                int gg = og >> 4, ke = og & 15;
                int kel = ke & ~1;
                int wd = (kel < 8) ? kel : (kel - 7);
                d_fa_h[(size_t)b * D_ + gg * 16 + wd * 2 + (ke & 1)] = __float2half_rn(v);
            }
#pragma unroll
            for (int mf = 0; mf < 2; mf++)
#pragma unroll
                for (int nf = 0; nf < 4; nf++)
#pragma unroll
                    for (int q = 0; q < 4; q++) acc[mf][nf][q] = 0.f;
        }
        __syncthreads();
    }
}

// =====================================================================
// k_g_mma: g[b,c,i] = sum_hw cam*feat_v -> fp16 k-permuted d_g_h
// =====================================================================
#define GC_OFF   1024
#define G_ROWB   416
#define GC_SZ    (32 * G_ROWB)
#define GF_OFF   (GC_OFF + GC_SZ)
#define GF_BUFSZ (128 * G_ROWB)
#define KG_SMEM  (GF_OFF + 2 * GF_BUFSZ)

__device__ __forceinline__ void g_load_fv(uint32_t sb, int buf, int b, int ic, int t) {
#pragma unroll
    for (int r = 0; r < 13; r++) {
        int idx = r * 256 + t;
        int row = idx / 26, c = idx % 26;
        const __half* src = d_fv_h + ((size_t)(b * D_) + ic * 128 + row) * HWP + c * 8;
        uint32_t dst = sb + GF_OFF + buf * GF_BUFSZ + row * G_ROWB + c * 16;
        CP_ASYNC16(dst, src);
    }
}

__global__ void __launch_bounds__(256, 1) k_g_mma() {
    extern __shared__ char smem[];
    uint32_t sb = smem_to_u32(smem);
    const int b = blockIdx.x;
    const int t = threadIdx.x;
    const int w = t >> 5, lane = t & 31;
    const int my = w & 1, ix = w >> 1;
    const int j = lane & 3, r4 = lane >> 2;

#pragma unroll
    for (int r = 0; r < 4; r++) {
        int idx = r * 256 + t;
        if (idx < 832) {
            int row = idx / 26, c = idx % 26;
            const __half* src = d_cam_h + ((size_t)(b * CLS_) + row) * HWP + c * 8;
            CP_ASYNC16(sb + GC_OFF + row * G_ROWB + c * 16, src);
        }
    }
    g_load_fv(sb, 0, b, 0, t);
    CP_ASYNC_COMMIT();

    for (int ic = 0; ic < 4; ic++) {
        const int buf = ic & 1;
        if (ic + 1 < 4) {
            g_load_fv(sb, buf ^ 1, b, ic + 1, t);
            CP_ASYNC_COMMIT();
            CP_ASYNC_WAIT1();
        } else {
            CP_ASYNC_WAIT0();
        }
        __syncthreads();

        float acc[4][4];
#pragma unroll
        for (int nf = 0; nf < 4; nf++)
#pragma unroll
            for (int q = 0; q < 4; q++) acc[nf][q] = 0.f;

        const uint32_t fvb = sb + GF_OFF + buf * GF_BUFSZ;
#pragma unroll
        for (int kst = 0; kst < 13; kst++) {
            uint32_t a[4];
            uint32_t abase = sb + GC_OFF + (my * 16 + r4) * G_ROWB + kst * 32 + j * 8;
            LDS64(a[0], a[2], abase);
            LDS64(a[1], a[3], abase + 8 * G_ROWB);
            uint32_t bh[4][2];
#pragma unroll
            for (int nf = 0; nf < 4; nf++) {
                uint32_t bb = fvb + (ix * 32 + nf * 8 + r4) * G_ROWB + kst * 32 + j * 8;
                LDS64(bh[nf][0], bh[nf][1], bb);
            }
#pragma unroll
            for (int nf = 0; nf < 4; nf++)
                MMA_F16(acc[nf], a, bh[nf]);
        }

        const int c0 = my * 16 + r4;
#pragma unroll
        for (int nf = 0; nf < 4; nf++) {
            int ig = ic * 128 + ix * 32 + nf * 8 + 2 * j;
            int gg = ig >> 4, rm = ig & 15;
            int wd = (rm < 8) ? rm : (rm - 7);
            int word = gg * 8 + wd;
            uint32_t* g0 = (uint32_t*)d_g_h + ((size_t)b * CLS_ + c0) * 256 + word;
            *g0 = pack_h2(__float2half_rn(acc[nf][0]), __float2half_rn(acc[nf][1]));
            uint32_t* g1 = (uint32_t*)d_g_h + ((size_t)b * CLS_ + c0 + 8) * 256 + word;
            *g1 = pack_h2(__float2half_rn(acc[nf][2]), __float2half_rn(acc[nf][3]));
        }
        __syncthreads();
    }
}

// =====================================================================
// wbs[o] = Wv[o,:].bs   (grid 128 x 32 threads)
// =====================================================================
__global__ void k_wbs(const float* __restrict__ Wv, const float* __restrict__ bs) {
    int o = blockIdx.x, lane = threadIdx.x;
    float s = 0.f;
    for (int d = lane; d < D_; d += 32) s = fmaf(Wv[(size_t)o * D_ + d], bs[d], s);
#pragma unroll
    for (int off = 16; off; off >>= 1) s += __shfl_xor_sync(0xffffffffu, s, off);
    if (!lane) d_wbs[o] = s;
}

// =====================================================================
// Wvs[o,i] = sum_d Wv[o,d]*Ws[d,i]  (fp16 permuted out)
// =====================================================================
__global__ __launch_bounds__(256) void k_wvs(const float* __restrict__ Wv,
                                             const float* __restrict__ Ws) {
    __shared__ float sV[32][65];
    __shared__ float sS[64][65];
    const int oT = blockIdx.x, iT = blockIdx.y;
    const int t = threadIdx.x;
    const int tx = t & 31, ty = t >> 5;

    float acc[4][2];
#pragma unroll
    for (int a = 0; a < 4; a++) { acc[a][0] = 0.f; acc[a][1] = 0.f; }

    for (int k0 = 0; k0 < D_; k0 += 64) {
#pragma unroll
        for (int r = 0; r < 8; r++) {
            int idx = r * 256 + t;
            int o = idx >> 6, kk = idx & 63;
            sV[o][kk] = Wv[(size_t)(oT * 32 + o) * D_ + k0 + kk];
        }
#pragma unroll
        for (int r = 0; r < 16; r++) {
            int idx = r * 256 + t;
            int kk = idx >> 6, i = idx & 63;
            sS[kk][i] = Ws[(size_t)(k0 + kk) * D_ + iT * 64 + i];
        }
        __syncthreads();
#pragma unroll
        for (int kk = 0; kk < 64; kk++) {
            float bb0 = sS[kk][tx], bb1 = sS[kk][tx + 32];
#pragma unroll
            for (int a = 0; a < 4; a++) {
                float av = sV[ty * 4 + a][kk];
                acc[a][0] = fmaf(av, bb0, acc[a][0]);
                acc[a][1] = fmaf(av, bb1, acc[a][1]);
            }
        }
        __syncthreads();
    }
#pragma unroll
    for (int a = 0; a < 4; a++) {
        int o = oT * 32 + ty * 4 + a;
#pragma unroll
        for (int half_ = 0; half_ < 2; half_++) {
            int i = iT * 64 + tx + 32 * half_;
            float v = acc[a][half_];
            int gg = i >> 4;
            int ke = (i & ~1) & 15;
            int wd = (ke < 8) ? ke : (ke - 7);
            d_wvs_h[(size_t)o * D_ + gg * 16 + wd * 2 + (i & 1)] = __float2half_rn(v);
        }
    }
}

// =====================================================================
// shared 128xK GEMM body used by k_tv_mma / k_ta_mma
// =====================================================================
#define TV_B_OFF   0
#define TV_B_ROWB  1056
#define TV_A_OFF   (128 * TV_B_ROWB)
#define TV_A_ROWB  288
#define TV_A_BUFSZ (128 * TV_A_ROWB)
#define TV_SMEM    (TV_A_OFF + 2 * TV_A_BUFSZ)

__device__ __forceinline__ void tv_load_a(uint32_t sb, int buf, const __half* A,
                                          int m0, int kc, int t) {
#pragma unroll
    for (int r = 0; r < 8; r++) {
        int idx = r * 256 + t;
        int row = idx >> 4, c = idx & 15;
        const __half* src = A + ((size_t)(m0 + row) * D_ + kc * 128 + c * 8);
        uint32_t dst = sb + TV_A_OFF + buf * TV_A_BUFSZ + row * TV_A_ROWB + c * 16;
        CP_ASYNC16(dst, src);
    }
}

__device__ __forceinline__ void tv_gemm_body(uint32_t sb, const __half* A, const __half* B,
                                             int m0, int t, float acc[2][8][4]) {
    const int w = t >> 5, lane = t & 31;
    const int mgrp = w & 3, ogrp = w >> 2;
    const int j = lane & 3, r4 = lane >> 2;

#pragma unroll
    for (int r = 0; r < 32; r++) {
        int idx = r * 256 + t;
        int row = idx >> 6, c = idx & 63;
        CP_ASYNC16(sb + TV_B_OFF + row * TV_B_ROWB + c * 16, B + ((size_t)row * D_ + c * 8));
    }
    tv_load_a(sb, 0, A, m0, 0, t);
    CP_ASYNC_COMMIT();

    for (int kc = 0; kc < 4; kc++) {
        const int buf = kc & 1;
        if (kc + 1 < 4) {
            tv_load_a(sb, buf ^ 1, A, m0, kc + 1, t);
            CP_ASYNC_COMMIT();
            CP_ASYNC_WAIT1();
        } else {
            CP_ASYNC_WAIT0();
        }
        __syncthreads();

#pragma unroll
        for (int kst = 0; kst < 8; kst++) {
            const int ks = kc * 8 + kst;
            uint32_t a[2][4];
#pragma unroll
            for (int mf = 0; mf < 2; mf++) {
                uint32_t base = sb + TV_A_OFF + buf * TV_A_BUFSZ
                              + (mgrp * 32 + mf * 16 + r4) * TV_A_ROWB + kst * 32 + j * 8;
                LDS64(a[mf][0], a[mf][2], base);
                LDS64(a[mf][1], a[mf][3], base + 8 * TV_A_ROWB);
            }
            uint32_t bh[8][2];
#pragma unroll
            for (int nf = 0; nf < 8; nf++) {
                uint32_t bb = sb + TV_B_OFF + (ogrp * 64 + nf * 8 + r4) * TV_B_ROWB
                            + ks * 32 + j * 8;
                LDS64(bh[nf][0], bh[nf][1], bb);
            }
#pragma unroll
            for (int mf = 0; mf < 2; mf++)
#pragma unroll
                for (int nf = 0; nf < 8; nf++)
                    MMA_F16(acc[mf][nf], a[mf], bh[nf]);
        }
        __syncthreads();
    }
}

__global__ void __launch_bounds__(256, 1) k_tv_mma(const float* __restrict__ bv) {
    extern __shared__ char smem[];
    uint32_t sb = smem_to_u32(smem);
    const int m0 = blockIdx.x * 128;
    const int t = threadIdx.x;
    const int w = t >> 5, lane = t & 31;
    const int mgrp = w & 3, ogrp = w >> 2;
    const int j = lane & 3, r4 = lane >> 2;

    float acc[2][8][4];
#pragma unroll
    for (int mf = 0; mf < 2; mf++)
#pragma unroll
        for (int nf = 0; nf < 8; nf++)
#pragma unroll
            for (int q = 0; q < 4; q++) acc[mf][nf][q] = 0.f;

    tv_gemm_body(sb, d_g_h, d_wvs_h, m0, t, acc);

#pragma unroll
    for (int mf = 0; mf < 2; mf++) {
        int mr0 = m0 + mgrp * 32 + mf * 16 + r4;
        int mr1 = mr0 + 8;
        float cs0 = d_camsum[mr0], cs1 = d_camsum[mr1];
        float inv0 = 1.f / (cs0 + 1e-10f), inv1 = 1.f / (cs1 + 1e-10f);
#pragma unroll
        for (int nf = 0; nf < 8; nf++) {
            int o0 = ogrp * 64 + nf * 8 + 2 * j;
            float wb0 = d_wbs[o0], wb1 = d_wbs[o0 + 1];
            float bv0 = bv[o0], bv1 = bv[o0 + 1];
            d_tv[(size_t)mr0 * DOUT + o0]     = (acc[mf][nf][0] + wb0 * cs0) * inv0 + bv0;
            d_tv[(size_t)mr0 * DOUT + o0 + 1] = (acc[mf][nf][1] + wb1 * cs0) * inv0 + bv1;
            d_tv[(size_t)mr1 * DOUT + o0]     = (acc[mf][nf][2] + wb0 * cs1) * inv1 + bv0;
            d_tv[(size_t)mr1 * DOUT + o0 + 1] = (acc[mf][nf][3] + wb1 * cs1) * inv1 + bv1;
        }
    }
}

__global__ void __launch_bounds__(256, 1) k_ta_mma(const float* __restrict__ ba) {
    extern __shared__ char smem[];
    uint32_t sb = smem_to_u32(smem);
    const int m0 = blockIdx.x * 128;
    const int t = threadIdx.x;
    const int w = t >> 5, lane = t & 31;
    const int mgrp = w & 3, ogrp = w >> 2;
    const int j = lane & 3, r4 = lane >> 2;

    float acc[2][8][4];
#pragma unroll
    for (int mf = 0; mf < 2; mf++)
#pragma unroll
        for (int nf = 0; nf < 8; nf++)
#pragma unroll
            for (int q = 0; q < 4; q++) acc[mf][nf][q] = 0.f;

    tv_gemm_body(sb, d_fa_h, d_wa_h, m0, t, acc);

#pragma unroll
    for (int mf = 0; mf < 2; mf++) {
        int mr0 = m0 + mgrp * 32 + mf * 16 + r4;
        int mr1 = mr0 + 8;
#pragma unroll
        for (int nf = 0; nf < 8; nf++) {
            int o0 = ogrp * 64 + nf * 8 + 2 * j;
            float ba0 = ba[o0], ba1 = ba[o0 + 1];
            d_ta[(size_t)mr0 * DOUT + o0]     = acc[mf][nf][0] + ba0;
            d_ta[(size_t)mr0 * DOUT + o0 + 1] = acc[mf][nf][1] + ba1;
            d_ta[(size_t)mr1 * DOUT + o0]     = acc[mf][nf][2] + ba0;
            d_ta[(size_t)mr1 * DOUT + o0 + 1] = acc[mf][nf][3] + ba1;
        }
    }
}

// =====================================================================
// losses
// =====================================================================
__global__ void k_loss(const float* __restrict__ pred_a, const float* __restrict__ pred_v,
                       const int* __restrict__ rand_frames, const int* __restrict__ rand_classes,
                       float* __restrict__ out) {
    const int s = blockIdx.x, c = blockIdx.y;
    const int f = threadIdx.x >> 5, lane = threadIdx.x & 31;

    const float pa = pred_a[s * CLS_ + c];
    const bool aa = pa > 0.3f;
    const int num = (int)(pa * (float)FRM);

    const float* tap = d_ta + (size_t)(s * CLS_ + c) * DOUT;
    const float* tvp = d_tv + (size_t)((s * FRM + f) * CLS_ + c) * DOUT;
    const int rf = rand_frames[(s * CLS_ + c) * FRM + f];
    const int rc = rand_classes[(s * CLS_ + c) * FRM + f];
    const float* tvd = d_tv + (size_t)(((s ^ 1) * FRM + rf) * CLS_ + rc) * DOUT;

    float sco = 0.f, sdi = 0.f;
#pragma unroll
    for (int jq = 0; jq < 4; jq++) {
        int o = lane + 32 * jq;
        float t0 = tap[o];
        float d0 = t0 - tvp[o]; sco = fmaf(d0, d0, sco);
        float d1 = t0 - tvd[o]; sdi = fmaf(d1, d1, sdi);
    }
#pragma unroll
    for (int off = 16; off; off >>= 1) {
        sco += __shfl_xor_sync(0xffffffffu, sco, off);
        sdi += __shfl_xor_sync(0xffffffffu, sdi, off);
    }
    if (!lane) {
        float pv = 1.f / (1.f + expf(-pred_v[(s * FRM + f) * CLS_ + c]));
        bool av = pv > 0.3f;
        float mco = (aa && av) ? 1.f : 0.f;
        float mdi = (aa && (f < num)) ? 1.f : 0.f;
        out[((0 * S_ + s) * CLS_ + c) * FRM + f] = sco * (1.f / 128.f) * mco;
        out[((1 * S_ + s) * CLS_ + c) * FRM + f] = sdi * (1.f / 128.f) * mdi;
    }
}

// =====================================================================
extern "C" void kernel_launch(void* const* d_in, const int* in_sizes, int n_in,
                              void* d_out, int out_size) {
    const float* feat_a = (const float*)d_in[0];
    const float* pred_a = (const float*)d_in[1];
    const float* feat_v = (const float*)d_in[2];
    const float* pred_v = (const float*)d_in[3];
    const float* cam    = (const float*)d_in[4];
    const int* rand_frames  = (const int*)d_in[5];
    const int* rand_classes = (const int*)d_in[6];
    const float* Wt = (const float*)d_in[7];
    const float* bt = (const float*)d_in[8];
    const float* Ws = (const float*)d_in[9];
    const float* bs = (const float*)d_in[10];
    const float* Wa = (const float*)d_in[11];
    const float* ba = (const float*)d_in[12];
    const float* Wv = (const float*)d_in[13];
    const float* bv = (const float*)d_in[14];
    float* out = (float*)d_out;

    static int inited = 0;
    static cudaStream_t s2 = 0;
    static cudaEvent_t eF = 0, eJ = 0;
    if (!inited) {
        inited = 1;
        cudaFuncSetAttribute(k_fa_mma, cudaFuncAttributeMaxDynamicSharedMemorySize, FA_SMEM);
        cudaFuncSetAttribute(k_g_mma, cudaFuncAttributeMaxDynamicSharedMemorySize, KG_SMEM);
        cudaFuncSetAttribute(k_tv_mma, cudaFuncAttributeMaxDynamicSharedMemorySize, TV_SMEM);
        cudaFuncSetAttribute(k_ta_mma, cudaFuncAttributeMaxDynamicSharedMemorySize, TV_SMEM);
        if (cudaStreamCreateWithFlags(&s2, cudaStreamNonBlocking) != cudaSuccess) s2 = 0;
        if (s2) {
            if (cudaEventCreateWithFlags(&eF, cudaEventDisableTiming) != cudaSuccess) { eF = 0; }
            if (cudaEventCreateWithFlags(&eJ, cudaEventDisableTiming) != cudaSuccess) { eJ = 0; }
        }
    }
    const bool fork = (s2 != 0) && (eF != 0) && (eJ != 0);
    cudaStream_t vs = fork ? s2 : (cudaStream_t)0;

    if (fork) {
        cudaEventRecord(eF, 0);
        cudaStreamWaitEvent(s2, eF, 0);
    }

    // ---- audio chain (capture/default stream) ----
    k_cvt_w<<<64, 256>>>(Wt, 0);                              // 1
    k_cvt_w<<<16, 256>>>(Wa, 1);                              // 2
    // ---- video chain start (s2) ----
    k_prep_fvcam<<<(BV * D_ + BV * CLS_) / 16, 256, 0, vs>>>(feat_v, cam);  // 3
    // ---- audio main ----
    k_fa_mma<<<BA, 256, FA_SMEM>>>(feat_a, bt);               // 4 <- profiled
    k_ta_mma<<<BA / 128, 256, TV_SMEM>>>(ba);                 // 5

    // ---- video chain rest (s2) ----
    k_wbs<<<DOUT, 32, 0, vs>>>(Wv, bs);
    k_wvs<<<dim3(4, 8), 256, 0, vs>>>(Wv, Ws);
    k_g_mma<<<BV, 256, KG_SMEM, vs>>>();
    k_tv_mma<<<(BV * CLS_) / 128, 256, TV_SMEM, vs>>>(bv);

    if (fork) {
        cudaEventRecord(eJ, s2);
        cudaStreamWaitEvent(0, eJ, 0);
    }

    k_loss<<<dim3(S_, CLS_), 256>>>(pred_a, pred_v, rand_frames, rand_classes, out);
}